// round 1
// baseline (speedup 1.0000x reference)
#include <cuda_runtime.h>
#include <cuda_bf16.h>

#define T_TOTAL 9792
#define EMBED   1024
#define NHEADS  16
#define HDIM    64

// Scratch (static device allocations — allowed)
__device__ float g_q[(size_t)T_TOTAL * EMBED];
__device__ float g_k[(size_t)T_TOTAL * EMBED];
__device__ float g_v[(size_t)T_TOTAL * EMBED];
__device__ float g_attn[(size_t)T_TOTAL * EMBED];

// Fixed sequence layout (from the reference's LENGTHS constant)
__constant__ int c_cu[12] = {0, 1024, 1792, 2688, 3200, 4224, 4864, 5888, 6656, 7168, 8064, 9088};
__constant__ int c_nt[12] = {16, 12, 14, 8, 16, 10, 16, 12, 8, 14, 16, 11};  // len/64 per batch

// ---------------------------------------------------------------------------
// Generic SGEMM body: C[M,N] = A[M,K] @ W[N,K]^T (+ bias), 128x128x8 tiles,
// 256 threads, 8x8 per thread.
// ---------------------------------------------------------------------------
__device__ __forceinline__ void gemm_body(const float* __restrict__ A,
                                          const float* __restrict__ W,
                                          const float* __restrict__ bias,
                                          float* __restrict__ C,
                                          int M, int N, int K)
{
    __shared__ float As[8][128];
    __shared__ float Bs[8][128];

    const int tid = threadIdx.x;
    const int tx = tid & 15;
    const int ty = tid >> 4;
    const int row0 = blockIdx.y * 128;
    const int col0 = blockIdx.x * 128;
    const int lr = tid >> 1;          // 0..127
    const int lc = (tid & 1) * 4;     // 0 or 4

    float acc[8][8];
#pragma unroll
    for (int i = 0; i < 8; i++)
#pragma unroll
        for (int j = 0; j < 8; j++) acc[i][j] = 0.0f;

    for (int kt = 0; kt < K; kt += 8) {
        float4 av = make_float4(0.f, 0.f, 0.f, 0.f);
        if (row0 + lr < M)
            av = *(const float4*)&A[(size_t)(row0 + lr) * K + kt + lc];
        As[lc + 0][lr] = av.x;
        As[lc + 1][lr] = av.y;
        As[lc + 2][lr] = av.z;
        As[lc + 3][lr] = av.w;

        float4 bv = *(const float4*)&W[(size_t)(col0 + lr) * K + kt + lc];
        Bs[lc + 0][lr] = bv.x;
        Bs[lc + 1][lr] = bv.y;
        Bs[lc + 2][lr] = bv.z;
        Bs[lc + 3][lr] = bv.w;

        __syncthreads();

#pragma unroll
        for (int k = 0; k < 8; k++) {
            float4 a0 = *(const float4*)&As[k][ty * 8];
            float4 a1 = *(const float4*)&As[k][ty * 8 + 4];
            float4 b0 = *(const float4*)&Bs[k][tx * 8];
            float4 b1 = *(const float4*)&Bs[k][tx * 8 + 4];
            float a[8] = {a0.x, a0.y, a0.z, a0.w, a1.x, a1.y, a1.z, a1.w};
            float b[8] = {b0.x, b0.y, b0.z, b0.w, b1.x, b1.y, b1.z, b1.w};
#pragma unroll
            for (int i = 0; i < 8; i++)
#pragma unroll
                for (int j = 0; j < 8; j++) acc[i][j] = fmaf(a[i], b[j], acc[i][j]);
        }
        __syncthreads();
    }

#pragma unroll
    for (int i = 0; i < 8; i++) {
        int r = row0 + ty * 8 + i;
        if (r < M) {
#pragma unroll
            for (int j = 0; j < 8; j++) {
                int cidx = col0 + tx * 8 + j;
                float v = acc[i][j];
                if (bias) v += bias[cidx];
                C[(size_t)r * N + cidx] = v;
            }
        }
    }
}

// Fused QKV projection: grid.z selects q / k / v
__global__ __launch_bounds__(256) void qkv_gemm_kernel(
    const float* __restrict__ A,
    const float* __restrict__ qw, const float* __restrict__ qb,
    const float* __restrict__ kw,
    const float* __restrict__ vw, const float* __restrict__ vb)
{
    int sel = blockIdx.z;
    const float* W = (sel == 0) ? qw : ((sel == 1) ? kw : vw);
    const float* bias = (sel == 0) ? qb : ((sel == 1) ? nullptr : vb);
    float* C = (sel == 0) ? g_q : ((sel == 1) ? g_k : g_v);
    gemm_body(A, W, bias, C, T_TOTAL, EMBED, EMBED);
}

// Output projection
__global__ __launch_bounds__(256) void out_gemm_kernel(
    const float* __restrict__ A,
    const float* __restrict__ ow, const float* __restrict__ ob,
    float* __restrict__ C)
{
    gemm_body(A, ow, ob, C, T_TOTAL, EMBED, EMBED);
}

// ---------------------------------------------------------------------------
// RoPE (in-place on g_q, g_k): each thread handles one (d, d+32) pair.
// cos/sin have 64 columns with cos[d] == cos[d+32].
// ---------------------------------------------------------------------------
__global__ void rope_kernel(const float* __restrict__ cosp,
                            const float* __restrict__ sinp)
{
    int idx = blockIdx.x * blockDim.x + threadIdx.x;
    if (idx >= T_TOTAL * NHEADS * 32) return;
    int d = idx & 31;
    int h = (idx >> 5) & (NHEADS - 1);
    int t = idx >> 9;
    float c = cosp[t * HDIM + d];
    float s = sinp[t * HDIM + d];
    size_t base = (size_t)t * EMBED + h * HDIM + d;

    float q1 = g_q[base], q2 = g_q[base + 32];
    g_q[base]      = q1 * c - q2 * s;
    g_q[base + 32] = q2 * c + q1 * s;

    float k1 = g_k[base], k2 = g_k[base + 32];
    g_k[base]      = k1 * c - k2 * s;
    g_k[base + 32] = k2 * c + k1 * s;
}

// ---------------------------------------------------------------------------
// Flash attention (varlen causal, fp32). Block = 256 threads, 64 q-rows tile.
// All sequence lengths are multiples of 64 -> only the diagonal tile is masked.
// smem tiles padded to stride 65 (2-way worst-case conflicts).
// ---------------------------------------------------------------------------
__global__ __launch_bounds__(256) void flash_kernel()
{
    extern __shared__ float sm[];
    float* Qs = sm;               // [64][65]
    float* Ks = Qs + 64 * 65;     // [64][65]
    float* Vs = Ks + 64 * 65;     // [64][65]
    float* Ps = Vs + 64 * 65;     // [64][65]

    const int tid = threadIdx.x;
    const int tx = tid & 15;
    const int ty = tid >> 4;
    const int h = blockIdx.y;

    int rem = blockIdx.x, b = 0;
    while (rem >= c_nt[b]) { rem -= c_nt[b]; ++b; }
    const int qt = rem;
    const int tok0 = c_cu[b];
    const int tokq = tok0 + qt * 64;

    // Load Q tile, folding in the 1/sqrt(64) scale
#pragma unroll
    for (int it = 0; it < 4; it++) {
        int idx = it * 256 + tid;
        int r = idx >> 4;
        int c4 = (idx & 15) * 4;
        float4 v = *(const float4*)&g_q[(size_t)(tokq + r) * EMBED + h * HDIM + c4];
        Qs[r * 65 + c4 + 0] = v.x * 0.125f;
        Qs[r * 65 + c4 + 1] = v.y * 0.125f;
        Qs[r * 65 + c4 + 2] = v.z * 0.125f;
        Qs[r * 65 + c4 + 3] = v.w * 0.125f;
    }

    float m_i[4], l_i[4], o[4][4];
#pragma unroll
    for (int i = 0; i < 4; i++) {
        m_i[i] = -1e30f;
        l_i[i] = 0.0f;
#pragma unroll
        for (int j = 0; j < 4; j++) o[i][j] = 0.0f;
    }

    for (int kt = 0; kt <= qt; kt++) {
        __syncthreads();  // protect K/V/P tiles from previous iteration reads
        const int tokk = tok0 + kt * 64;
#pragma unroll
        for (int it = 0; it < 4; it++) {
            int idx = it * 256 + tid;
            int r = idx >> 4;
            int c4 = (idx & 15) * 4;
            float4 kv = *(const float4*)&g_k[(size_t)(tokk + r) * EMBED + h * HDIM + c4];
            Ks[r * 65 + c4 + 0] = kv.x;
            Ks[r * 65 + c4 + 1] = kv.y;
            Ks[r * 65 + c4 + 2] = kv.z;
            Ks[r * 65 + c4 + 3] = kv.w;
            float4 vv = *(const float4*)&g_v[(size_t)(tokk + r) * EMBED + h * HDIM + c4];
            Vs[r * 65 + c4 + 0] = vv.x;
            Vs[r * 65 + c4 + 1] = vv.y;
            Vs[r * 65 + c4 + 2] = vv.z;
            Vs[r * 65 + c4 + 3] = vv.w;
        }
        __syncthreads();

        // S = Q @ K^T (4x4 per thread)
        float s[4][4];
#pragma unroll
        for (int i = 0; i < 4; i++)
#pragma unroll
            for (int j = 0; j < 4; j++) s[i][j] = 0.0f;

#pragma unroll 8
        for (int k = 0; k < 64; k++) {
            float a0 = Qs[(ty * 4 + 0) * 65 + k];
            float a1 = Qs[(ty * 4 + 1) * 65 + k];
            float a2 = Qs[(ty * 4 + 2) * 65 + k];
            float a3 = Qs[(ty * 4 + 3) * 65 + k];
            float b0 = Ks[(tx * 4 + 0) * 65 + k];
            float b1 = Ks[(tx * 4 + 1) * 65 + k];
            float b2 = Ks[(tx * 4 + 2) * 65 + k];
            float b3 = Ks[(tx * 4 + 3) * 65 + k];
            s[0][0] = fmaf(a0, b0, s[0][0]); s[0][1] = fmaf(a0, b1, s[0][1]);
            s[0][2] = fmaf(a0, b2, s[0][2]); s[0][3] = fmaf(a0, b3, s[0][3]);
            s[1][0] = fmaf(a1, b0, s[1][0]); s[1][1] = fmaf(a1, b1, s[1][1]);
            s[1][2] = fmaf(a1, b2, s[1][2]); s[1][3] = fmaf(a1, b3, s[1][3]);
            s[2][0] = fmaf(a2, b0, s[2][0]); s[2][1] = fmaf(a2, b1, s[2][1]);
            s[2][2] = fmaf(a2, b2, s[2][2]); s[2][3] = fmaf(a2, b3, s[2][3]);
            s[3][0] = fmaf(a3, b0, s[3][0]); s[3][1] = fmaf(a3, b1, s[3][1]);
            s[3][2] = fmaf(a3, b2, s[3][2]); s[3][3] = fmaf(a3, b3, s[3][3]);
        }

        // Causal mask on diagonal tile only
        if (kt == qt) {
#pragma unroll
            for (int i = 0; i < 4; i++)
#pragma unroll
                for (int j = 0; j < 4; j++)
                    if (ty * 4 + i < tx * 4 + j) s[i][j] = -1e30f;
        }

        // Online softmax (row groups = 16 lanes = half warp)
#pragma unroll
        for (int i = 0; i < 4; i++) {
            float tm = fmaxf(fmaxf(s[i][0], s[i][1]), fmaxf(s[i][2], s[i][3]));
#pragma unroll
            for (int w = 8; w >= 1; w >>= 1)
                tm = fmaxf(tm, __shfl_xor_sync(0xffffffffu, tm, w, 32));
            float mn = fmaxf(m_i[i], tm);
            float alpha = __expf(m_i[i] - mn);
            float rs = 0.0f;
#pragma unroll
            for (int j = 0; j < 4; j++) {
                float p = __expf(s[i][j] - mn);
                s[i][j] = p;
                rs += p;
            }
#pragma unroll
            for (int w = 8; w >= 1; w >>= 1)
                rs += __shfl_xor_sync(0xffffffffu, rs, w, 32);
            l_i[i] = l_i[i] * alpha + rs;
            m_i[i] = mn;
#pragma unroll
            for (int j = 0; j < 4; j++) {
                o[i][j] *= alpha;
                Ps[(ty * 4 + i) * 65 + tx * 4 + j] = s[i][j];
            }
        }
        __syncthreads();

        // O += P @ V
#pragma unroll 8
        for (int n = 0; n < 64; n++) {
            float p0 = Ps[(ty * 4 + 0) * 65 + n];
            float p1 = Ps[(ty * 4 + 1) * 65 + n];
            float p2 = Ps[(ty * 4 + 2) * 65 + n];
            float p3 = Ps[(ty * 4 + 3) * 65 + n];
            float v0 = Vs[n * 65 + tx * 4 + 0];
            float v1 = Vs[n * 65 + tx * 4 + 1];
            float v2 = Vs[n * 65 + tx * 4 + 2];
            float v3 = Vs[n * 65 + tx * 4 + 3];
            o[0][0] = fmaf(p0, v0, o[0][0]); o[0][1] = fmaf(p0, v1, o[0][1]);
            o[0][2] = fmaf(p0, v2, o[0][2]); o[0][3] = fmaf(p0, v3, o[0][3]);
            o[1][0] = fmaf(p1, v0, o[1][0]); o[1][1] = fmaf(p1, v1, o[1][1]);
            o[1][2] = fmaf(p1, v2, o[1][2]); o[1][3] = fmaf(p1, v3, o[1][3]);
            o[2][0] = fmaf(p2, v0, o[2][0]); o[2][1] = fmaf(p2, v1, o[2][1]);
            o[2][2] = fmaf(p2, v2, o[2][2]); o[2][3] = fmaf(p2, v3, o[2][3]);
            o[3][0] = fmaf(p3, v0, o[3][0]); o[3][1] = fmaf(p3, v1, o[3][1]);
            o[3][2] = fmaf(p3, v2, o[3][2]); o[3][3] = fmaf(p3, v3, o[3][3]);
        }
    }

    // Normalize + store
#pragma unroll
    for (int i = 0; i < 4; i++) {
        float inv = 1.0f / l_i[i];
        size_t base = (size_t)(tokq + ty * 4 + i) * EMBED + h * HDIM + tx * 4;
        float4 r;
        r.x = o[i][0] * inv;
        r.y = o[i][1] * inv;
        r.z = o[i][2] * inv;
        r.w = o[i][3] * inv;
        *(float4*)&g_attn[base] = r;
    }
}

// ---------------------------------------------------------------------------
extern "C" void kernel_launch(void* const* d_in, const int* in_sizes, int n_in,
                              void* d_out, int out_size)
{
    const float* hidden = (const float*)d_in[0];
    const float* cosp   = (const float*)d_in[1];
    const float* sinp   = (const float*)d_in[2];
    const float* q_w    = (const float*)d_in[3];
    const float* q_b    = (const float*)d_in[4];
    const float* k_w    = (const float*)d_in[5];
    const float* v_w    = (const float*)d_in[6];
    const float* v_b    = (const float*)d_in[7];
    const float* out_w  = (const float*)d_in[8];
    const float* out_b  = (const float*)d_in[9];
    float* out = (float*)d_out;

    float* pa = nullptr;
    cudaGetSymbolAddress((void**)&pa, g_attn);

    dim3 blk(256);

    // Fused QKV GEMM (grid.z = 3 selects q/k/v)
    dim3 gq(EMBED / 128, (T_TOTAL + 127) / 128, 3);
    qkv_gemm_kernel<<<gq, blk>>>(hidden, q_w, q_b, k_w, v_w, v_b);

    // RoPE on q, k
    int nrope = T_TOTAL * NHEADS * 32;
    rope_kernel<<<(nrope + 255) / 256, 256>>>(cosp, sinp);

    // Flash attention (153 q-tiles x 16 heads)
    const int smem_bytes = 4 * 64 * 65 * (int)sizeof(float);
    cudaFuncSetAttribute(flash_kernel, cudaFuncAttributeMaxDynamicSharedMemorySize, smem_bytes);
    flash_kernel<<<dim3(153, 16), blk, smem_bytes>>>();

    // Output projection
    dim3 go(EMBED / 128, (T_TOTAL + 127) / 128, 1);
    out_gemm_kernel<<<go, blk>>>(pa, out_w, out_b, out);
}

// round 2
// speedup vs baseline: 1.0031x; 1.0031x over previous
#include <cuda_runtime.h>
#include <cuda_bf16.h>

#define T_TOTAL 9792
#define EMBED   1024
#define NHEADS  16
#define HDIM    64

// Scratch (static device allocations — allowed)
__device__ float g_q[(size_t)T_TOTAL * EMBED];
__device__ float g_k[(size_t)T_TOTAL * EMBED];
__device__ float g_v[(size_t)T_TOTAL * EMBED];
__device__ float g_attn[(size_t)T_TOTAL * EMBED];

// Fixed sequence layout (from the reference's LENGTHS constant)
__constant__ int c_cu[12] = {0, 1024, 1792, 2688, 3200, 4224, 4864, 5888, 6656, 7168, 8064, 9088};
__constant__ int c_nt[12] = {16, 12, 14, 8, 16, 10, 16, 12, 8, 14, 16, 11};  // len/64 per batch

// ---------------------------------------------------------------------------
// Generic SGEMM body: C[M,N] = A[M,K] @ W[N,K]^T (+ bias), 128x128x8 tiles,
// 256 threads, 8x8 per thread.
// ---------------------------------------------------------------------------
__device__ __forceinline__ void gemm_body(const float* __restrict__ A,
                                          const float* __restrict__ W,
                                          const float* __restrict__ bias,
                                          float* __restrict__ C,
                                          int M, int N, int K)
{
    __shared__ float As[8][128];
    __shared__ float Bs[8][128];

    const int tid = threadIdx.x;
    const int tx = tid & 15;
    const int ty = tid >> 4;
    const int row0 = blockIdx.y * 128;
    const int col0 = blockIdx.x * 128;
    const int lr = tid >> 1;          // 0..127
    const int lc = (tid & 1) * 4;     // 0 or 4

    float acc[8][8];
#pragma unroll
    for (int i = 0; i < 8; i++)
#pragma unroll
        for (int j = 0; j < 8; j++) acc[i][j] = 0.0f;

    for (int kt = 0; kt < K; kt += 8) {
        float4 av = make_float4(0.f, 0.f, 0.f, 0.f);
        if (row0 + lr < M)
            av = *(const float4*)&A[(size_t)(row0 + lr) * K + kt + lc];
        As[lc + 0][lr] = av.x;
        As[lc + 1][lr] = av.y;
        As[lc + 2][lr] = av.z;
        As[lc + 3][lr] = av.w;

        float4 bv = *(const float4*)&W[(size_t)(col0 + lr) * K + kt + lc];
        Bs[lc + 0][lr] = bv.x;
        Bs[lc + 1][lr] = bv.y;
        Bs[lc + 2][lr] = bv.z;
        Bs[lc + 3][lr] = bv.w;

        __syncthreads();

#pragma unroll
        for (int k = 0; k < 8; k++) {
            float4 a0 = *(const float4*)&As[k][ty * 8];
            float4 a1 = *(const float4*)&As[k][ty * 8 + 4];
            float4 b0 = *(const float4*)&Bs[k][tx * 8];
            float4 b1 = *(const float4*)&Bs[k][tx * 8 + 4];
            float a[8] = {a0.x, a0.y, a0.z, a0.w, a1.x, a1.y, a1.z, a1.w};
            float b[8] = {b0.x, b0.y, b0.z, b0.w, b1.x, b1.y, b1.z, b1.w};
#pragma unroll
            for (int i = 0; i < 8; i++)
#pragma unroll
                for (int j = 0; j < 8; j++) acc[i][j] = fmaf(a[i], b[j], acc[i][j]);
        }
        __syncthreads();
    }

#pragma unroll
    for (int i = 0; i < 8; i++) {
        int r = row0 + ty * 8 + i;
        if (r < M) {
#pragma unroll
            for (int j = 0; j < 8; j++) {
                int cidx = col0 + tx * 8 + j;
                float v = acc[i][j];
                if (bias) v += bias[cidx];
                C[(size_t)r * N + cidx] = v;
            }
        }
    }
}

// Fused QKV projection: grid.z selects q / k / v
__global__ __launch_bounds__(256) void qkv_gemm_kernel(
    const float* __restrict__ A,
    const float* __restrict__ qw, const float* __restrict__ qb,
    const float* __restrict__ kw,
    const float* __restrict__ vw, const float* __restrict__ vb)
{
    int sel = blockIdx.z;
    const float* W = (sel == 0) ? qw : ((sel == 1) ? kw : vw);
    const float* bias = (sel == 0) ? qb : ((sel == 1) ? nullptr : vb);
    float* C = (sel == 0) ? g_q : ((sel == 1) ? g_k : g_v);
    gemm_body(A, W, bias, C, T_TOTAL, EMBED, EMBED);
}

// Output projection
__global__ __launch_bounds__(256) void out_gemm_kernel(
    const float* __restrict__ A,
    const float* __restrict__ ow, const float* __restrict__ ob,
    float* __restrict__ C)
{
    gemm_body(A, ow, ob, C, T_TOTAL, EMBED, EMBED);
}

// ---------------------------------------------------------------------------
// RoPE (in-place on g_q, g_k): each thread handles one (d, d+32) pair.
// cos/sin have 64 columns with cos[d] == cos[d+32].
// ---------------------------------------------------------------------------
__global__ void rope_kernel(const float* __restrict__ cosp,
                            const float* __restrict__ sinp)
{
    int idx = blockIdx.x * blockDim.x + threadIdx.x;
    if (idx >= T_TOTAL * NHEADS * 32) return;
    int d = idx & 31;
    int h = (idx >> 5) & (NHEADS - 1);
    int t = idx >> 9;
    float c = cosp[t * HDIM + d];
    float s = sinp[t * HDIM + d];
    size_t base = (size_t)t * EMBED + h * HDIM + d;

    float q1 = g_q[base], q2 = g_q[base + 32];
    g_q[base]      = q1 * c - q2 * s;
    g_q[base + 32] = q2 * c + q1 * s;

    float k1 = g_k[base], k2 = g_k[base + 32];
    g_k[base]      = k1 * c - k2 * s;
    g_k[base + 32] = k2 * c + k1 * s;
}

// ---------------------------------------------------------------------------
// Flash attention (varlen causal, fp32). Block = 256 threads, 64 q-rows tile.
// All sequence lengths are multiples of 64 -> only the diagonal tile is masked.
// smem tiles padded to stride 65 (2-way worst-case conflicts).
// ---------------------------------------------------------------------------
__global__ __launch_bounds__(256) void flash_kernel()
{
    extern __shared__ float sm[];
    float* Qs = sm;               // [64][65]
    float* Ks = Qs + 64 * 65;     // [64][65]
    float* Vs = Ks + 64 * 65;     // [64][65]
    float* Ps = Vs + 64 * 65;     // [64][65]

    const int tid = threadIdx.x;
    const int tx = tid & 15;
    const int ty = tid >> 4;
    const int h = blockIdx.y;

    int rem = blockIdx.x, b = 0;
    while (rem >= c_nt[b]) { rem -= c_nt[b]; ++b; }
    const int qt = rem;
    const int tok0 = c_cu[b];
    const int tokq = tok0 + qt * 64;

    // Load Q tile, folding in the 1/sqrt(64) scale
#pragma unroll
    for (int it = 0; it < 4; it++) {
        int idx = it * 256 + tid;
        int r = idx >> 4;
        int c4 = (idx & 15) * 4;
        float4 v = *(const float4*)&g_q[(size_t)(tokq + r) * EMBED + h * HDIM + c4];
        Qs[r * 65 + c4 + 0] = v.x * 0.125f;
        Qs[r * 65 + c4 + 1] = v.y * 0.125f;
        Qs[r * 65 + c4 + 2] = v.z * 0.125f;
        Qs[r * 65 + c4 + 3] = v.w * 0.125f;
    }

    float m_i[4], l_i[4], o[4][4];
#pragma unroll
    for (int i = 0; i < 4; i++) {
        m_i[i] = -1e30f;
        l_i[i] = 0.0f;
#pragma unroll
        for (int j = 0; j < 4; j++) o[i][j] = 0.0f;
    }

    for (int kt = 0; kt <= qt; kt++) {
        __syncthreads();  // protect K/V/P tiles from previous iteration reads
        const int tokk = tok0 + kt * 64;
#pragma unroll
        for (int it = 0; it < 4; it++) {
            int idx = it * 256 + tid;
            int r = idx >> 4;
            int c4 = (idx & 15) * 4;
            float4 kv = *(const float4*)&g_k[(size_t)(tokk + r) * EMBED + h * HDIM + c4];
            Ks[r * 65 + c4 + 0] = kv.x;
            Ks[r * 65 + c4 + 1] = kv.y;
            Ks[r * 65 + c4 + 2] = kv.z;
            Ks[r * 65 + c4 + 3] = kv.w;
            float4 vv = *(const float4*)&g_v[(size_t)(tokk + r) * EMBED + h * HDIM + c4];
            Vs[r * 65 + c4 + 0] = vv.x;
            Vs[r * 65 + c4 + 1] = vv.y;
            Vs[r * 65 + c4 + 2] = vv.z;
            Vs[r * 65 + c4 + 3] = vv.w;
        }
        __syncthreads();

        // S = Q @ K^T (4x4 per thread)
        float s[4][4];
#pragma unroll
        for (int i = 0; i < 4; i++)
#pragma unroll
            for (int j = 0; j < 4; j++) s[i][j] = 0.0f;

#pragma unroll 8
        for (int k = 0; k < 64; k++) {
            float a0 = Qs[(ty * 4 + 0) * 65 + k];
            float a1 = Qs[(ty * 4 + 1) * 65 + k];
            float a2 = Qs[(ty * 4 + 2) * 65 + k];
            float a3 = Qs[(ty * 4 + 3) * 65 + k];
            float b0 = Ks[(tx * 4 + 0) * 65 + k];
            float b1 = Ks[(tx * 4 + 1) * 65 + k];
            float b2 = Ks[(tx * 4 + 2) * 65 + k];
            float b3 = Ks[(tx * 4 + 3) * 65 + k];
            s[0][0] = fmaf(a0, b0, s[0][0]); s[0][1] = fmaf(a0, b1, s[0][1]);
            s[0][2] = fmaf(a0, b2, s[0][2]); s[0][3] = fmaf(a0, b3, s[0][3]);
            s[1][0] = fmaf(a1, b0, s[1][0]); s[1][1] = fmaf(a1, b1, s[1][1]);
            s[1][2] = fmaf(a1, b2, s[1][2]); s[1][3] = fmaf(a1, b3, s[1][3]);
            s[2][0] = fmaf(a2, b0, s[2][0]); s[2][1] = fmaf(a2, b1, s[2][1]);
            s[2][2] = fmaf(a2, b2, s[2][2]); s[2][3] = fmaf(a2, b3, s[2][3]);
            s[3][0] = fmaf(a3, b0, s[3][0]); s[3][1] = fmaf(a3, b1, s[3][1]);
            s[3][2] = fmaf(a3, b2, s[3][2]); s[3][3] = fmaf(a3, b3, s[3][3]);
        }

        // Causal mask on diagonal tile only
        if (kt == qt) {
#pragma unroll
            for (int i = 0; i < 4; i++)
#pragma unroll
                for (int j = 0; j < 4; j++)
                    if (ty * 4 + i < tx * 4 + j) s[i][j] = -1e30f;
        }

        // Online softmax (row groups = 16 lanes = half warp)
#pragma unroll
        for (int i = 0; i < 4; i++) {
            float tm = fmaxf(fmaxf(s[i][0], s[i][1]), fmaxf(s[i][2], s[i][3]));
#pragma unroll
            for (int w = 8; w >= 1; w >>= 1)
                tm = fmaxf(tm, __shfl_xor_sync(0xffffffffu, tm, w, 32));
            float mn = fmaxf(m_i[i], tm);
            float alpha = __expf(m_i[i] - mn);
            float rs = 0.0f;
#pragma unroll
            for (int j = 0; j < 4; j++) {
                float p = __expf(s[i][j] - mn);
                s[i][j] = p;
                rs += p;
            }
#pragma unroll
            for (int w = 8; w >= 1; w >>= 1)
                rs += __shfl_xor_sync(0xffffffffu, rs, w, 32);
            l_i[i] = l_i[i] * alpha + rs;
            m_i[i] = mn;
#pragma unroll
            for (int j = 0; j < 4; j++) {
                o[i][j] *= alpha;
                Ps[(ty * 4 + i) * 65 + tx * 4 + j] = s[i][j];
            }
        }
        __syncthreads();

        // O += P @ V
#pragma unroll 8
        for (int n = 0; n < 64; n++) {
            float p0 = Ps[(ty * 4 + 0) * 65 + n];
            float p1 = Ps[(ty * 4 + 1) * 65 + n];
            float p2 = Ps[(ty * 4 + 2) * 65 + n];
            float p3 = Ps[(ty * 4 + 3) * 65 + n];
            float v0 = Vs[n * 65 + tx * 4 + 0];
            float v1 = Vs[n * 65 + tx * 4 + 1];
            float v2 = Vs[n * 65 + tx * 4 + 2];
            float v3 = Vs[n * 65 + tx * 4 + 3];
            o[0][0] = fmaf(p0, v0, o[0][0]); o[0][1] = fmaf(p0, v1, o[0][1]);
            o[0][2] = fmaf(p0, v2, o[0][2]); o[0][3] = fmaf(p0, v3, o[0][3]);
            o[1][0] = fmaf(p1, v0, o[1][0]); o[1][1] = fmaf(p1, v1, o[1][1]);
            o[1][2] = fmaf(p1, v2, o[1][2]); o[1][3] = fmaf(p1, v3, o[1][3]);
            o[2][0] = fmaf(p2, v0, o[2][0]); o[2][1] = fmaf(p2, v1, o[2][1]);
            o[2][2] = fmaf(p2, v2, o[2][2]); o[2][3] = fmaf(p2, v3, o[2][3]);
            o[3][0] = fmaf(p3, v0, o[3][0]); o[3][1] = fmaf(p3, v1, o[3][1]);
            o[3][2] = fmaf(p3, v2, o[3][2]); o[3][3] = fmaf(p3, v3, o[3][3]);
        }
    }

    // Normalize + store
#pragma unroll
    for (int i = 0; i < 4; i++) {
        float inv = 1.0f / l_i[i];
        size_t base = (size_t)(tokq + ty * 4 + i) * EMBED + h * HDIM + tx * 4;
        float4 r;
        r.x = o[i][0] * inv;
        r.y = o[i][1] * inv;
        r.z = o[i][2] * inv;
        r.w = o[i][3] * inv;
        *(float4*)&g_attn[base] = r;
    }
}

// ---------------------------------------------------------------------------
extern "C" void kernel_launch(void* const* d_in, const int* in_sizes, int n_in,
                              void* d_out, int out_size)
{
    const float* hidden = (const float*)d_in[0];
    const float* cosp   = (const float*)d_in[1];
    const float* sinp   = (const float*)d_in[2];
    const float* q_w    = (const float*)d_in[3];
    const float* q_b    = (const float*)d_in[4];
    const float* k_w    = (const float*)d_in[5];
    const float* v_w    = (const float*)d_in[6];
    const float* v_b    = (const float*)d_in[7];
    const float* out_w  = (const float*)d_in[8];
    const float* out_b  = (const float*)d_in[9];
    float* out = (float*)d_out;

    float* pa = nullptr;
    cudaGetSymbolAddress((void**)&pa, g_attn);

    dim3 blk(256);

    // Fused QKV GEMM (grid.z = 3 selects q/k/v)
    dim3 gq(EMBED / 128, (T_TOTAL + 127) / 128, 3);
    qkv_gemm_kernel<<<gq, blk>>>(hidden, q_w, q_b, k_w, v_w, v_b);

    // RoPE on q, k
    int nrope = T_TOTAL * NHEADS * 32;
    rope_kernel<<<(nrope + 255) / 256, 256>>>(cosp, sinp);

    // Flash attention (153 q-tiles x 16 heads)
    const int smem_bytes = 4 * 64 * 65 * (int)sizeof(float);
    cudaFuncSetAttribute(flash_kernel, cudaFuncAttributeMaxDynamicSharedMemorySize, smem_bytes);
    flash_kernel<<<dim3(153, 16), blk, smem_bytes>>>();

    // Output projection
    dim3 go(EMBED / 128, (T_TOTAL + 127) / 128, 1);
    out_gemm_kernel<<<go, blk>>>(pa, out_w, out_b, out);
}

// round 5
// speedup vs baseline: 1.9432x; 1.9372x over previous
#include <cuda_runtime.h>
#include <cuda_bf16.h>
#include <cstdint>

#define T_TOTAL 9792
#define EMBED   1024
#define NHEADS  16
#define HDIM    64
#define MTILES  77          // ceil(9792/128)

using bf16 = __nv_bfloat16;

// ------------------------- scratch (static device) -------------------------
__device__ float g_q[(size_t)T_TOTAL * EMBED];
__device__ float g_k[(size_t)T_TOTAL * EMBED];
__device__ float g_v[(size_t)T_TOTAL * EMBED];
__device__ float g_attn[(size_t)T_TOTAL * EMBED];

__device__ bf16 g_ahi[(size_t)T_TOTAL * EMBED];
__device__ bf16 g_alo[(size_t)T_TOTAL * EMBED];
__device__ bf16 g_chi[(size_t)T_TOTAL * EMBED];
__device__ bf16 g_clo[(size_t)T_TOTAL * EMBED];
__device__ bf16 g_whi[4][(size_t)EMBED * EMBED];
__device__ bf16 g_wlo[4][(size_t)EMBED * EMBED];

__constant__ int c_cu[12] = {0, 1024, 1792, 2688, 3200, 4224, 4864, 5888, 6656, 7168, 8064, 9088};
__constant__ int c_nt[12] = {16, 12, 14, 8, 16, 10, 16, 12, 8, 14, 16, 11};

// ------------------------- PTX helpers (baseline ISA only) ------------------
__device__ __forceinline__ uint32_t smem_u32(const void* p) {
    uint32_t a;
    asm("{ .reg .u64 t; cvta.to.shared.u64 t, %1; cvt.u32.u64 %0, t; }" : "=r"(a) : "l"(p));
    return a;
}

#define LDSM_X4(R, addr)                                                      \
    asm volatile("ldmatrix.sync.aligned.m8n8.x4.shared.b16 {%0,%1,%2,%3}, [%4];" \
        : "=r"((R)[0]), "=r"((R)[1]), "=r"((R)[2]), "=r"((R)[3]) : "r"(addr))

#define MMA_BF16(C, A, B0, B1)                                                \
    asm volatile("mma.sync.aligned.m16n8k16.row.col.f32.bf16.bf16.f32 "       \
        "{%0,%1,%2,%3}, {%4,%5,%6,%7}, {%8,%9}, {%0,%1,%2,%3};"               \
        : "+f"((C)[0]), "+f"((C)[1]), "+f"((C)[2]), "+f"((C)[3])              \
        : "r"((A)[0]), "r"((A)[1]), "r"((A)[2]), "r"((A)[3]), "r"(B0), "r"(B1))

// ------------------------- fp32 -> bf16 hi/lo split -------------------------
__device__ __forceinline__ void split_store(const float4 v, bf16* hi, bf16* lo, size_t i4) {
    union { bf16 b[4]; uint2 u; } H, L;
    float x[4] = {v.x, v.y, v.z, v.w};
#pragma unroll
    for (int j = 0; j < 4; j++) {
        bf16 h = __float2bfloat16(x[j]);
        H.b[j] = h;
        L.b[j] = __float2bfloat16(x[j] - __bfloat162float(h));
    }
    ((uint2*)hi)[i4] = H.u;
    ((uint2*)lo)[i4] = L.u;
}

__global__ void split_kernel(const float* __restrict__ src, bf16* __restrict__ hi,
                             bf16* __restrict__ lo, int n4) {
    int i = blockIdx.x * blockDim.x + threadIdx.x;
    if (i >= n4) return;
    split_store(((const float4*)src)[i], hi, lo, i);
}

__global__ void split_w_kernel(const float* __restrict__ w0, const float* __restrict__ w1,
                               const float* __restrict__ w2, const float* __restrict__ w3) {
    int z = blockIdx.z;
    const float* src = (z == 0) ? w0 : (z == 1) ? w1 : (z == 2) ? w2 : w3;
    int i = blockIdx.x * blockDim.x + threadIdx.x;
    int n4 = EMBED * EMBED / 4;
    if (i >= n4) return;
    split_store(((const float4*)src)[i], g_whi[z], g_wlo[z], i);
}

// ------------------------- warp-MMA GEMM: C[M,1024] = A @ W^T (+bias) -------
// bf16x3 split: D = Ahi*Bhi + Ahi*Blo + Alo*Bhi, fp32 accumulate in registers.
// CTA: 128x128 tile, 8 warps, warp tile 64(M)x32(N). K-tiles of 64 in SMEM.
#define SM_AHI  0
#define SM_ALO  16384
#define SM_BHI  32768
#define SM_BLO  49152
#define SM_TOTAL 65536

__device__ __forceinline__ uint32_t sw_off(int r, int chunk) {
    uint32_t off = (uint32_t)(r * 128 + chunk * 16);
    return off ^ ((off >> 3) & 0x70);
}

__device__ __forceinline__ void mma_gemm_body(
    const bf16* __restrict__ Ahi, const bf16* __restrict__ Alo,
    const bf16* __restrict__ Bhi, const bf16* __restrict__ Blo,
    const float* __restrict__ bias, float* __restrict__ C, int M)
{
    extern __shared__ char smem[];
    const uint32_t sb = smem_u32(smem);
    const int tid = threadIdx.x;
    const int wid = tid >> 5, lane = tid & 31;
    const int row0 = blockIdx.y * 128;
    const int col0 = blockIdx.x * 128;
    const int wm = (wid & 1) * 64;    // warp M offset within CTA tile
    const int wn = (wid >> 1) * 32;   // warp N offset within CTA tile

    float acc[4][4][4];
#pragma unroll
    for (int a = 0; a < 4; a++)
#pragma unroll
        for (int b = 0; b < 4; b++)
#pragma unroll
            for (int c = 0; c < 4; c++) acc[a][b][c] = 0.0f;

    // ldmatrix lane->address mappings (fixed per thread)
    const int a_r = lane & 15;               // A: rows 0..15 of the 16x16 tile
    const int a_c = lane >> 4;               // A: k-chunk parity (0 = k0-7, 1 = k8-15)
    const int b_r = ((lane >> 4) << 3) + (lane & 7);  // B: n-row 0..15
    const int b_c = (lane >> 3) & 1;         // B: k-chunk parity

    for (int kt = 0; kt < 16; kt++) {
        if (kt) __syncthreads();             // previous tile fully consumed
        const int k0 = kt * 64;
#pragma unroll
        for (int j = 0; j < 4; j++) {
            int idx = tid + j * 256;          // 0..1023
            int r = idx >> 3;                 // row 0..127
            int c16 = idx & 7;                // 16B chunk 0..7
            uint32_t sw = sw_off(r, c16);

            float4 vah = make_float4(0.f, 0.f, 0.f, 0.f);
            float4 val = make_float4(0.f, 0.f, 0.f, 0.f);
            if (row0 + r < M) {
                vah = *(const float4*)&Ahi[(size_t)(row0 + r) * EMBED + k0 + c16 * 8];
                val = *(const float4*)&Alo[(size_t)(row0 + r) * EMBED + k0 + c16 * 8];
            }
            *(float4*)(smem + SM_AHI + sw) = vah;
            *(float4*)(smem + SM_ALO + sw) = val;

            float4 vbh = *(const float4*)&Bhi[(size_t)(col0 + r) * EMBED + k0 + c16 * 8];
            float4 vbl = *(const float4*)&Blo[(size_t)(col0 + r) * EMBED + k0 + c16 * 8];
            *(float4*)(smem + SM_BHI + sw) = vbh;
            *(float4*)(smem + SM_BLO + sw) = vbl;
        }
        __syncthreads();

#pragma unroll
        for (int ks = 0; ks < 4; ks++) {
            uint32_t ahi[4][4], alo[4][4];
#pragma unroll
            for (int mt = 0; mt < 4; mt++) {
                uint32_t sw = sw_off(wm + mt * 16 + a_r, ks * 2 + a_c);
                LDSM_X4(ahi[mt], sb + SM_AHI + sw);
                LDSM_X4(alo[mt], sb + SM_ALO + sw);
            }
            uint32_t bhi[2][4], blo[2][4];
#pragma unroll
            for (int np = 0; np < 2; np++) {
                uint32_t sw = sw_off(wn + np * 16 + b_r, ks * 2 + b_c);
                LDSM_X4(bhi[np], sb + SM_BHI + sw);
                LDSM_X4(blo[np], sb + SM_BLO + sw);
            }
#pragma unroll
            for (int mt = 0; mt < 4; mt++) {
#pragma unroll
                for (int nt = 0; nt < 4; nt++) {
                    uint32_t bh0 = bhi[nt >> 1][(nt & 1) * 2];
                    uint32_t bh1 = bhi[nt >> 1][(nt & 1) * 2 + 1];
                    uint32_t bl0 = blo[nt >> 1][(nt & 1) * 2];
                    uint32_t bl1 = blo[nt >> 1][(nt & 1) * 2 + 1];
                    MMA_BF16(acc[mt][nt], ahi[mt], bh0, bh1);
                    MMA_BF16(acc[mt][nt], ahi[mt], bl0, bl1);
                    MMA_BF16(acc[mt][nt], alo[mt], bh0, bh1);
                }
            }
        }
    }

    // Epilogue: c0,c1 -> (row = lane/4, col = (lane%4)*2), c2,c3 -> row+8
    const int erow = lane >> 2;
    const int ecol = (lane & 3) * 2;
#pragma unroll
    for (int mt = 0; mt < 4; mt++) {
        int r0g = row0 + wm + mt * 16 + erow;
#pragma unroll
        for (int nt = 0; nt < 4; nt++) {
            int colg = col0 + wn + nt * 8 + ecol;
            float b0 = bias ? bias[colg] : 0.f;
            float b1 = bias ? bias[colg + 1] : 0.f;
            if (r0g < M) {
                float2 v = make_float2(acc[mt][nt][0] + b0, acc[mt][nt][1] + b1);
                *(float2*)&C[(size_t)r0g * EMBED + colg] = v;
            }
            if (r0g + 8 < M) {
                float2 v = make_float2(acc[mt][nt][2] + b0, acc[mt][nt][3] + b1);
                *(float2*)&C[(size_t)(r0g + 8) * EMBED + colg] = v;
            }
        }
    }
}

__global__ __launch_bounds__(256) void qkv_mma_kernel(const float* __restrict__ qb,
                                                      const float* __restrict__ vb) {
    int z = blockIdx.z;
    const float* bias = (z == 0) ? qb : ((z == 2) ? vb : nullptr);
    float* C = (z == 0) ? g_q : ((z == 1) ? g_k : g_v);
    mma_gemm_body(g_ahi, g_alo, g_whi[z], g_wlo[z], bias, C, T_TOTAL);
}

__global__ __launch_bounds__(256) void out_mma_kernel(const float* __restrict__ ob,
                                                      float* __restrict__ out) {
    mma_gemm_body(g_chi, g_clo, g_whi[3], g_wlo[3], ob, out, T_TOTAL);
}

// ------------------------- RoPE (unchanged) -------------------------
__global__ void rope_kernel(const float* __restrict__ cosp, const float* __restrict__ sinp) {
    int idx = blockIdx.x * blockDim.x + threadIdx.x;
    if (idx >= T_TOTAL * NHEADS * 32) return;
    int d = idx & 31;
    int h = (idx >> 5) & (NHEADS - 1);
    int t = idx >> 9;
    float c = cosp[t * HDIM + d];
    float s = sinp[t * HDIM + d];
    size_t base = (size_t)t * EMBED + h * HDIM + d;

    float q1 = g_q[base], q2 = g_q[base + 32];
    g_q[base]      = q1 * c - q2 * s;
    g_q[base + 32] = q2 * c + q1 * s;

    float k1 = g_k[base], k2 = g_k[base + 32];
    g_k[base]      = k1 * c - k2 * s;
    g_k[base + 32] = k2 * c + k1 * s;
}

// ------------------------- flash attention (unchanged fp32) -----------------
__global__ __launch_bounds__(256) void flash_kernel() {
    extern __shared__ float sm[];
    float* Qs = sm;
    float* Ks = Qs + 64 * 65;
    float* Vs = Ks + 64 * 65;
    float* Ps = Vs + 64 * 65;

    const int tid = threadIdx.x;
    const int tx = tid & 15;
    const int ty = tid >> 4;
    const int h = blockIdx.y;

    int rem = blockIdx.x, b = 0;
    while (rem >= c_nt[b]) { rem -= c_nt[b]; ++b; }
    const int qt = rem;
    const int tok0 = c_cu[b];
    const int tokq = tok0 + qt * 64;

#pragma unroll
    for (int it = 0; it < 4; it++) {
        int idx = it * 256 + tid;
        int r = idx >> 4;
        int c4 = (idx & 15) * 4;
        float4 v = *(const float4*)&g_q[(size_t)(tokq + r) * EMBED + h * HDIM + c4];
        Qs[r * 65 + c4 + 0] = v.x * 0.125f;
        Qs[r * 65 + c4 + 1] = v.y * 0.125f;
        Qs[r * 65 + c4 + 2] = v.z * 0.125f;
        Qs[r * 65 + c4 + 3] = v.w * 0.125f;
    }

    float m_i[4], l_i[4], o[4][4];
#pragma unroll
    for (int i = 0; i < 4; i++) {
        m_i[i] = -1e30f;
        l_i[i] = 0.0f;
#pragma unroll
        for (int j = 0; j < 4; j++) o[i][j] = 0.0f;
    }

    for (int kt = 0; kt <= qt; kt++) {
        __syncthreads();
        const int tokk = tok0 + kt * 64;
#pragma unroll
        for (int it = 0; it < 4; it++) {
            int idx = it * 256 + tid;
            int r = idx >> 4;
            int c4 = (idx & 15) * 4;
            float4 kv = *(const float4*)&g_k[(size_t)(tokk + r) * EMBED + h * HDIM + c4];
            Ks[r * 65 + c4 + 0] = kv.x;
            Ks[r * 65 + c4 + 1] = kv.y;
            Ks[r * 65 + c4 + 2] = kv.z;
            Ks[r * 65 + c4 + 3] = kv.w;
            float4 vv = *(const float4*)&g_v[(size_t)(tokk + r) * EMBED + h * HDIM + c4];
            Vs[r * 65 + c4 + 0] = vv.x;
            Vs[r * 65 + c4 + 1] = vv.y;
            Vs[r * 65 + c4 + 2] = vv.z;
            Vs[r * 65 + c4 + 3] = vv.w;
        }
        __syncthreads();

        float s[4][4];
#pragma unroll
        for (int i = 0; i < 4; i++)
#pragma unroll
            for (int j = 0; j < 4; j++) s[i][j] = 0.0f;

#pragma unroll 8
        for (int k = 0; k < 64; k++) {
            float a0 = Qs[(ty * 4 + 0) * 65 + k];
            float a1 = Qs[(ty * 4 + 1) * 65 + k];
            float a2 = Qs[(ty * 4 + 2) * 65 + k];
            float a3 = Qs[(ty * 4 + 3) * 65 + k];
            float b0 = Ks[(tx * 4 + 0) * 65 + k];
            float b1 = Ks[(tx * 4 + 1) * 65 + k];
            float b2 = Ks[(tx * 4 + 2) * 65 + k];
            float b3 = Ks[(tx * 4 + 3) * 65 + k];
            s[0][0] = fmaf(a0, b0, s[0][0]); s[0][1] = fmaf(a0, b1, s[0][1]);
            s[0][2] = fmaf(a0, b2, s[0][2]); s[0][3] = fmaf(a0, b3, s[0][3]);
            s[1][0] = fmaf(a1, b0, s[1][0]); s[1][1] = fmaf(a1, b1, s[1][1]);
            s[1][2] = fmaf(a1, b2, s[1][2]); s[1][3] = fmaf(a1, b3, s[1][3]);
            s[2][0] = fmaf(a2, b0, s[2][0]); s[2][1] = fmaf(a2, b1, s[2][1]);
            s[2][2] = fmaf(a2, b2, s[2][2]); s[2][3] = fmaf(a2, b3, s[2][3]);
            s[3][0] = fmaf(a3, b0, s[3][0]); s[3][1] = fmaf(a3, b1, s[3][1]);
            s[3][2] = fmaf(a3, b2, s[3][2]); s[3][3] = fmaf(a3, b3, s[3][3]);
        }

        if (kt == qt) {
#pragma unroll
            for (int i = 0; i < 4; i++)
#pragma unroll
                for (int j = 0; j < 4; j++)
                    if (ty * 4 + i < tx * 4 + j) s[i][j] = -1e30f;
        }

#pragma unroll
        for (int i = 0; i < 4; i++) {
            float tm = fmaxf(fmaxf(s[i][0], s[i][1]), fmaxf(s[i][2], s[i][3]));
#pragma unroll
            for (int w = 8; w >= 1; w >>= 1)
                tm = fmaxf(tm, __shfl_xor_sync(0xffffffffu, tm, w, 32));
            float mn = fmaxf(m_i[i], tm);
            float alpha = __expf(m_i[i] - mn);
            float rs = 0.0f;
#pragma unroll
            for (int j = 0; j < 4; j++) {
                float p = __expf(s[i][j] - mn);
                s[i][j] = p;
                rs += p;
            }
#pragma unroll
            for (int w = 8; w >= 1; w >>= 1)
                rs += __shfl_xor_sync(0xffffffffu, rs, w, 32);
            l_i[i] = l_i[i] * alpha + rs;
            m_i[i] = mn;
#pragma unroll
            for (int j = 0; j < 4; j++) {
                o[i][j] *= alpha;
                Ps[(ty * 4 + i) * 65 + tx * 4 + j] = s[i][j];
            }
        }
        __syncthreads();

#pragma unroll 8
        for (int n = 0; n < 64; n++) {
            float p0 = Ps[(ty * 4 + 0) * 65 + n];
            float p1 = Ps[(ty * 4 + 1) * 65 + n];
            float p2 = Ps[(ty * 4 + 2) * 65 + n];
            float p3 = Ps[(ty * 4 + 3) * 65 + n];
            float v0 = Vs[n * 65 + tx * 4 + 0];
            float v1 = Vs[n * 65 + tx * 4 + 1];
            float v2 = Vs[n * 65 + tx * 4 + 2];
            float v3 = Vs[n * 65 + tx * 4 + 3];
            o[0][0] = fmaf(p0, v0, o[0][0]); o[0][1] = fmaf(p0, v1, o[0][1]);
            o[0][2] = fmaf(p0, v2, o[0][2]); o[0][3] = fmaf(p0, v3, o[0][3]);
            o[1][0] = fmaf(p1, v0, o[1][0]); o[1][1] = fmaf(p1, v1, o[1][1]);
            o[1][2] = fmaf(p1, v2, o[1][2]); o[1][3] = fmaf(p1, v3, o[1][3]);
            o[2][0] = fmaf(p2, v0, o[2][0]); o[2][1] = fmaf(p2, v1, o[2][1]);
            o[2][2] = fmaf(p2, v2, o[2][2]); o[2][3] = fmaf(p2, v3, o[2][3]);
            o[3][0] = fmaf(p3, v0, o[3][0]); o[3][1] = fmaf(p3, v1, o[3][1]);
            o[3][2] = fmaf(p3, v2, o[3][2]); o[3][3] = fmaf(p3, v3, o[3][3]);
        }
    }

#pragma unroll
    for (int i = 0; i < 4; i++) {
        float inv = 1.0f / l_i[i];
        size_t base = (size_t)(tokq + ty * 4 + i) * EMBED + h * HDIM + tx * 4;
        float4 r;
        r.x = o[i][0] * inv;
        r.y = o[i][1] * inv;
        r.z = o[i][2] * inv;
        r.w = o[i][3] * inv;
        *(float4*)&g_attn[base] = r;
    }
}

// ---------------------------------------------------------------------------
extern "C" void kernel_launch(void* const* d_in, const int* in_sizes, int n_in,
                              void* d_out, int out_size)
{
    const float* hidden = (const float*)d_in[0];
    const float* cosp   = (const float*)d_in[1];
    const float* sinp   = (const float*)d_in[2];
    const float* q_w    = (const float*)d_in[3];
    const float* q_b    = (const float*)d_in[4];
    const float* k_w    = (const float*)d_in[5];
    const float* v_w    = (const float*)d_in[6];
    const float* v_b    = (const float*)d_in[7];
    const float* out_w  = (const float*)d_in[8];
    const float* out_b  = (const float*)d_in[9];
    float* out = (float*)d_out;

    bf16 *pahi, *palo, *pchi, *pclo;
    float* pattn;
    cudaGetSymbolAddress((void**)&pahi, g_ahi);
    cudaGetSymbolAddress((void**)&palo, g_alo);
    cudaGetSymbolAddress((void**)&pchi, g_chi);
    cudaGetSymbolAddress((void**)&pclo, g_clo);
    cudaGetSymbolAddress((void**)&pattn, g_attn);

    // 1. Split hidden -> bf16 hi/lo
    {
        int n4 = T_TOTAL * EMBED / 4;
        split_kernel<<<(n4 + 255) / 256, 256>>>(hidden, pahi, palo, n4);
    }
    // 2. Split weights (z = q,k,v,out)
    {
        int n4 = EMBED * EMBED / 4;
        dim3 g((n4 + 255) / 256, 1, 4);
        split_w_kernel<<<g, 256>>>(q_w, k_w, v_w, out_w);
    }
    // 3. QKV GEMMs via warp MMA (bf16x3)
    cudaFuncSetAttribute(qkv_mma_kernel, cudaFuncAttributeMaxDynamicSharedMemorySize, SM_TOTAL);
    qkv_mma_kernel<<<dim3(EMBED / 128, MTILES, 3), 256, SM_TOTAL>>>(q_b, v_b);

    // 4. RoPE
    int nrope = T_TOTAL * NHEADS * 32;
    rope_kernel<<<(nrope + 255) / 256, 256>>>(cosp, sinp);

    // 5. Flash attention
    const int smem_bytes = 4 * 64 * 65 * (int)sizeof(float);
    cudaFuncSetAttribute(flash_kernel, cudaFuncAttributeMaxDynamicSharedMemorySize, smem_bytes);
    flash_kernel<<<dim3(153, 16), 256, smem_bytes>>>();

    // 6. Split attention output -> bf16 hi/lo
    {
        int n4 = T_TOTAL * EMBED / 4;
        split_kernel<<<(n4 + 255) / 256, 256>>>(pattn, pchi, pclo, n4);
    }
    // 7. Output GEMM via warp MMA
    cudaFuncSetAttribute(out_mma_kernel, cudaFuncAttributeMaxDynamicSharedMemorySize, SM_TOTAL);
    out_mma_kernel<<<dim3(EMBED / 128, MTILES, 1), 256, SM_TOTAL>>>(out_b, out);
}

// round 6
// speedup vs baseline: 2.1769x; 1.1203x over previous
#include <cuda_runtime.h>
#include <cuda_bf16.h>
#include <cstdint>

#define T_TOTAL 9792
#define EMBED   1024
#define NHEADS  16
#define HDIM    64
#define MTILES  77          // ceil(9792/128)

using bf16 = __nv_bfloat16;

// ------------------------- scratch (static device) -------------------------
__device__ float g_q[(size_t)T_TOTAL * EMBED];
__device__ float g_k[(size_t)T_TOTAL * EMBED];
__device__ float g_v[(size_t)T_TOTAL * EMBED];

__device__ bf16 g_ahi[(size_t)T_TOTAL * EMBED];
__device__ bf16 g_alo[(size_t)T_TOTAL * EMBED];
__device__ bf16 g_chi[(size_t)T_TOTAL * EMBED];
__device__ bf16 g_clo[(size_t)T_TOTAL * EMBED];
__device__ bf16 g_whi[4][(size_t)EMBED * EMBED];
__device__ bf16 g_wlo[4][(size_t)EMBED * EMBED];

__constant__ int c_cu[12] = {0, 1024, 1792, 2688, 3200, 4224, 4864, 5888, 6656, 7168, 8064, 9088};
__constant__ int c_nt[12] = {16, 12, 14, 8, 16, 10, 16, 12, 8, 14, 16, 11};

// ------------------------- PTX helpers (baseline ISA only) ------------------
__device__ __forceinline__ uint32_t smem_u32(const void* p) {
    uint32_t a;
    asm("{ .reg .u64 t; cvta.to.shared.u64 t, %1; cvt.u32.u64 %0, t; }" : "=r"(a) : "l"(p));
    return a;
}

#define LDSM_X4(R, addr)                                                      \
    asm volatile("ldmatrix.sync.aligned.m8n8.x4.shared.b16 {%0,%1,%2,%3}, [%4];" \
        : "=r"((R)[0]), "=r"((R)[1]), "=r"((R)[2]), "=r"((R)[3]) : "r"(addr))

#define MMA_BF16(C, A, B0, B1)                                                \
    asm volatile("mma.sync.aligned.m16n8k16.row.col.f32.bf16.bf16.f32 "       \
        "{%0,%1,%2,%3}, {%4,%5,%6,%7}, {%8,%9}, {%0,%1,%2,%3};"               \
        : "+f"((C)[0]), "+f"((C)[1]), "+f"((C)[2]), "+f"((C)[3])              \
        : "r"((A)[0]), "r"((A)[1]), "r"((A)[2]), "r"((A)[3]), "r"(B0), "r"(B1))

__device__ __forceinline__ void cp16(uint32_t dst, const void* src, int srcbytes) {
    asm volatile("cp.async.cg.shared.global [%0], [%1], 16, %2;"
                 :: "r"(dst), "l"(src), "r"(srcbytes) : "memory");
}
#define CP_COMMIT() asm volatile("cp.async.commit_group;" ::: "memory")
#define CP_WAIT(N)  asm volatile("cp.async.wait_group %0;" :: "n"(N) : "memory")

// ------------------------- fp32 -> bf16 hi/lo split -------------------------
__device__ __forceinline__ void split_store(const float4 v, bf16* hi, bf16* lo, size_t i4) {
    union { bf16 b[4]; uint2 u; } H, L;
    float x[4] = {v.x, v.y, v.z, v.w};
#pragma unroll
    for (int j = 0; j < 4; j++) {
        bf16 h = __float2bfloat16(x[j]);
        H.b[j] = h;
        L.b[j] = __float2bfloat16(x[j] - __bfloat162float(h));
    }
    ((uint2*)hi)[i4] = H.u;
    ((uint2*)lo)[i4] = L.u;
}

__global__ void split_kernel(const float* __restrict__ src, bf16* __restrict__ hi,
                             bf16* __restrict__ lo, int n4) {
    int i = blockIdx.x * blockDim.x + threadIdx.x;
    if (i >= n4) return;
    split_store(((const float4*)src)[i], hi, lo, i);
}

__global__ void split_w_kernel(const float* __restrict__ w0, const float* __restrict__ w1,
                               const float* __restrict__ w2, const float* __restrict__ w3) {
    int z = blockIdx.z;
    const float* src = (z == 0) ? w0 : (z == 1) ? w1 : (z == 2) ? w2 : w3;
    int i = blockIdx.x * blockDim.x + threadIdx.x;
    int n4 = EMBED * EMBED / 4;
    if (i >= n4) return;
    split_store(((const float4*)src)[i], g_whi[z], g_wlo[z], i);
}

// ------------------------- warp-MMA GEMM: C[M,1024] = A @ W^T (+bias) -------
// bf16x3 split: D = Ahi*Bhi + Ahi*Blo + Alo*Bhi, fp32 accumulate in registers.
// CTA: 128x128 tile, 8 warps, warp tile 64(M)x32(N). K-tiles of 64, 2-stage
// cp.async pipeline (128KB smem).
#define SM_AHI  0
#define SM_ALO  16384
#define SM_BHI  32768
#define SM_BLO  49152
#define SM_STAGE 65536
#define SM_TOTAL 131072

__device__ __forceinline__ uint32_t sw_off(int r, int chunk) {
    uint32_t off = (uint32_t)(r * 128 + chunk * 16);
    return off ^ ((off >> 3) & 0x70);
}

__device__ __forceinline__ void mma_gemm_body(
    const bf16* __restrict__ Ahi, const bf16* __restrict__ Alo,
    const bf16* __restrict__ Bhi, const bf16* __restrict__ Blo,
    const float* __restrict__ bias, float* __restrict__ C, int M)
{
    extern __shared__ char smem[];
    const uint32_t sb = smem_u32(smem);
    const int tid = threadIdx.x;
    const int wid = tid >> 5, lane = tid & 31;
    const int row0 = blockIdx.y * 128;
    const int col0 = blockIdx.x * 128;
    const int wm = (wid & 1) * 64;    // warp M offset within CTA tile
    const int wn = (wid >> 1) * 32;   // warp N offset within CTA tile

    float acc[4][4][4];
#pragma unroll
    for (int a = 0; a < 4; a++)
#pragma unroll
        for (int b = 0; b < 4; b++)
#pragma unroll
            for (int c = 0; c < 4; c++) acc[a][b][c] = 0.0f;

    // per-thread load mapping: covers 128 rows x 8 chunks in 4 steps of 256
    const int l_r[4] = { (tid + 0) >> 3, (tid + 256) >> 3, (tid + 512) >> 3, (tid + 768) >> 3 };
    const int l_c = tid & 7;

    // ldmatrix lane->address mappings (fixed per thread)
    const int a_r = lane & 15;
    const int a_c = lane >> 4;
    const int b_r = ((lane >> 4) << 3) + (lane & 7);
    const int b_c = (lane >> 3) & 1;

    auto load_tile = [&](int kt, int stage) {
        const int k0 = kt * 64;
        const uint32_t stb = sb + stage * SM_STAGE;
#pragma unroll
        for (int j = 0; j < 4; j++) {
            int r = l_r[j];
            uint32_t sw = sw_off(r, l_c);
            int apred = (row0 + r < M) ? 16 : 0;
            size_t aoff = (size_t)(row0 + r) * EMBED + k0 + l_c * 8;
            size_t boff = (size_t)(col0 + r) * EMBED + k0 + l_c * 8;
            cp16(stb + SM_AHI + sw, Ahi + aoff, apred);
            cp16(stb + SM_ALO + sw, Alo + aoff, apred);
            cp16(stb + SM_BHI + sw, Bhi + boff, 16);
            cp16(stb + SM_BLO + sw, Blo + boff, 16);
        }
        CP_COMMIT();
    };

    load_tile(0, 0);

    for (int kt = 0; kt < 16; kt++) {
        const int stage = kt & 1;
        if (kt + 1 < 16) {
            load_tile(kt + 1, stage ^ 1);
            CP_WAIT(1);
        } else {
            CP_WAIT(0);
        }
        __syncthreads();

        const uint32_t stb = sb + stage * SM_STAGE;
#pragma unroll
        for (int ks = 0; ks < 4; ks++) {
            uint32_t ahi[4][4], alo[4][4];
#pragma unroll
            for (int mt = 0; mt < 4; mt++) {
                uint32_t sw = sw_off(wm + mt * 16 + a_r, ks * 2 + a_c);
                LDSM_X4(ahi[mt], stb + SM_AHI + sw);
                LDSM_X4(alo[mt], stb + SM_ALO + sw);
            }
            uint32_t bhi[2][4], blo[2][4];
#pragma unroll
            for (int np = 0; np < 2; np++) {
                uint32_t sw = sw_off(wn + np * 16 + b_r, ks * 2 + b_c);
                LDSM_X4(bhi[np], stb + SM_BHI + sw);
                LDSM_X4(blo[np], stb + SM_BLO + sw);
            }
#pragma unroll
            for (int mt = 0; mt < 4; mt++) {
#pragma unroll
                for (int nt = 0; nt < 4; nt++) {
                    uint32_t bh0 = bhi[nt >> 1][(nt & 1) * 2];
                    uint32_t bh1 = bhi[nt >> 1][(nt & 1) * 2 + 1];
                    uint32_t bl0 = blo[nt >> 1][(nt & 1) * 2];
                    uint32_t bl1 = blo[nt >> 1][(nt & 1) * 2 + 1];
                    MMA_BF16(acc[mt][nt], ahi[mt], bh0, bh1);
                    MMA_BF16(acc[mt][nt], ahi[mt], bl0, bl1);
                    MMA_BF16(acc[mt][nt], alo[mt], bh0, bh1);
                }
            }
        }
        __syncthreads();   // stage fully consumed before it is overwritten
    }

    // Epilogue
    const int erow = lane >> 2;
    const int ecol = (lane & 3) * 2;
#pragma unroll
    for (int mt = 0; mt < 4; mt++) {
        int r0g = row0 + wm + mt * 16 + erow;
#pragma unroll
        for (int nt = 0; nt < 4; nt++) {
            int colg = col0 + wn + nt * 8 + ecol;
            float b0 = bias ? bias[colg] : 0.f;
            float b1 = bias ? bias[colg + 1] : 0.f;
            if (r0g < M) {
                float2 v = make_float2(acc[mt][nt][0] + b0, acc[mt][nt][1] + b1);
                *(float2*)&C[(size_t)r0g * EMBED + colg] = v;
            }
            if (r0g + 8 < M) {
                float2 v = make_float2(acc[mt][nt][2] + b0, acc[mt][nt][3] + b1);
                *(float2*)&C[(size_t)(r0g + 8) * EMBED + colg] = v;
            }
        }
    }
}

__global__ __launch_bounds__(256) void qkv_mma_kernel(const float* __restrict__ qb,
                                                      const float* __restrict__ vb) {
    int z = blockIdx.z;
    const float* bias = (z == 0) ? qb : ((z == 2) ? vb : nullptr);
    float* C = (z == 0) ? g_q : ((z == 1) ? g_k : g_v);
    mma_gemm_body(g_ahi, g_alo, g_whi[z], g_wlo[z], bias, C, T_TOTAL);
}

__global__ __launch_bounds__(256) void out_mma_kernel(const float* __restrict__ ob,
                                                      float* __restrict__ out) {
    mma_gemm_body(g_chi, g_clo, g_whi[3], g_wlo[3], ob, out, T_TOTAL);
}

// ------------------------- RoPE (unchanged) -------------------------
__global__ void rope_kernel(const float* __restrict__ cosp, const float* __restrict__ sinp) {
    int idx = blockIdx.x * blockDim.x + threadIdx.x;
    if (idx >= T_TOTAL * NHEADS * 32) return;
    int d = idx & 31;
    int h = (idx >> 5) & (NHEADS - 1);
    int t = idx >> 9;
    float c = cosp[t * HDIM + d];
    float s = sinp[t * HDIM + d];
    size_t base = (size_t)t * EMBED + h * HDIM + d;

    float q1 = g_q[base], q2 = g_q[base + 32];
    g_q[base]      = q1 * c - q2 * s;
    g_q[base + 32] = q2 * c + q1 * s;

    float k1 = g_k[base], k2 = g_k[base + 32];
    g_k[base]      = k1 * c - k2 * s;
    g_k[base + 32] = k2 * c + k1 * s;
}

// ------------------------- flash attention (fp32; epilogue writes hi/lo) ----
__global__ __launch_bounds__(256) void flash_kernel() {
    extern __shared__ float sm[];
    float* Qs = sm;
    float* Ks = Qs + 64 * 65;
    float* Vs = Ks + 64 * 65;
    float* Ps = Vs + 64 * 65;

    const int tid = threadIdx.x;
    const int tx = tid & 15;
    const int ty = tid >> 4;
    const int h = blockIdx.y;

    int rem = blockIdx.x, b = 0;
    while (rem >= c_nt[b]) { rem -= c_nt[b]; ++b; }
    const int qt = rem;
    const int tok0 = c_cu[b];
    const int tokq = tok0 + qt * 64;

#pragma unroll
    for (int it = 0; it < 4; it++) {
        int idx = it * 256 + tid;
        int r = idx >> 4;
        int c4 = (idx & 15) * 4;
        float4 v = *(const float4*)&g_q[(size_t)(tokq + r) * EMBED + h * HDIM + c4];
        Qs[r * 65 + c4 + 0] = v.x * 0.125f;
        Qs[r * 65 + c4 + 1] = v.y * 0.125f;
        Qs[r * 65 + c4 + 2] = v.z * 0.125f;
        Qs[r * 65 + c4 + 3] = v.w * 0.125f;
    }

    float m_i[4], l_i[4], o[4][4];
#pragma unroll
    for (int i = 0; i < 4; i++) {
        m_i[i] = -1e30f;
        l_i[i] = 0.0f;
#pragma unroll
        for (int j = 0; j < 4; j++) o[i][j] = 0.0f;
    }

    for (int kt = 0; kt <= qt; kt++) {
        __syncthreads();
        const int tokk = tok0 + kt * 64;
#pragma unroll
        for (int it = 0; it < 4; it++) {
            int idx = it * 256 + tid;
            int r = idx >> 4;
            int c4 = (idx & 15) * 4;
            float4 kv = *(const float4*)&g_k[(size_t)(tokk + r) * EMBED + h * HDIM + c4];
            Ks[r * 65 + c4 + 0] = kv.x;
            Ks[r * 65 + c4 + 1] = kv.y;
            Ks[r * 65 + c4 + 2] = kv.z;
            Ks[r * 65 + c4 + 3] = kv.w;
            float4 vv = *(const float4*)&g_v[(size_t)(tokk + r) * EMBED + h * HDIM + c4];
            Vs[r * 65 + c4 + 0] = vv.x;
            Vs[r * 65 + c4 + 1] = vv.y;
            Vs[r * 65 + c4 + 2] = vv.z;
            Vs[r * 65 + c4 + 3] = vv.w;
        }
        __syncthreads();

        float s[4][4];
#pragma unroll
        for (int i = 0; i < 4; i++)
#pragma unroll
            for (int j = 0; j < 4; j++) s[i][j] = 0.0f;

#pragma unroll 8
        for (int k = 0; k < 64; k++) {
            float a0 = Qs[(ty * 4 + 0) * 65 + k];
            float a1 = Qs[(ty * 4 + 1) * 65 + k];
            float a2 = Qs[(ty * 4 + 2) * 65 + k];
            float a3 = Qs[(ty * 4 + 3) * 65 + k];
            float b0 = Ks[(tx * 4 + 0) * 65 + k];
            float b1 = Ks[(tx * 4 + 1) * 65 + k];
            float b2 = Ks[(tx * 4 + 2) * 65 + k];
            float b3 = Ks[(tx * 4 + 3) * 65 + k];
            s[0][0] = fmaf(a0, b0, s[0][0]); s[0][1] = fmaf(a0, b1, s[0][1]);
            s[0][2] = fmaf(a0, b2, s[0][2]); s[0][3] = fmaf(a0, b3, s[0][3]);
            s[1][0] = fmaf(a1, b0, s[1][0]); s[1][1] = fmaf(a1, b1, s[1][1]);
            s[1][2] = fmaf(a1, b2, s[1][2]); s[1][3] = fmaf(a1, b3, s[1][3]);
            s[2][0] = fmaf(a2, b0, s[2][0]); s[2][1] = fmaf(a2, b1, s[2][1]);
            s[2][2] = fmaf(a2, b2, s[2][2]); s[2][3] = fmaf(a2, b3, s[2][3]);
            s[3][0] = fmaf(a3, b0, s[3][0]); s[3][1] = fmaf(a3, b1, s[3][1]);
            s[3][2] = fmaf(a3, b2, s[3][2]); s[3][3] = fmaf(a3, b3, s[3][3]);
        }

        if (kt == qt) {
#pragma unroll
            for (int i = 0; i < 4; i++)
#pragma unroll
                for (int j = 0; j < 4; j++)
                    if (ty * 4 + i < tx * 4 + j) s[i][j] = -1e30f;
        }

#pragma unroll
        for (int i = 0; i < 4; i++) {
            float tm = fmaxf(fmaxf(s[i][0], s[i][1]), fmaxf(s[i][2], s[i][3]));
#pragma unroll
            for (int w = 8; w >= 1; w >>= 1)
                tm = fmaxf(tm, __shfl_xor_sync(0xffffffffu, tm, w, 32));
            float mn = fmaxf(m_i[i], tm);
            float alpha = __expf(m_i[i] - mn);
            float rs = 0.0f;
#pragma unroll
            for (int j = 0; j < 4; j++) {
                float p = __expf(s[i][j] - mn);
                s[i][j] = p;
                rs += p;
            }
#pragma unroll
            for (int w = 8; w >= 1; w >>= 1)
                rs += __shfl_xor_sync(0xffffffffu, rs, w, 32);
            l_i[i] = l_i[i] * alpha + rs;
            m_i[i] = mn;
#pragma unroll
            for (int j = 0; j < 4; j++) {
                o[i][j] *= alpha;
                Ps[(ty * 4 + i) * 65 + tx * 4 + j] = s[i][j];
            }
        }
        __syncthreads();

#pragma unroll 8
        for (int n = 0; n < 64; n++) {
            float p0 = Ps[(ty * 4 + 0) * 65 + n];
            float p1 = Ps[(ty * 4 + 1) * 65 + n];
            float p2 = Ps[(ty * 4 + 2) * 65 + n];
            float p3 = Ps[(ty * 4 + 3) * 65 + n];
            float v0 = Vs[n * 65 + tx * 4 + 0];
            float v1 = Vs[n * 65 + tx * 4 + 1];
            float v2 = Vs[n * 65 + tx * 4 + 2];
            float v3 = Vs[n * 65 + tx * 4 + 3];
            o[0][0] = fmaf(p0, v0, o[0][0]); o[0][1] = fmaf(p0, v1, o[0][1]);
            o[0][2] = fmaf(p0, v2, o[0][2]); o[0][3] = fmaf(p0, v3, o[0][3]);
            o[1][0] = fmaf(p1, v0, o[1][0]); o[1][1] = fmaf(p1, v1, o[1][1]);
            o[1][2] = fmaf(p1, v2, o[1][2]); o[1][3] = fmaf(p1, v3, o[1][3]);
            o[2][0] = fmaf(p2, v0, o[2][0]); o[2][1] = fmaf(p2, v1, o[2][1]);
            o[2][2] = fmaf(p2, v2, o[2][2]); o[2][3] = fmaf(p2, v3, o[2][3]);
            o[3][0] = fmaf(p3, v0, o[3][0]); o[3][1] = fmaf(p3, v1, o[3][1]);
            o[3][2] = fmaf(p3, v2, o[3][2]); o[3][3] = fmaf(p3, v3, o[3][3]);
        }
    }

    // Epilogue: normalize + write bf16 hi/lo split directly (fused split)
#pragma unroll
    for (int i = 0; i < 4; i++) {
        float inv = 1.0f / l_i[i];
        size_t base = (size_t)(tokq + ty * 4 + i) * EMBED + h * HDIM + tx * 4;
        union { bf16 b[4]; uint2 u; } H, L;
#pragma unroll
        for (int j = 0; j < 4; j++) {
            float v = o[i][j] * inv;
            bf16 hb = __float2bfloat16(v);
            H.b[j] = hb;
            L.b[j] = __float2bfloat16(v - __bfloat162float(hb));
        }
        *(uint2*)&g_chi[base] = H.u;
        *(uint2*)&g_clo[base] = L.u;
    }
}

// ---------------------------------------------------------------------------
extern "C" void kernel_launch(void* const* d_in, const int* in_sizes, int n_in,
                              void* d_out, int out_size)
{
    const float* hidden = (const float*)d_in[0];
    const float* cosp   = (const float*)d_in[1];
    const float* sinp   = (const float*)d_in[2];
    const float* q_w    = (const float*)d_in[3];
    const float* q_b    = (const float*)d_in[4];
    const float* k_w    = (const float*)d_in[5];
    const float* v_w    = (const float*)d_in[6];
    const float* v_b    = (const float*)d_in[7];
    const float* out_w  = (const float*)d_in[8];
    const float* out_b  = (const float*)d_in[9];
    float* out = (float*)d_out;

    bf16 *pahi, *palo;
    cudaGetSymbolAddress((void**)&pahi, g_ahi);
    cudaGetSymbolAddress((void**)&palo, g_alo);

    // 1. Split hidden -> bf16 hi/lo
    {
        int n4 = T_TOTAL * EMBED / 4;
        split_kernel<<<(n4 + 255) / 256, 256>>>(hidden, pahi, palo, n4);
    }
    // 2. Split weights (z = q,k,v,out)
    {
        int n4 = EMBED * EMBED / 4;
        dim3 g((n4 + 255) / 256, 1, 4);
        split_w_kernel<<<g, 256>>>(q_w, k_w, v_w, out_w);
    }
    // 3. QKV GEMMs via pipelined warp MMA (bf16x3)
    cudaFuncSetAttribute(qkv_mma_kernel, cudaFuncAttributeMaxDynamicSharedMemorySize, SM_TOTAL);
    qkv_mma_kernel<<<dim3(EMBED / 128, MTILES, 3), 256, SM_TOTAL>>>(q_b, v_b);

    // 4. RoPE
    int nrope = T_TOTAL * NHEADS * 32;
    rope_kernel<<<(nrope + 255) / 256, 256>>>(cosp, sinp);

    // 5. Flash attention (writes g_chi/g_clo directly)
    const int smem_bytes = 4 * 64 * 65 * (int)sizeof(float);
    cudaFuncSetAttribute(flash_kernel, cudaFuncAttributeMaxDynamicSharedMemorySize, smem_bytes);
    flash_kernel<<<dim3(153, 16), 256, smem_bytes>>>();

    // 6. Output GEMM via pipelined warp MMA
    cudaFuncSetAttribute(out_mma_kernel, cudaFuncAttributeMaxDynamicSharedMemorySize, SM_TOTAL);
    out_mma_kernel<<<dim3(EMBED / 128, MTILES, 1), 256, SM_TOTAL>>>(out_b, out);
}

// round 7
// speedup vs baseline: 2.5088x; 1.1525x over previous
#include <cuda_runtime.h>
#include <cuda_fp16.h>
#include <cstdint>

#define T_TOTAL 9792
#define EMBED   1024
#define NHEADS  16
#define HDIM    64
#define MTILES  77          // ceil(9792/128)

// ------------------------- scratch (static device) -------------------------
__device__ float g_q[(size_t)T_TOTAL * EMBED];
__device__ float g_k[(size_t)T_TOTAL * EMBED];
__device__ float g_v[(size_t)T_TOTAL * EMBED];

__device__ __half g_ahi[(size_t)T_TOTAL * EMBED];
__device__ __half g_alo[(size_t)T_TOTAL * EMBED];
__device__ __half g_chi[(size_t)T_TOTAL * EMBED];
__device__ __half g_clo[(size_t)T_TOTAL * EMBED];
__device__ __half g_whi[4][(size_t)EMBED * EMBED];

__constant__ int c_cu[12] = {0, 1024, 1792, 2688, 3200, 4224, 4864, 5888, 6656, 7168, 8064, 9088};
__constant__ int c_nt[12] = {16, 12, 14, 8, 16, 10, 16, 12, 8, 14, 16, 11};

// ------------------------- PTX helpers (baseline ISA only) ------------------
__device__ __forceinline__ uint32_t smem_u32(const void* p) {
    uint32_t a;
    asm("{ .reg .u64 t; cvta.to.shared.u64 t, %1; cvt.u32.u64 %0, t; }" : "=r"(a) : "l"(p));
    return a;
}

#define LDSM_X4(R, addr)                                                      \
    asm volatile("ldmatrix.sync.aligned.m8n8.x4.shared.b16 {%0,%1,%2,%3}, [%4];" \
        : "=r"((R)[0]), "=r"((R)[1]), "=r"((R)[2]), "=r"((R)[3]) : "r"(addr))

#define MMA_F16(C, A, B0, B1)                                                 \
    asm volatile("mma.sync.aligned.m16n8k16.row.col.f32.f16.f16.f32 "         \
        "{%0,%1,%2,%3}, {%4,%5,%6,%7}, {%8,%9}, {%0,%1,%2,%3};"               \
        : "+f"((C)[0]), "+f"((C)[1]), "+f"((C)[2]), "+f"((C)[3])              \
        : "r"((A)[0]), "r"((A)[1]), "r"((A)[2]), "r"((A)[3]), "r"(B0), "r"(B1))

__device__ __forceinline__ void cp16(uint32_t dst, const void* src, int srcbytes) {
    asm volatile("cp.async.cg.shared.global [%0], [%1], 16, %2;"
                 :: "r"(dst), "l"(src), "r"(srcbytes) : "memory");
}
#define CP_COMMIT() asm volatile("cp.async.commit_group;" ::: "memory")
#define CP_WAIT(N)  asm volatile("cp.async.wait_group %0;" :: "n"(N) : "memory")

// ------------------------- fp32 -> fp16 hi/lo split -------------------------
__device__ __forceinline__ void split_store(const float4 v, __half* hi, __half* lo, size_t i4) {
    union { __half b[4]; uint2 u; } H, L;
    float x[4] = {v.x, v.y, v.z, v.w};
#pragma unroll
    for (int j = 0; j < 4; j++) {
        __half h = __float2half(x[j]);
        H.b[j] = h;
        L.b[j] = __float2half(x[j] - __half2float(h));
    }
    ((uint2*)hi)[i4] = H.u;
    ((uint2*)lo)[i4] = L.u;
}

__global__ void split_kernel(const float* __restrict__ src, __half* __restrict__ hi,
                             __half* __restrict__ lo, int n4) {
    int i = blockIdx.x * blockDim.x + threadIdx.x;
    if (i >= n4) return;
    split_store(((const float4*)src)[i], hi, lo, i);
}

// Weights: hi only (B-side of the 2-pass scheme)
__global__ void split_w_kernel(const float* __restrict__ w0, const float* __restrict__ w1,
                               const float* __restrict__ w2, const float* __restrict__ w3) {
    int z = blockIdx.z;
    const float* src = (z == 0) ? w0 : (z == 1) ? w1 : (z == 2) ? w2 : w3;
    int i = blockIdx.x * blockDim.x + threadIdx.x;
    int n4 = EMBED * EMBED / 4;
    if (i >= n4) return;
    float4 v = ((const float4*)src)[i];
    union { __half b[4]; uint2 u; } H;
    H.b[0] = __float2half(v.x);
    H.b[1] = __float2half(v.y);
    H.b[2] = __float2half(v.z);
    H.b[3] = __float2half(v.w);
    ((uint2*)g_whi[z])[i] = H.u;
}

// ------------------------- warp-MMA GEMM: C[M,1024] = A @ W^T (+bias) -------
// fp16x2 split: D = Ahi*Bhi + Alo*Bhi = A*Bhi, fp32 accumulate in registers.
// CTA: 128x128 tile, 8 warps, warp tile 64(M)x32(N). K-tiles of 64, 2-stage
// cp.async pipeline (96KB smem -> 2 CTAs/SM).
#define SM_AHI  0
#define SM_ALO  16384
#define SM_BHI  32768
#define SM_STAGE 49152
#define SM_TOTAL 98304

__device__ __forceinline__ uint32_t sw_off(int r, int chunk) {
    uint32_t off = (uint32_t)(r * 128 + chunk * 16);
    return off ^ ((off >> 3) & 0x70);
}

__device__ __forceinline__ void mma_gemm_body(
    const __half* __restrict__ Ahi, const __half* __restrict__ Alo,
    const __half* __restrict__ Bhi,
    const float* __restrict__ bias, float* __restrict__ C, int M)
{
    extern __shared__ char smem[];
    const uint32_t sb = smem_u32(smem);
    const int tid = threadIdx.x;
    const int wid = tid >> 5, lane = tid & 31;
    const int row0 = blockIdx.y * 128;
    const int col0 = blockIdx.x * 128;
    const int wm = (wid & 1) * 64;    // warp M offset within CTA tile
    const int wn = (wid >> 1) * 32;   // warp N offset within CTA tile

    float acc[4][4][4];
#pragma unroll
    for (int a = 0; a < 4; a++)
#pragma unroll
        for (int b = 0; b < 4; b++)
#pragma unroll
            for (int c = 0; c < 4; c++) acc[a][b][c] = 0.0f;

    const int l_r[4] = { (tid + 0) >> 3, (tid + 256) >> 3, (tid + 512) >> 3, (tid + 768) >> 3 };
    const int l_c = tid & 7;

    const int a_r = lane & 15;
    const int a_c = lane >> 4;
    const int b_r = ((lane >> 4) << 3) + (lane & 7);
    const int b_c = (lane >> 3) & 1;

    auto load_tile = [&](int kt, int stage) {
        const int k0 = kt * 64;
        const uint32_t stb = sb + stage * SM_STAGE;
#pragma unroll
        for (int j = 0; j < 4; j++) {
            int r = l_r[j];
            uint32_t sw = sw_off(r, l_c);
            int apred = (row0 + r < M) ? 16 : 0;
            size_t aoff = (size_t)(row0 + r) * EMBED + k0 + l_c * 8;
            size_t boff = (size_t)(col0 + r) * EMBED + k0 + l_c * 8;
            cp16(stb + SM_AHI + sw, Ahi + aoff, apred);
            cp16(stb + SM_ALO + sw, Alo + aoff, apred);
            cp16(stb + SM_BHI + sw, Bhi + boff, 16);
        }
        CP_COMMIT();
    };

    load_tile(0, 0);

    for (int kt = 0; kt < 16; kt++) {
        const int stage = kt & 1;
        if (kt + 1 < 16) {
            load_tile(kt + 1, stage ^ 1);
            CP_WAIT(1);
        } else {
            CP_WAIT(0);
        }
        __syncthreads();

        const uint32_t stb = sb + stage * SM_STAGE;
#pragma unroll
        for (int ks = 0; ks < 4; ks++) {
            uint32_t ahi[4][4], alo[4][4];
#pragma unroll
            for (int mt = 0; mt < 4; mt++) {
                uint32_t sw = sw_off(wm + mt * 16 + a_r, ks * 2 + a_c);
                LDSM_X4(ahi[mt], stb + SM_AHI + sw);
                LDSM_X4(alo[mt], stb + SM_ALO + sw);
            }
            uint32_t bhi[2][4];
#pragma unroll
            for (int np = 0; np < 2; np++) {
                uint32_t sw = sw_off(wn + np * 16 + b_r, ks * 2 + b_c);
                LDSM_X4(bhi[np], stb + SM_BHI + sw);
            }
#pragma unroll
            for (int mt = 0; mt < 4; mt++) {
#pragma unroll
                for (int nt = 0; nt < 4; nt++) {
                    uint32_t bh0 = bhi[nt >> 1][(nt & 1) * 2];
                    uint32_t bh1 = bhi[nt >> 1][(nt & 1) * 2 + 1];
                    MMA_F16(acc[mt][nt], ahi[mt], bh0, bh1);
                    MMA_F16(acc[mt][nt], alo[mt], bh0, bh1);
                }
            }
        }
        __syncthreads();   // stage fully consumed before it is overwritten
    }

    // Epilogue
    const int erow = lane >> 2;
    const int ecol = (lane & 3) * 2;
#pragma unroll
    for (int mt = 0; mt < 4; mt++) {
        int r0g = row0 + wm + mt * 16 + erow;
#pragma unroll
        for (int nt = 0; nt < 4; nt++) {
            int colg = col0 + wn + nt * 8 + ecol;
            float b0 = bias ? bias[colg] : 0.f;
            float b1 = bias ? bias[colg + 1] : 0.f;
            if (r0g < M) {
                float2 v = make_float2(acc[mt][nt][0] + b0, acc[mt][nt][1] + b1);
                *(float2*)&C[(size_t)r0g * EMBED + colg] = v;
            }
            if (r0g + 8 < M) {
                float2 v = make_float2(acc[mt][nt][2] + b0, acc[mt][nt][3] + b1);
                *(float2*)&C[(size_t)(r0g + 8) * EMBED + colg] = v;
            }
        }
    }
}

__global__ __launch_bounds__(256) void qkv_mma_kernel(const float* __restrict__ qb,
                                                      const float* __restrict__ vb) {
    int z = blockIdx.z;
    const float* bias = (z == 0) ? qb : ((z == 2) ? vb : nullptr);
    float* C = (z == 0) ? g_q : ((z == 1) ? g_k : g_v);
    mma_gemm_body(g_ahi, g_alo, g_whi[z], bias, C, T_TOTAL);
}

__global__ __launch_bounds__(256) void out_mma_kernel(const float* __restrict__ ob,
                                                      float* __restrict__ out) {
    mma_gemm_body(g_chi, g_clo, g_whi[3], ob, out, T_TOTAL);
}

// ------------------------- RoPE (unchanged) -------------------------
__global__ void rope_kernel(const float* __restrict__ cosp, const float* __restrict__ sinp) {
    int idx = blockIdx.x * blockDim.x + threadIdx.x;
    if (idx >= T_TOTAL * NHEADS * 32) return;
    int d = idx & 31;
    int h = (idx >> 5) & (NHEADS - 1);
    int t = idx >> 9;
    float c = cosp[t * HDIM + d];
    float s = sinp[t * HDIM + d];
    size_t base = (size_t)t * EMBED + h * HDIM + d;

    float q1 = g_q[base], q2 = g_q[base + 32];
    g_q[base]      = q1 * c - q2 * s;
    g_q[base + 32] = q2 * c + q1 * s;

    float k1 = g_k[base], k2 = g_k[base + 32];
    g_k[base]      = k1 * c - k2 * s;
    g_k[base + 32] = k2 * c + k1 * s;
}

// ------------------------- flash attention (fp32; epilogue writes hi/lo) ----
__global__ __launch_bounds__(256) void flash_kernel() {
    extern __shared__ float sm[];
    float* Qs = sm;
    float* Ks = Qs + 64 * 65;
    float* Vs = Ks + 64 * 65;
    float* Ps = Vs + 64 * 65;

    const int tid = threadIdx.x;
    const int tx = tid & 15;
    const int ty = tid >> 4;
    const int h = blockIdx.y;

    int rem = blockIdx.x, b = 0;
    while (rem >= c_nt[b]) { rem -= c_nt[b]; ++b; }
    const int qt = rem;
    const int tok0 = c_cu[b];
    const int tokq = tok0 + qt * 64;

#pragma unroll
    for (int it = 0; it < 4; it++) {
        int idx = it * 256 + tid;
        int r = idx >> 4;
        int c4 = (idx & 15) * 4;
        float4 v = *(const float4*)&g_q[(size_t)(tokq + r) * EMBED + h * HDIM + c4];
        Qs[r * 65 + c4 + 0] = v.x * 0.125f;
        Qs[r * 65 + c4 + 1] = v.y * 0.125f;
        Qs[r * 65 + c4 + 2] = v.z * 0.125f;
        Qs[r * 65 + c4 + 3] = v.w * 0.125f;
    }

    float m_i[4], l_i[4], o[4][4];
#pragma unroll
    for (int i = 0; i < 4; i++) {
        m_i[i] = -1e30f;
        l_i[i] = 0.0f;
#pragma unroll
        for (int j = 0; j < 4; j++) o[i][j] = 0.0f;
    }

    for (int kt = 0; kt <= qt; kt++) {
        __syncthreads();
        const int tokk = tok0 + kt * 64;
#pragma unroll
        for (int it = 0; it < 4; it++) {
            int idx = it * 256 + tid;
            int r = idx >> 4;
            int c4 = (idx & 15) * 4;
            float4 kv = *(const float4*)&g_k[(size_t)(tokk + r) * EMBED + h * HDIM + c4];
            Ks[r * 65 + c4 + 0] = kv.x;
            Ks[r * 65 + c4 + 1] = kv.y;
            Ks[r * 65 + c4 + 2] = kv.z;
            Ks[r * 65 + c4 + 3] = kv.w;
            float4 vv = *(const float4*)&g_v[(size_t)(tokk + r) * EMBED + h * HDIM + c4];
            Vs[r * 65 + c4 + 0] = vv.x;
            Vs[r * 65 + c4 + 1] = vv.y;
            Vs[r * 65 + c4 + 2] = vv.z;
            Vs[r * 65 + c4 + 3] = vv.w;
        }
        __syncthreads();

        float s[4][4];
#pragma unroll
        for (int i = 0; i < 4; i++)
#pragma unroll
            for (int j = 0; j < 4; j++) s[i][j] = 0.0f;

#pragma unroll 8
        for (int k = 0; k < 64; k++) {
            float a0 = Qs[(ty * 4 + 0) * 65 + k];
            float a1 = Qs[(ty * 4 + 1) * 65 + k];
            float a2 = Qs[(ty * 4 + 2) * 65 + k];
            float a3 = Qs[(ty * 4 + 3) * 65 + k];
            float b0 = Ks[(tx * 4 + 0) * 65 + k];
            float b1 = Ks[(tx * 4 + 1) * 65 + k];
            float b2 = Ks[(tx * 4 + 2) * 65 + k];
            float b3 = Ks[(tx * 4 + 3) * 65 + k];
            s[0][0] = fmaf(a0, b0, s[0][0]); s[0][1] = fmaf(a0, b1, s[0][1]);
            s[0][2] = fmaf(a0, b2, s[0][2]); s[0][3] = fmaf(a0, b3, s[0][3]);
            s[1][0] = fmaf(a1, b0, s[1][0]); s[1][1] = fmaf(a1, b1, s[1][1]);
            s[1][2] = fmaf(a1, b2, s[1][2]); s[1][3] = fmaf(a1, b3, s[1][3]);
            s[2][0] = fmaf(a2, b0, s[2][0]); s[2][1] = fmaf(a2, b1, s[2][1]);
            s[2][2] = fmaf(a2, b2, s[2][2]); s[2][3] = fmaf(a2, b3, s[2][3]);
            s[3][0] = fmaf(a3, b0, s[3][0]); s[3][1] = fmaf(a3, b1, s[3][1]);
            s[3][2] = fmaf(a3, b2, s[3][2]); s[3][3] = fmaf(a3, b3, s[3][3]);
        }

        if (kt == qt) {
#pragma unroll
            for (int i = 0; i < 4; i++)
#pragma unroll
                for (int j = 0; j < 4; j++)
                    if (ty * 4 + i < tx * 4 + j) s[i][j] = -1e30f;
        }

#pragma unroll
        for (int i = 0; i < 4; i++) {
            float tm = fmaxf(fmaxf(s[i][0], s[i][1]), fmaxf(s[i][2], s[i][3]));
#pragma unroll
            for (int w = 8; w >= 1; w >>= 1)
                tm = fmaxf(tm, __shfl_xor_sync(0xffffffffu, tm, w, 32));
            float mn = fmaxf(m_i[i], tm);
            float alpha = __expf(m_i[i] - mn);
            float rs = 0.0f;
#pragma unroll
            for (int j = 0; j < 4; j++) {
                float p = __expf(s[i][j] - mn);
                s[i][j] = p;
                rs += p;
            }
#pragma unroll
            for (int w = 8; w >= 1; w >>= 1)
                rs += __shfl_xor_sync(0xffffffffu, rs, w, 32);
            l_i[i] = l_i[i] * alpha + rs;
            m_i[i] = mn;
#pragma unroll
            for (int j = 0; j < 4; j++) {
                o[i][j] *= alpha;
                Ps[(ty * 4 + i) * 65 + tx * 4 + j] = s[i][j];
            }
        }
        __syncthreads();

#pragma unroll 8
        for (int n = 0; n < 64; n++) {
            float p0 = Ps[(ty * 4 + 0) * 65 + n];
            float p1 = Ps[(ty * 4 + 1) * 65 + n];
            float p2 = Ps[(ty * 4 + 2) * 65 + n];
            float p3 = Ps[(ty * 4 + 3) * 65 + n];
            float v0 = Vs[n * 65 + tx * 4 + 0];
            float v1 = Vs[n * 65 + tx * 4 + 1];
            float v2 = Vs[n * 65 + tx * 4 + 2];
            float v3 = Vs[n * 65 + tx * 4 + 3];
            o[0][0] = fmaf(p0, v0, o[0][0]); o[0][1] = fmaf(p0, v1, o[0][1]);
            o[0][2] = fmaf(p0, v2, o[0][2]); o[0][3] = fmaf(p0, v3, o[0][3]);
            o[1][0] = fmaf(p1, v0, o[1][0]); o[1][1] = fmaf(p1, v1, o[1][1]);
            o[1][2] = fmaf(p1, v2, o[1][2]); o[1][3] = fmaf(p1, v3, o[1][3]);
            o[2][0] = fmaf(p2, v0, o[2][0]); o[2][1] = fmaf(p2, v1, o[2][1]);
            o[2][2] = fmaf(p2, v2, o[2][2]); o[2][3] = fmaf(p2, v3, o[2][3]);
            o[3][0] = fmaf(p3, v0, o[3][0]); o[3][1] = fmaf(p3, v1, o[3][1]);
            o[3][2] = fmaf(p3, v2, o[3][2]); o[3][3] = fmaf(p3, v3, o[3][3]);
        }
    }

    // Epilogue: normalize + write fp16 hi/lo split directly (fused split)
#pragma unroll
    for (int i = 0; i < 4; i++) {
        float inv = 1.0f / l_i[i];
        size_t base = (size_t)(tokq + ty * 4 + i) * EMBED + h * HDIM + tx * 4;
        union { __half b[4]; uint2 u; } H, L;
#pragma unroll
        for (int j = 0; j < 4; j++) {
            float v = o[i][j] * inv;
            __half hb = __float2half(v);
            H.b[j] = hb;
            L.b[j] = __float2half(v - __half2float(hb));
        }
        *(uint2*)&g_chi[base] = H.u;
        *(uint2*)&g_clo[base] = L.u;
    }
}

// ---------------------------------------------------------------------------
extern "C" void kernel_launch(void* const* d_in, const int* in_sizes, int n_in,
                              void* d_out, int out_size)
{
    const float* hidden = (const float*)d_in[0];
    const float* cosp   = (const float*)d_in[1];
    const float* sinp   = (const float*)d_in[2];
    const float* q_w    = (const float*)d_in[3];
    const float* q_b    = (const float*)d_in[4];
    const float* k_w    = (const float*)d_in[5];
    const float* v_w    = (const float*)d_in[6];
    const float* v_b    = (const float*)d_in[7];
    const float* out_w  = (const float*)d_in[8];
    const float* out_b  = (const float*)d_in[9];
    float* out = (float*)d_out;

    __half *pahi, *palo;
    cudaGetSymbolAddress((void**)&pahi, g_ahi);
    cudaGetSymbolAddress((void**)&palo, g_alo);

    // 1. Split hidden -> fp16 hi/lo
    {
        int n4 = T_TOTAL * EMBED / 4;
        split_kernel<<<(n4 + 255) / 256, 256>>>(hidden, pahi, palo, n4);
    }
    // 2. Convert weights -> fp16 hi (z = q,k,v,out)
    {
        int n4 = EMBED * EMBED / 4;
        dim3 g((n4 + 255) / 256, 1, 4);
        split_w_kernel<<<g, 256>>>(q_w, k_w, v_w, out_w);
    }
    // 3. QKV GEMMs via pipelined warp MMA (fp16x2)
    cudaFuncSetAttribute(qkv_mma_kernel, cudaFuncAttributeMaxDynamicSharedMemorySize, SM_TOTAL);
    qkv_mma_kernel<<<dim3(EMBED / 128, MTILES, 3), 256, SM_TOTAL>>>(q_b, v_b);

    // 4. RoPE
    int nrope = T_TOTAL * NHEADS * 32;
    rope_kernel<<<(nrope + 255) / 256, 256>>>(cosp, sinp);

    // 5. Flash attention (writes g_chi/g_clo directly)
    const int smem_bytes = 4 * 64 * 65 * (int)sizeof(float);
    cudaFuncSetAttribute(flash_kernel, cudaFuncAttributeMaxDynamicSharedMemorySize, smem_bytes);
    flash_kernel<<<dim3(153, 16), 256, smem_bytes>>>();

    // 6. Output GEMM via pipelined warp MMA
    cudaFuncSetAttribute(out_mma_kernel, cudaFuncAttributeMaxDynamicSharedMemorySize, SM_TOTAL);
    out_mma_kernel<<<dim3(EMBED / 128, MTILES, 1), 256, SM_TOTAL>>>(out_b, out);
}

// round 8
// speedup vs baseline: 4.5745x; 1.8234x over previous
#include <cuda_runtime.h>
#include <cuda_fp16.h>
#include <cstdint>

#define T_TOTAL 9792
#define EMBED   1024
#define NHEADS  16
#define HDIM    64
#define MTILES  77          // ceil(9792/128)

// ------------------------- scratch (static device) -------------------------
__device__ float g_q[(size_t)T_TOTAL * EMBED];   // fp32 q before rope
__device__ float g_k[(size_t)T_TOTAL * EMBED];   // fp32 k before rope

__device__ __half g_ahi[(size_t)T_TOTAL * EMBED];
__device__ __half g_alo[(size_t)T_TOTAL * EMBED];
__device__ __half g_chi[(size_t)T_TOTAL * EMBED];
__device__ __half g_clo[(size_t)T_TOTAL * EMBED];
__device__ __half g_whi[4][(size_t)EMBED * EMBED];

__device__ __half g_qhi[(size_t)T_TOTAL * EMBED];  // rope'd q * 0.125, hi
__device__ __half g_qlo[(size_t)T_TOTAL * EMBED];  // rope'd q * 0.125, lo
__device__ __half g_kh [(size_t)T_TOTAL * EMBED];  // rope'd k, fp16
__device__ __half g_vh [(size_t)T_TOTAL * EMBED];  // v, fp16 (GEMM epilogue)

__constant__ int c_cu[12] = {0, 1024, 1792, 2688, 3200, 4224, 4864, 5888, 6656, 7168, 8064, 9088};
__constant__ int c_nt[12] = {16, 12, 14, 8, 16, 10, 16, 12, 8, 14, 16, 11};

// ------------------------- PTX helpers (baseline ISA only) ------------------
__device__ __forceinline__ uint32_t smem_u32(const void* p) {
    uint32_t a;
    asm("{ .reg .u64 t; cvta.to.shared.u64 t, %1; cvt.u32.u64 %0, t; }" : "=r"(a) : "l"(p));
    return a;
}

#define LDSM_X4(R, addr)                                                      \
    asm volatile("ldmatrix.sync.aligned.m8n8.x4.shared.b16 {%0,%1,%2,%3}, [%4];" \
        : "=r"((R)[0]), "=r"((R)[1]), "=r"((R)[2]), "=r"((R)[3]) : "r"(addr))

#define LDSM_X4_T(R, addr)                                                    \
    asm volatile("ldmatrix.sync.aligned.m8n8.x4.trans.shared.b16 {%0,%1,%2,%3}, [%4];" \
        : "=r"((R)[0]), "=r"((R)[1]), "=r"((R)[2]), "=r"((R)[3]) : "r"(addr))

#define MMA_F16(C, A, B0, B1)                                                 \
    asm volatile("mma.sync.aligned.m16n8k16.row.col.f32.f16.f16.f32 "         \
        "{%0,%1,%2,%3}, {%4,%5,%6,%7}, {%8,%9}, {%0,%1,%2,%3};"               \
        : "+f"((C)[0]), "+f"((C)[1]), "+f"((C)[2]), "+f"((C)[3])              \
        : "r"((A)[0]), "r"((A)[1]), "r"((A)[2]), "r"((A)[3]), "r"(B0), "r"(B1))

__device__ __forceinline__ void cp16(uint32_t dst, const void* src, int srcbytes) {
    asm volatile("cp.async.cg.shared.global [%0], [%1], 16, %2;"
                 :: "r"(dst), "l"(src), "r"(srcbytes) : "memory");
}
#define CP_COMMIT() asm volatile("cp.async.commit_group;" ::: "memory")
#define CP_WAIT(N)  asm volatile("cp.async.wait_group %0;" :: "n"(N) : "memory")

__device__ __forceinline__ uint32_t pack_h2(__half a, __half b) {
    __half2 t = __halves2half2(a, b);
    return *(uint32_t*)&t;
}

// ------------------------- fp32 -> fp16 hi/lo split -------------------------
__global__ void split_kernel(const float* __restrict__ src, __half* __restrict__ hi,
                             __half* __restrict__ lo, int n4) {
    int i = blockIdx.x * blockDim.x + threadIdx.x;
    if (i >= n4) return;
    float4 v = ((const float4*)src)[i];
    union { __half b[4]; uint2 u; } H, L;
    float x[4] = {v.x, v.y, v.z, v.w};
#pragma unroll
    for (int j = 0; j < 4; j++) {
        __half h = __float2half(x[j]);
        H.b[j] = h;
        L.b[j] = __float2half(x[j] - __half2float(h));
    }
    ((uint2*)hi)[i] = H.u;
    ((uint2*)lo)[i] = L.u;
}

__global__ void split_w_kernel(const float* __restrict__ w0, const float* __restrict__ w1,
                               const float* __restrict__ w2, const float* __restrict__ w3) {
    int z = blockIdx.z;
    const float* src = (z == 0) ? w0 : (z == 1) ? w1 : (z == 2) ? w2 : w3;
    int i = blockIdx.x * blockDim.x + threadIdx.x;
    int n4 = EMBED * EMBED / 4;
    if (i >= n4) return;
    float4 v = ((const float4*)src)[i];
    union { __half b[4]; uint2 u; } H;
    H.b[0] = __float2half(v.x);
    H.b[1] = __float2half(v.y);
    H.b[2] = __float2half(v.z);
    H.b[3] = __float2half(v.w);
    ((uint2*)g_whi[z])[i] = H.u;
}

// ------------------------- warp-MMA GEMM: C[M,1024] = A @ W^T (+bias) -------
#define SM_AHI  0
#define SM_ALO  16384
#define SM_BHI  32768
#define SM_STAGE 49152
#define SM_TOTAL 98304

__device__ __forceinline__ uint32_t sw_off(int r, int chunk) {
    uint32_t off = (uint32_t)(r * 128 + chunk * 16);
    return off ^ ((off >> 3) & 0x70);
}

__device__ __forceinline__ void mma_gemm_body(
    const __half* __restrict__ Ahi, const __half* __restrict__ Alo,
    const __half* __restrict__ Bhi,
    const float* __restrict__ bias, float* __restrict__ C,
    __half* __restrict__ Ch, int M)
{
    extern __shared__ char smem[];
    const uint32_t sb = smem_u32(smem);
    const int tid = threadIdx.x;
    const int wid = tid >> 5, lane = tid & 31;
    const int row0 = blockIdx.y * 128;
    const int col0 = blockIdx.x * 128;
    const int wm = (wid & 1) * 64;
    const int wn = (wid >> 1) * 32;

    float acc[4][4][4];
#pragma unroll
    for (int a = 0; a < 4; a++)
#pragma unroll
        for (int b = 0; b < 4; b++)
#pragma unroll
            for (int c = 0; c < 4; c++) acc[a][b][c] = 0.0f;

    const int l_r[4] = { (tid + 0) >> 3, (tid + 256) >> 3, (tid + 512) >> 3, (tid + 768) >> 3 };
    const int l_c = tid & 7;

    const int a_r = lane & 15;
    const int a_c = lane >> 4;
    const int b_r = ((lane >> 4) << 3) + (lane & 7);
    const int b_c = (lane >> 3) & 1;

    auto load_tile = [&](int kt, int stage) {
        const int k0 = kt * 64;
        const uint32_t stb = sb + stage * SM_STAGE;
#pragma unroll
        for (int j = 0; j < 4; j++) {
            int r = l_r[j];
            uint32_t sw = sw_off(r, l_c);
            int apred = (row0 + r < M) ? 16 : 0;
            size_t aoff = (size_t)(row0 + r) * EMBED + k0 + l_c * 8;
            size_t boff = (size_t)(col0 + r) * EMBED + k0 + l_c * 8;
            cp16(stb + SM_AHI + sw, Ahi + aoff, apred);
            cp16(stb + SM_ALO + sw, Alo + aoff, apred);
            cp16(stb + SM_BHI + sw, Bhi + boff, 16);
        }
        CP_COMMIT();
    };

    load_tile(0, 0);

    for (int kt = 0; kt < 16; kt++) {
        const int stage = kt & 1;
        if (kt + 1 < 16) {
            load_tile(kt + 1, stage ^ 1);
            CP_WAIT(1);
        } else {
            CP_WAIT(0);
        }
        __syncthreads();

        const uint32_t stb = sb + stage * SM_STAGE;
#pragma unroll
        for (int ks = 0; ks < 4; ks++) {
            uint32_t ahi[4][4], alo[4][4];
#pragma unroll
            for (int mt = 0; mt < 4; mt++) {
                uint32_t sw = sw_off(wm + mt * 16 + a_r, ks * 2 + a_c);
                LDSM_X4(ahi[mt], stb + SM_AHI + sw);
                LDSM_X4(alo[mt], stb + SM_ALO + sw);
            }
            uint32_t bhi[2][4];
#pragma unroll
            for (int np = 0; np < 2; np++) {
                uint32_t sw = sw_off(wn + np * 16 + b_r, ks * 2 + b_c);
                LDSM_X4(bhi[np], stb + SM_BHI + sw);
            }
#pragma unroll
            for (int mt = 0; mt < 4; mt++) {
#pragma unroll
                for (int nt = 0; nt < 4; nt++) {
                    uint32_t bh0 = bhi[nt >> 1][(nt & 1) * 2];
                    uint32_t bh1 = bhi[nt >> 1][(nt & 1) * 2 + 1];
                    MMA_F16(acc[mt][nt], ahi[mt], bh0, bh1);
                    MMA_F16(acc[mt][nt], alo[mt], bh0, bh1);
                }
            }
        }
        __syncthreads();
    }

    // Epilogue
    const int erow = lane >> 2;
    const int ecol = (lane & 3) * 2;
#pragma unroll
    for (int mt = 0; mt < 4; mt++) {
        int r0g = row0 + wm + mt * 16 + erow;
#pragma unroll
        for (int nt = 0; nt < 4; nt++) {
            int colg = col0 + wn + nt * 8 + ecol;
            float b0 = bias ? bias[colg] : 0.f;
            float b1 = bias ? bias[colg + 1] : 0.f;
            if (Ch) {
                if (r0g < M) {
                    __half2 v = __floats2half2_rn(acc[mt][nt][0] + b0, acc[mt][nt][1] + b1);
                    *(__half2*)&Ch[(size_t)r0g * EMBED + colg] = v;
                }
                if (r0g + 8 < M) {
                    __half2 v = __floats2half2_rn(acc[mt][nt][2] + b0, acc[mt][nt][3] + b1);
                    *(__half2*)&Ch[(size_t)(r0g + 8) * EMBED + colg] = v;
                }
            } else {
                if (r0g < M) {
                    float2 v = make_float2(acc[mt][nt][0] + b0, acc[mt][nt][1] + b1);
                    *(float2*)&C[(size_t)r0g * EMBED + colg] = v;
                }
                if (r0g + 8 < M) {
                    float2 v = make_float2(acc[mt][nt][2] + b0, acc[mt][nt][3] + b1);
                    *(float2*)&C[(size_t)(r0g + 8) * EMBED + colg] = v;
                }
            }
        }
    }
}

__global__ __launch_bounds__(256) void qkv_mma_kernel(const float* __restrict__ qb,
                                                      const float* __restrict__ vb) {
    int z = blockIdx.z;
    const float* bias = (z == 0) ? qb : ((z == 2) ? vb : nullptr);
    float* C = (z == 0) ? g_q : ((z == 1) ? g_k : nullptr);
    __half* Ch = (z == 2) ? g_vh : nullptr;
    mma_gemm_body(g_ahi, g_alo, g_whi[z], bias, C, Ch, T_TOTAL);
}

__global__ __launch_bounds__(256) void out_mma_kernel(const float* __restrict__ ob,
                                                      float* __restrict__ out) {
    mma_gemm_body(g_chi, g_clo, g_whi[3], ob, out, nullptr, T_TOTAL);
}

// ------------------------- RoPE: fp32 in -> fp16 out (q scaled+split, k) ----
__global__ void rope_kernel(const float* __restrict__ cosp, const float* __restrict__ sinp) {
    int idx = blockIdx.x * blockDim.x + threadIdx.x;
    if (idx >= T_TOTAL * NHEADS * 32) return;
    int d = idx & 31;
    int h = (idx >> 5) & (NHEADS - 1);
    int t = idx >> 9;
    float c = cosp[t * HDIM + d];
    float s = sinp[t * HDIM + d];
    size_t base = (size_t)t * EMBED + h * HDIM + d;

    float q1 = g_q[base], q2 = g_q[base + 32];
    float q1r = (q1 * c - q2 * s) * 0.125f;
    float q2r = (q2 * c + q1 * s) * 0.125f;
    __half h1 = __float2half(q1r);
    __half h2 = __float2half(q2r);
    g_qhi[base]      = h1;
    g_qhi[base + 32] = h2;
    g_qlo[base]      = __float2half(q1r - __half2float(h1));
    g_qlo[base + 32] = __float2half(q2r - __half2float(h2));

    float k1 = g_k[base], k2 = g_k[base + 32];
    g_kh[base]      = __float2half(k1 * c - k2 * s);
    g_kh[base + 32] = __float2half(k2 * c + k1 * s);
}

// ------------------------- flash attention (fp16 MMA, 2-pass) ---------------
// CTA = 128 threads (4 warps), 64 q-rows x 64-key tiles, warp = 16 rows.
// smem: Qhi 8K | Qlo 8K | stage0 {K 8K, V 8K} | stage1 {K 8K, V 8K} = 48KB
#define FSM_QHI 0
#define FSM_QLO 8192
#define FSM_KV  16384
#define FSM_TOTAL 49152

__global__ __launch_bounds__(128) void flash_kernel() {
    extern __shared__ char smem[];
    const uint32_t sb = smem_u32(smem);
    const int tid = threadIdx.x;
    const int wid = tid >> 5, lane = tid & 31;
    const int h = blockIdx.y;

    int rem = blockIdx.x, b = 0;
    while (rem >= c_nt[b]) { rem -= c_nt[b]; ++b; }
    const int qt = rem;
    const int tok0 = c_cu[b];
    const int tokq = tok0 + qt * 64;

    auto kvload = [&](int kt, int stage) {
        const int tokk = tok0 + kt * 64;
        const uint32_t kb = sb + FSM_KV + stage * 16384;
#pragma unroll
        for (int j = 0; j < 4; j++) {
            int idx = tid + j * 128;
            int r = idx >> 3;
            int c = idx & 7;
            uint32_t sw = sw_off(r, c);
            size_t go = (size_t)(tokk + r) * EMBED + h * HDIM + c * 8;
            cp16(kb + sw, g_kh + go, 16);
            cp16(kb + 8192 + sw, g_vh + go, 16);
        }
    };

    // Q tile + first K/V tile
#pragma unroll
    for (int j = 0; j < 4; j++) {
        int idx = tid + j * 128;
        int r = idx >> 3;
        int c = idx & 7;
        uint32_t sw = sw_off(r, c);
        size_t go = (size_t)(tokq + r) * EMBED + h * HDIM + c * 8;
        cp16(sb + FSM_QHI + sw, g_qhi + go, 16);
        cp16(sb + FSM_QLO + sw, g_qlo + go, 16);
    }
    kvload(0, 0);
    CP_COMMIT();
    CP_WAIT(0);
    __syncthreads();

    // Q fragments (held in registers the whole kernel)
    uint32_t qhi[4][4], qlo[4][4];
    {
        const int a_row = wid * 16 + (lane & 15);
        const int a_c = lane >> 4;
#pragma unroll
        for (int ks = 0; ks < 4; ks++) {
            uint32_t sw = sw_off(a_row, ks * 2 + a_c);
            LDSM_X4(qhi[ks], sb + FSM_QHI + sw);
            LDSM_X4(qlo[ks], sb + FSM_QLO + sw);
        }
    }

    float oacc[8][4];
#pragma unroll
    for (int n = 0; n < 8; n++)
#pragma unroll
        for (int c = 0; c < 4; c++) oacc[n][c] = 0.0f;
    float m0 = -1e30f, m1 = -1e30f, l0 = 0.0f, l1 = 0.0f;

    const int b_r = ((lane >> 4) << 3) + (lane & 7);
    const int b_c = (lane >> 3) & 1;
    // ldmatrix.trans lane mapping for V (see fragment analysis)
    const int v_row = ((lane >> 3) & 1) * 8 + (lane & 7);
    const int v_ch  = lane >> 4;

    for (int kt = 0; kt <= qt; kt++) {
        const int stage = kt & 1;
        if (kt < qt) {
            kvload(kt + 1, stage ^ 1);
            CP_COMMIT();
            CP_WAIT(1);
        } else {
            CP_WAIT(0);
        }
        __syncthreads();

        const uint32_t kbase = sb + FSM_KV + stage * 16384;
        const uint32_t vbase = kbase + 8192;

        // S = Q @ K^T (2-pass: Qhi + Qlo)
        float sacc[8][4];
#pragma unroll
        for (int n = 0; n < 8; n++)
#pragma unroll
            for (int c = 0; c < 4; c++) sacc[n][c] = 0.0f;

#pragma unroll
        for (int ks = 0; ks < 4; ks++) {
            uint32_t kf[4][4];
#pragma unroll
            for (int np = 0; np < 4; np++) {
                uint32_t sw = sw_off(np * 16 + b_r, ks * 2 + b_c);
                LDSM_X4(kf[np], kbase + sw);
            }
#pragma unroll
            for (int nt = 0; nt < 8; nt++) {
                uint32_t b0 = kf[nt >> 1][(nt & 1) * 2];
                uint32_t b1 = kf[nt >> 1][(nt & 1) * 2 + 1];
                MMA_F16(sacc[nt], qhi[ks], b0, b1);
                MMA_F16(sacc[nt], qlo[ks], b0, b1);
            }
        }

        // causal mask on diagonal tile
        if (kt == qt) {
            const int r0 = wid * 16 + (lane >> 2);
#pragma unroll
            for (int nt = 0; nt < 8; nt++) {
                int c0 = nt * 8 + (lane & 3) * 2;
                if (c0 > r0) sacc[nt][0] = -1e30f;
                if (c0 + 1 > r0) sacc[nt][1] = -1e30f;
                if (c0 > r0 + 8) sacc[nt][2] = -1e30f;
                if (c0 + 1 > r0 + 8) sacc[nt][3] = -1e30f;
            }
        }

        // online softmax
        {
            float tm0 = -1e30f, tm1 = -1e30f;
#pragma unroll
            for (int nt = 0; nt < 8; nt++) {
                tm0 = fmaxf(tm0, fmaxf(sacc[nt][0], sacc[nt][1]));
                tm1 = fmaxf(tm1, fmaxf(sacc[nt][2], sacc[nt][3]));
            }
            tm0 = fmaxf(tm0, __shfl_xor_sync(0xffffffffu, tm0, 1, 32));
            tm0 = fmaxf(tm0, __shfl_xor_sync(0xffffffffu, tm0, 2, 32));
            tm1 = fmaxf(tm1, __shfl_xor_sync(0xffffffffu, tm1, 1, 32));
            tm1 = fmaxf(tm1, __shfl_xor_sync(0xffffffffu, tm1, 2, 32));
            float mn0 = fmaxf(m0, tm0), mn1 = fmaxf(m1, tm1);
            float al0 = __expf(m0 - mn0), al1 = __expf(m1 - mn1);
            float rs0 = 0.0f, rs1 = 0.0f;
#pragma unroll
            for (int nt = 0; nt < 8; nt++) {
                sacc[nt][0] = __expf(sacc[nt][0] - mn0); rs0 += sacc[nt][0];
                sacc[nt][1] = __expf(sacc[nt][1] - mn0); rs0 += sacc[nt][1];
                sacc[nt][2] = __expf(sacc[nt][2] - mn1); rs1 += sacc[nt][2];
                sacc[nt][3] = __expf(sacc[nt][3] - mn1); rs1 += sacc[nt][3];
            }
            rs0 += __shfl_xor_sync(0xffffffffu, rs0, 1, 32);
            rs0 += __shfl_xor_sync(0xffffffffu, rs0, 2, 32);
            rs1 += __shfl_xor_sync(0xffffffffu, rs1, 1, 32);
            rs1 += __shfl_xor_sync(0xffffffffu, rs1, 2, 32);
            l0 = l0 * al0 + rs0; m0 = mn0;
            l1 = l1 * al1 + rs1; m1 = mn1;
#pragma unroll
            for (int n = 0; n < 8; n++) {
                oacc[n][0] *= al0; oacc[n][1] *= al0;
                oacc[n][2] *= al1; oacc[n][3] *= al1;
            }
        }

        // O += P @ V (2-pass: Phi + Plo, V via ldmatrix.trans)
#pragma unroll
        for (int ks = 0; ks < 4; ks++) {
            // repack S acc tiles 2ks, 2ks+1 into A fragments (hi/lo split)
            uint32_t ph[4], pl[4];
            {
                float* s0 = sacc[2 * ks];
                float* s1 = sacc[2 * ks + 1];
                __half h00 = __float2half(s0[0]), h01 = __float2half(s0[1]);
                __half h02 = __float2half(s0[2]), h03 = __float2half(s0[3]);
                __half h10 = __float2half(s1[0]), h11 = __float2half(s1[1]);
                __half h12 = __float2half(s1[2]), h13 = __float2half(s1[3]);
                ph[0] = pack_h2(h00, h01);
                ph[1] = pack_h2(h02, h03);
                ph[2] = pack_h2(h10, h11);
                ph[3] = pack_h2(h12, h13);
                pl[0] = pack_h2(__float2half(s0[0] - __half2float(h00)),
                                __float2half(s0[1] - __half2float(h01)));
                pl[1] = pack_h2(__float2half(s0[2] - __half2float(h02)),
                                __float2half(s0[3] - __half2float(h03)));
                pl[2] = pack_h2(__float2half(s1[0] - __half2float(h10)),
                                __float2half(s1[1] - __half2float(h11)));
                pl[3] = pack_h2(__float2half(s1[2] - __half2float(h12)),
                                __float2half(s1[3] - __half2float(h13)));
            }
#pragma unroll
            for (int nd2 = 0; nd2 < 4; nd2++) {
                uint32_t vf[4];
                uint32_t sw = sw_off(ks * 16 + v_row, nd2 * 2 + v_ch);
                LDSM_X4_T(vf, vbase + sw);
                MMA_F16(oacc[nd2 * 2],     ph, vf[0], vf[1]);
                MMA_F16(oacc[nd2 * 2],     pl, vf[0], vf[1]);
                MMA_F16(oacc[nd2 * 2 + 1], ph, vf[2], vf[3]);
                MMA_F16(oacc[nd2 * 2 + 1], pl, vf[2], vf[3]);
            }
        }
        __syncthreads();
    }

    // Epilogue: normalize + write fp16 hi/lo split (input of out-proj GEMM)
    {
        float inv0 = 1.0f / l0;
        float inv1 = 1.0f / l1;
        int gr0 = tokq + wid * 16 + (lane >> 2);
        int gr1 = gr0 + 8;
#pragma unroll
        for (int nt = 0; nt < 8; nt++) {
            int col = h * HDIM + nt * 8 + (lane & 3) * 2;
            {
                float v0 = oacc[nt][0] * inv0, v1 = oacc[nt][1] * inv0;
                __half h0 = __float2half(v0), h1 = __float2half(v1);
                *(__half2*)&g_chi[(size_t)gr0 * EMBED + col] = __halves2half2(h0, h1);
                *(__half2*)&g_clo[(size_t)gr0 * EMBED + col] =
                    __halves2half2(__float2half(v0 - __half2float(h0)),
                                   __float2half(v1 - __half2float(h1)));
            }
            {
                float v0 = oacc[nt][2] * inv1, v1 = oacc[nt][3] * inv1;
                __half h0 = __float2half(v0), h1 = __float2half(v1);
                *(__half2*)&g_chi[(size_t)gr1 * EMBED + col] = __halves2half2(h0, h1);
                *(__half2*)&g_clo[(size_t)gr1 * EMBED + col] =
                    __halves2half2(__float2half(v0 - __half2float(h0)),
                                   __float2half(v1 - __half2float(h1)));
            }
        }
    }
}

// ---------------------------------------------------------------------------
extern "C" void kernel_launch(void* const* d_in, const int* in_sizes, int n_in,
                              void* d_out, int out_size)
{
    const float* hidden = (const float*)d_in[0];
    const float* cosp   = (const float*)d_in[1];
    const float* sinp   = (const float*)d_in[2];
    const float* q_w    = (const float*)d_in[3];
    const float* q_b    = (const float*)d_in[4];
    const float* k_w    = (const float*)d_in[5];
    const float* v_w    = (const float*)d_in[6];
    const float* v_b    = (const float*)d_in[7];
    const float* out_w  = (const float*)d_in[8];
    const float* out_b  = (const float*)d_in[9];
    float* out = (float*)d_out;

    __half *pahi, *palo;
    cudaGetSymbolAddress((void**)&pahi, g_ahi);
    cudaGetSymbolAddress((void**)&palo, g_alo);

    // 1. Split hidden -> fp16 hi/lo
    {
        int n4 = T_TOTAL * EMBED / 4;
        split_kernel<<<(n4 + 255) / 256, 256>>>(hidden, pahi, palo, n4);
    }
    // 2. Convert weights -> fp16 (z = q,k,v,out)
    {
        int n4 = EMBED * EMBED / 4;
        dim3 g((n4 + 255) / 256, 1, 4);
        split_w_kernel<<<g, 256>>>(q_w, k_w, v_w, out_w);
    }
    // 3. QKV GEMMs (q,k -> fp32 for rope; v -> fp16 directly)
    cudaFuncSetAttribute(qkv_mma_kernel, cudaFuncAttributeMaxDynamicSharedMemorySize, SM_TOTAL);
    qkv_mma_kernel<<<dim3(EMBED / 128, MTILES, 3), 256, SM_TOTAL>>>(q_b, v_b);

    // 4. RoPE (fp32 -> fp16 q hi/lo scaled, k)
    int nrope = T_TOTAL * NHEADS * 32;
    rope_kernel<<<(nrope + 255) / 256, 256>>>(cosp, sinp);

    // 5. Flash attention (fp16 MMA, writes g_chi/g_clo)
    cudaFuncSetAttribute(flash_kernel, cudaFuncAttributeMaxDynamicSharedMemorySize, FSM_TOTAL);
    flash_kernel<<<dim3(153, NHEADS), 128, FSM_TOTAL>>>();

    // 6. Output GEMM
    cudaFuncSetAttribute(out_mma_kernel, cudaFuncAttributeMaxDynamicSharedMemorySize, SM_TOTAL);
    out_mma_kernel<<<dim3(EMBED / 128, MTILES, 1), 256, SM_TOTAL>>>(out_b, out);
}

// round 9
// speedup vs baseline: 5.1844x; 1.1333x over previous
#include <cuda_runtime.h>
#include <cuda_fp16.h>
#include <cstdint>

#define T_TOTAL 9792
#define EMBED   1024
#define NHEADS  16
#define HDIM    64
#define MTILES  77          // ceil(9792/128)

// ------------------------- scratch (static device) -------------------------
__device__ float g_q[(size_t)T_TOTAL * EMBED];   // fp32 q before rope
__device__ float g_k[(size_t)T_TOTAL * EMBED];   // fp32 k before rope

__device__ __half g_ahi[(size_t)T_TOTAL * EMBED];
__device__ __half g_alo[(size_t)T_TOTAL * EMBED];
__device__ __half g_chi[(size_t)T_TOTAL * EMBED];
__device__ __half g_clo[(size_t)T_TOTAL * EMBED];
__device__ __half g_whi[4][(size_t)EMBED * EMBED];

__device__ __half g_qhi[(size_t)T_TOTAL * EMBED];  // rope'd q * 0.125, hi
__device__ __half g_qlo[(size_t)T_TOTAL * EMBED];  // rope'd q * 0.125, lo
__device__ __half g_kh [(size_t)T_TOTAL * EMBED];  // rope'd k, fp16
__device__ __half g_vh [(size_t)T_TOTAL * EMBED];  // v, fp16 (GEMM epilogue)

__constant__ int c_cu[12] = {0, 1024, 1792, 2688, 3200, 4224, 4864, 5888, 6656, 7168, 8064, 9088};
__constant__ int c_nt[12] = {16, 12, 14, 8, 16, 10, 16, 12, 8, 14, 16, 11};

// ------------------------- PTX helpers (baseline ISA only) ------------------
__device__ __forceinline__ uint32_t smem_u32(const void* p) {
    uint32_t a;
    asm("{ .reg .u64 t; cvta.to.shared.u64 t, %1; cvt.u32.u64 %0, t; }" : "=r"(a) : "l"(p));
    return a;
}

#define LDSM_X4(R, addr)                                                      \
    asm volatile("ldmatrix.sync.aligned.m8n8.x4.shared.b16 {%0,%1,%2,%3}, [%4];" \
        : "=r"((R)[0]), "=r"((R)[1]), "=r"((R)[2]), "=r"((R)[3]) : "r"(addr))

#define LDSM_X4_T(R, addr)                                                    \
    asm volatile("ldmatrix.sync.aligned.m8n8.x4.trans.shared.b16 {%0,%1,%2,%3}, [%4];" \
        : "=r"((R)[0]), "=r"((R)[1]), "=r"((R)[2]), "=r"((R)[3]) : "r"(addr))

#define MMA_F16(C, A, B0, B1)                                                 \
    asm volatile("mma.sync.aligned.m16n8k16.row.col.f32.f16.f16.f32 "         \
        "{%0,%1,%2,%3}, {%4,%5,%6,%7}, {%8,%9}, {%0,%1,%2,%3};"               \
        : "+f"((C)[0]), "+f"((C)[1]), "+f"((C)[2]), "+f"((C)[3])              \
        : "r"((A)[0]), "r"((A)[1]), "r"((A)[2]), "r"((A)[3]), "r"(B0), "r"(B1))

__device__ __forceinline__ void cp16(uint32_t dst, const void* src, int srcbytes) {
    asm volatile("cp.async.cg.shared.global [%0], [%1], 16, %2;"
                 :: "r"(dst), "l"(src), "r"(srcbytes) : "memory");
}
#define CP_COMMIT() asm volatile("cp.async.commit_group;" ::: "memory")
#define CP_WAIT(N)  asm volatile("cp.async.wait_group %0;" :: "n"(N) : "memory")

__device__ __forceinline__ uint32_t pack_h2(__half a, __half b) {
    __half2 t = __halves2half2(a, b);
    return *(uint32_t*)&t;
}

// ------------------------- fp32 -> fp16 hi/lo split -------------------------
__global__ void split_kernel(const float* __restrict__ src, __half* __restrict__ hi,
                             __half* __restrict__ lo, int n4) {
    int i = blockIdx.x * blockDim.x + threadIdx.x;
    if (i >= n4) return;
    float4 v = ((const float4*)src)[i];
    union { __half b[4]; uint2 u; } H, L;
    float x[4] = {v.x, v.y, v.z, v.w};
#pragma unroll
    for (int j = 0; j < 4; j++) {
        __half h = __float2half(x[j]);
        H.b[j] = h;
        L.b[j] = __float2half(x[j] - __half2float(h));
    }
    ((uint2*)hi)[i] = H.u;
    ((uint2*)lo)[i] = L.u;
}

__global__ void split_w_kernel(const float* __restrict__ w0, const float* __restrict__ w1,
                               const float* __restrict__ w2, const float* __restrict__ w3) {
    int z = blockIdx.z;
    const float* src = (z == 0) ? w0 : (z == 1) ? w1 : (z == 2) ? w2 : w3;
    int i = blockIdx.x * blockDim.x + threadIdx.x;
    int n4 = EMBED * EMBED / 4;
    if (i >= n4) return;
    float4 v = ((const float4*)src)[i];
    union { __half b[4]; uint2 u; } H;
    H.b[0] = __float2half(v.x);
    H.b[1] = __float2half(v.y);
    H.b[2] = __float2half(v.z);
    H.b[3] = __float2half(v.w);
    ((uint2*)g_whi[z])[i] = H.u;
}

// ------------------------- warp-MMA GEMM: C[M,1024] = A @ W^T (+bias) -------
// TWOPASS: D = Ahi*Bhi + Alo*Bhi (A split, ~1e-5 on A side)
// !TWOPASS: D = Ahi*Bhi (single pass, ~2.4e-4)
#define SM_TOTAL_2P 98304   // 2 stages x (Ahi 16K + Alo 16K + Bhi 16K)
#define SM_TOTAL_1P 65536   // 2 stages x (Ahi 16K + Bhi 16K)

__device__ __forceinline__ uint32_t sw_off(int r, int chunk) {
    uint32_t off = (uint32_t)(r * 128 + chunk * 16);
    return off ^ ((off >> 3) & 0x70);
}

template<bool TP>
__device__ __forceinline__ void mma_gemm_body(
    const __half* __restrict__ Ahi, const __half* __restrict__ Alo,
    const __half* __restrict__ Bhi,
    const float* __restrict__ bias, float* __restrict__ C,
    __half* __restrict__ Ch, int M)
{
    constexpr uint32_t OFF_ALO  = 16384;
    constexpr uint32_t OFF_BHI  = TP ? 32768 : 16384;
    constexpr uint32_t SM_STAGE = TP ? 49152 : 32768;

    extern __shared__ char smem[];
    const uint32_t sb = smem_u32(smem);
    const int tid = threadIdx.x;
    const int wid = tid >> 5, lane = tid & 31;
    const int row0 = blockIdx.y * 128;
    const int col0 = blockIdx.x * 128;
    const int wm = (wid & 1) * 64;
    const int wn = (wid >> 1) * 32;

    float acc[4][4][4];
#pragma unroll
    for (int a = 0; a < 4; a++)
#pragma unroll
        for (int b = 0; b < 4; b++)
#pragma unroll
            for (int c = 0; c < 4; c++) acc[a][b][c] = 0.0f;

    const int l_r[4] = { (tid + 0) >> 3, (tid + 256) >> 3, (tid + 512) >> 3, (tid + 768) >> 3 };
    const int l_c = tid & 7;

    const int a_r = lane & 15;
    const int a_c = lane >> 4;
    const int b_r = ((lane >> 4) << 3) + (lane & 7);
    const int b_c = (lane >> 3) & 1;

    auto load_tile = [&](int kt, int stage) {
        const int k0 = kt * 64;
        const uint32_t stb = sb + stage * SM_STAGE;
#pragma unroll
        for (int j = 0; j < 4; j++) {
            int r = l_r[j];
            uint32_t sw = sw_off(r, l_c);
            int apred = (row0 + r < M) ? 16 : 0;
            size_t aoff = (size_t)(row0 + r) * EMBED + k0 + l_c * 8;
            size_t boff = (size_t)(col0 + r) * EMBED + k0 + l_c * 8;
            cp16(stb + sw, Ahi + aoff, apred);
            if (TP) cp16(stb + OFF_ALO + sw, Alo + aoff, apred);
            cp16(stb + OFF_BHI + sw, Bhi + boff, 16);
        }
        CP_COMMIT();
    };

    load_tile(0, 0);

    for (int kt = 0; kt < 16; kt++) {
        const int stage = kt & 1;
        if (kt + 1 < 16) {
            load_tile(kt + 1, stage ^ 1);
            CP_WAIT(1);
        } else {
            CP_WAIT(0);
        }
        __syncthreads();

        const uint32_t stb = sb + stage * SM_STAGE;
#pragma unroll
        for (int ks = 0; ks < 4; ks++) {
            uint32_t ahi[4][4], alo[4][4];
#pragma unroll
            for (int mt = 0; mt < 4; mt++) {
                uint32_t sw = sw_off(wm + mt * 16 + a_r, ks * 2 + a_c);
                LDSM_X4(ahi[mt], stb + sw);
                if (TP) LDSM_X4(alo[mt], stb + OFF_ALO + sw);
            }
            uint32_t bhi[2][4];
#pragma unroll
            for (int np = 0; np < 2; np++) {
                uint32_t sw = sw_off(wn + np * 16 + b_r, ks * 2 + b_c);
                LDSM_X4(bhi[np], stb + OFF_BHI + sw);
            }
#pragma unroll
            for (int mt = 0; mt < 4; mt++) {
#pragma unroll
                for (int nt = 0; nt < 4; nt++) {
                    uint32_t bh0 = bhi[nt >> 1][(nt & 1) * 2];
                    uint32_t bh1 = bhi[nt >> 1][(nt & 1) * 2 + 1];
                    MMA_F16(acc[mt][nt], ahi[mt], bh0, bh1);
                    if (TP) MMA_F16(acc[mt][nt], alo[mt], bh0, bh1);
                }
            }
        }
        __syncthreads();
    }

    // Epilogue
    const int erow = lane >> 2;
    const int ecol = (lane & 3) * 2;
#pragma unroll
    for (int mt = 0; mt < 4; mt++) {
        int r0g = row0 + wm + mt * 16 + erow;
#pragma unroll
        for (int nt = 0; nt < 4; nt++) {
            int colg = col0 + wn + nt * 8 + ecol;
            float b0 = bias ? bias[colg] : 0.f;
            float b1 = bias ? bias[colg + 1] : 0.f;
            if (Ch) {
                if (r0g < M) {
                    __half2 v = __floats2half2_rn(acc[mt][nt][0] + b0, acc[mt][nt][1] + b1);
                    *(__half2*)&Ch[(size_t)r0g * EMBED + colg] = v;
                }
                if (r0g + 8 < M) {
                    __half2 v = __floats2half2_rn(acc[mt][nt][2] + b0, acc[mt][nt][3] + b1);
                    *(__half2*)&Ch[(size_t)(r0g + 8) * EMBED + colg] = v;
                }
            } else {
                if (r0g < M) {
                    float2 v = make_float2(acc[mt][nt][0] + b0, acc[mt][nt][1] + b1);
                    *(float2*)&C[(size_t)r0g * EMBED + colg] = v;
                }
                if (r0g + 8 < M) {
                    float2 v = make_float2(acc[mt][nt][2] + b0, acc[mt][nt][3] + b1);
                    *(float2*)&C[(size_t)(r0g + 8) * EMBED + colg] = v;
                }
            }
        }
    }
}

// Q projection: 2-pass (feeds exact hi/lo split into attention)
__global__ __launch_bounds__(256) void q_mma_kernel(const float* __restrict__ qb) {
    mma_gemm_body<true>(g_ahi, g_alo, g_whi[0], qb, g_q, nullptr, T_TOTAL);
}

// K,V projections: single-pass (outputs rounded to single fp16 anyway)
__global__ __launch_bounds__(256) void kv_mma_kernel(const float* __restrict__ vb) {
    int z = blockIdx.z;     // 0 -> k, 1 -> v
    if (z == 0)
        mma_gemm_body<false>(g_ahi, nullptr, g_whi[1], nullptr, g_k, nullptr, T_TOTAL);
    else
        mma_gemm_body<false>(g_ahi, nullptr, g_whi[2], vb, nullptr, g_vh, T_TOTAL);
}

// Output projection: 2-pass (directly gates final rel_err)
__global__ __launch_bounds__(256) void out_mma_kernel(const float* __restrict__ ob,
                                                      float* __restrict__ out) {
    mma_gemm_body<true>(g_chi, g_clo, g_whi[3], ob, out, nullptr, T_TOTAL);
}

// ------------------------- RoPE: fp32 in -> fp16 out (q scaled+split, k) ----
__global__ void rope_kernel(const float* __restrict__ cosp, const float* __restrict__ sinp) {
    int idx = blockIdx.x * blockDim.x + threadIdx.x;
    if (idx >= T_TOTAL * NHEADS * 32) return;
    int d = idx & 31;
    int h = (idx >> 5) & (NHEADS - 1);
    int t = idx >> 9;
    float c = cosp[t * HDIM + d];
    float s = sinp[t * HDIM + d];
    size_t base = (size_t)t * EMBED + h * HDIM + d;

    float q1 = g_q[base], q2 = g_q[base + 32];
    float q1r = (q1 * c - q2 * s) * 0.125f;
    float q2r = (q2 * c + q1 * s) * 0.125f;
    __half h1 = __float2half(q1r);
    __half h2 = __float2half(q2r);
    g_qhi[base]      = h1;
    g_qhi[base + 32] = h2;
    g_qlo[base]      = __float2half(q1r - __half2float(h1));
    g_qlo[base + 32] = __float2half(q2r - __half2float(h2));

    float k1 = g_k[base], k2 = g_k[base + 32];
    g_kh[base]      = __float2half(k1 * c - k2 * s);
    g_kh[base + 32] = __float2half(k2 * c + k1 * s);
}

// ------------------------- flash attention (fp16 MMA, 2-pass) ---------------
#define FSM_QHI 0
#define FSM_QLO 8192
#define FSM_KV  16384
#define FSM_TOTAL 49152

__global__ __launch_bounds__(128) void flash_kernel() {
    extern __shared__ char smem[];
    const uint32_t sb = smem_u32(smem);
    const int tid = threadIdx.x;
    const int wid = tid >> 5, lane = tid & 31;
    const int h = blockIdx.y;

    int rem = blockIdx.x, b = 0;
    while (rem >= c_nt[b]) { rem -= c_nt[b]; ++b; }
    const int qt = rem;
    const int tok0 = c_cu[b];
    const int tokq = tok0 + qt * 64;

    auto kvload = [&](int kt, int stage) {
        const int tokk = tok0 + kt * 64;
        const uint32_t kb = sb + FSM_KV + stage * 16384;
#pragma unroll
        for (int j = 0; j < 4; j++) {
            int idx = tid + j * 128;
            int r = idx >> 3;
            int c = idx & 7;
            uint32_t sw = sw_off(r, c);
            size_t go = (size_t)(tokk + r) * EMBED + h * HDIM + c * 8;
            cp16(kb + sw, g_kh + go, 16);
            cp16(kb + 8192 + sw, g_vh + go, 16);
        }
    };

#pragma unroll
    for (int j = 0; j < 4; j++) {
        int idx = tid + j * 128;
        int r = idx >> 3;
        int c = idx & 7;
        uint32_t sw = sw_off(r, c);
        size_t go = (size_t)(tokq + r) * EMBED + h * HDIM + c * 8;
        cp16(sb + FSM_QHI + sw, g_qhi + go, 16);
        cp16(sb + FSM_QLO + sw, g_qlo + go, 16);
    }
    kvload(0, 0);
    CP_COMMIT();
    CP_WAIT(0);
    __syncthreads();

    uint32_t qhi[4][4], qlo[4][4];
    {
        const int a_row = wid * 16 + (lane & 15);
        const int a_c = lane >> 4;
#pragma unroll
        for (int ks = 0; ks < 4; ks++) {
            uint32_t sw = sw_off(a_row, ks * 2 + a_c);
            LDSM_X4(qhi[ks], sb + FSM_QHI + sw);
            LDSM_X4(qlo[ks], sb + FSM_QLO + sw);
        }
    }

    float oacc[8][4];
#pragma unroll
    for (int n = 0; n < 8; n++)
#pragma unroll
        for (int c = 0; c < 4; c++) oacc[n][c] = 0.0f;
    float m0 = -1e30f, m1 = -1e30f, l0 = 0.0f, l1 = 0.0f;

    const int b_r = ((lane >> 4) << 3) + (lane & 7);
    const int b_c = (lane >> 3) & 1;
    const int v_row = ((lane >> 3) & 1) * 8 + (lane & 7);
    const int v_ch  = lane >> 4;

    for (int kt = 0; kt <= qt; kt++) {
        const int stage = kt & 1;
        if (kt < qt) {
            kvload(kt + 1, stage ^ 1);
            CP_COMMIT();
            CP_WAIT(1);
        } else {
            CP_WAIT(0);
        }
        __syncthreads();

        const uint32_t kbase = sb + FSM_KV + stage * 16384;
        const uint32_t vbase = kbase + 8192;

        float sacc[8][4];
#pragma unroll
        for (int n = 0; n < 8; n++)
#pragma unroll
            for (int c = 0; c < 4; c++) sacc[n][c] = 0.0f;

#pragma unroll
        for (int ks = 0; ks < 4; ks++) {
            uint32_t kf[4][4];
#pragma unroll
            for (int np = 0; np < 4; np++) {
                uint32_t sw = sw_off(np * 16 + b_r, ks * 2 + b_c);
                LDSM_X4(kf[np], kbase + sw);
            }
#pragma unroll
            for (int nt = 0; nt < 8; nt++) {
                uint32_t b0 = kf[nt >> 1][(nt & 1) * 2];
                uint32_t b1 = kf[nt >> 1][(nt & 1) * 2 + 1];
                MMA_F16(sacc[nt], qhi[ks], b0, b1);
                MMA_F16(sacc[nt], qlo[ks], b0, b1);
            }
        }

        if (kt == qt) {
            const int r0 = wid * 16 + (lane >> 2);
#pragma unroll
            for (int nt = 0; nt < 8; nt++) {
                int c0 = nt * 8 + (lane & 3) * 2;
                if (c0 > r0) sacc[nt][0] = -1e30f;
                if (c0 + 1 > r0) sacc[nt][1] = -1e30f;
                if (c0 > r0 + 8) sacc[nt][2] = -1e30f;
                if (c0 + 1 > r0 + 8) sacc[nt][3] = -1e30f;
            }
        }

        {
            float tm0 = -1e30f, tm1 = -1e30f;
#pragma unroll
            for (int nt = 0; nt < 8; nt++) {
                tm0 = fmaxf(tm0, fmaxf(sacc[nt][0], sacc[nt][1]));
                tm1 = fmaxf(tm1, fmaxf(sacc[nt][2], sacc[nt][3]));
            }
            tm0 = fmaxf(tm0, __shfl_xor_sync(0xffffffffu, tm0, 1, 32));
            tm0 = fmaxf(tm0, __shfl_xor_sync(0xffffffffu, tm0, 2, 32));
            tm1 = fmaxf(tm1, __shfl_xor_sync(0xffffffffu, tm1, 1, 32));
            tm1 = fmaxf(tm1, __shfl_xor_sync(0xffffffffu, tm1, 2, 32));
            float mn0 = fmaxf(m0, tm0), mn1 = fmaxf(m1, tm1);
            float al0 = __expf(m0 - mn0), al1 = __expf(m1 - mn1);
            float rs0 = 0.0f, rs1 = 0.0f;
#pragma unroll
            for (int nt = 0; nt < 8; nt++) {
                sacc[nt][0] = __expf(sacc[nt][0] - mn0); rs0 += sacc[nt][0];
                sacc[nt][1] = __expf(sacc[nt][1] - mn0); rs0 += sacc[nt][1];
                sacc[nt][2] = __expf(sacc[nt][2] - mn1); rs1 += sacc[nt][2];
                sacc[nt][3] = __expf(sacc[nt][3] - mn1); rs1 += sacc[nt][3];
            }
            rs0 += __shfl_xor_sync(0xffffffffu, rs0, 1, 32);
            rs0 += __shfl_xor_sync(0xffffffffu, rs0, 2, 32);
            rs1 += __shfl_xor_sync(0xffffffffu, rs1, 1, 32);
            rs1 += __shfl_xor_sync(0xffffffffu, rs1, 2, 32);
            l0 = l0 * al0 + rs0; m0 = mn0;
            l1 = l1 * al1 + rs1; m1 = mn1;
#pragma unroll
            for (int n = 0; n < 8; n++) {
                oacc[n][0] *= al0; oacc[n][1] *= al0;
                oacc[n][2] *= al1; oacc[n][3] *= al1;
            }
        }

#pragma unroll
        for (int ks = 0; ks < 4; ks++) {
            uint32_t ph[4], pl[4];
            {
                float* s0 = sacc[2 * ks];
                float* s1 = sacc[2 * ks + 1];
                __half h00 = __float2half(s0[0]), h01 = __float2half(s0[1]);
                __half h02 = __float2half(s0[2]), h03 = __float2half(s0[3]);
                __half h10 = __float2half(s1[0]), h11 = __float2half(s1[1]);
                __half h12 = __float2half(s1[2]), h13 = __float2half(s1[3]);
                ph[0] = pack_h2(h00, h01);
                ph[1] = pack_h2(h02, h03);
                ph[2] = pack_h2(h10, h11);
                ph[3] = pack_h2(h12, h13);
                pl[0] = pack_h2(__float2half(s0[0] - __half2float(h00)),
                                __float2half(s0[1] - __half2float(h01)));
                pl[1] = pack_h2(__float2half(s0[2] - __half2float(h02)),
                                __float2half(s0[3] - __half2float(h03)));
                pl[2] = pack_h2(__float2half(s1[0] - __half2float(h10)),
                                __float2half(s1[1] - __half2float(h11)));
                pl[3] = pack_h2(__float2half(s1[2] - __half2float(h12)),
                                __float2half(s1[3] - __half2float(h13)));
            }
#pragma unroll
            for (int nd2 = 0; nd2 < 4; nd2++) {
                uint32_t vf[4];
                uint32_t sw = sw_off(ks * 16 + v_row, nd2 * 2 + v_ch);
                LDSM_X4_T(vf, vbase + sw);
                MMA_F16(oacc[nd2 * 2],     ph, vf[0], vf[1]);
                MMA_F16(oacc[nd2 * 2],     pl, vf[0], vf[1]);
                MMA_F16(oacc[nd2 * 2 + 1], ph, vf[2], vf[3]);
                MMA_F16(oacc[nd2 * 2 + 1], pl, vf[2], vf[3]);
            }
        }
        __syncthreads();
    }

    {
        float inv0 = 1.0f / l0;
        float inv1 = 1.0f / l1;
        int gr0 = tokq + wid * 16 + (lane >> 2);
        int gr1 = gr0 + 8;
#pragma unroll
        for (int nt = 0; nt < 8; nt++) {
            int col = h * HDIM + nt * 8 + (lane & 3) * 2;
            {
                float v0 = oacc[nt][0] * inv0, v1 = oacc[nt][1] * inv0;
                __half h0 = __float2half(v0), h1 = __float2half(v1);
                *(__half2*)&g_chi[(size_t)gr0 * EMBED + col] = __halves2half2(h0, h1);
                *(__half2*)&g_clo[(size_t)gr0 * EMBED + col] =
                    __halves2half2(__float2half(v0 - __half2float(h0)),
                                   __float2half(v1 - __half2float(h1)));
            }
            {
                float v0 = oacc[nt][2] * inv1, v1 = oacc[nt][3] * inv1;
                __half h0 = __float2half(v0), h1 = __float2half(v1);
                *(__half2*)&g_chi[(size_t)gr1 * EMBED + col] = __halves2half2(h0, h1);
                *(__half2*)&g_clo[(size_t)gr1 * EMBED + col] =
                    __halves2half2(__float2half(v0 - __half2float(h0)),
                                   __float2half(v1 - __half2float(h1)));
            }
        }
    }
}

// ---------------------------------------------------------------------------
extern "C" void kernel_launch(void* const* d_in, const int* in_sizes, int n_in,
                              void* d_out, int out_size)
{
    const float* hidden = (const float*)d_in[0];
    const float* cosp   = (const float*)d_in[1];
    const float* sinp   = (const float*)d_in[2];
    const float* q_w    = (const float*)d_in[3];
    const float* q_b    = (const float*)d_in[4];
    const float* k_w    = (const float*)d_in[5];
    const float* v_w    = (const float*)d_in[6];
    const float* v_b    = (const float*)d_in[7];
    const float* out_w  = (const float*)d_in[8];
    const float* out_b  = (const float*)d_in[9];
    float* out = (float*)d_out;

    __half *pahi, *palo;
    cudaGetSymbolAddress((void**)&pahi, g_ahi);
    cudaGetSymbolAddress((void**)&palo, g_alo);

    // 1. Split hidden -> fp16 hi/lo
    {
        int n4 = T_TOTAL * EMBED / 4;
        split_kernel<<<(n4 + 255) / 256, 256>>>(hidden, pahi, palo, n4);
    }
    // 2. Convert weights -> fp16 (z = q,k,v,out)
    {
        int n4 = EMBED * EMBED / 4;
        dim3 g((n4 + 255) / 256, 1, 4);
        split_w_kernel<<<g, 256>>>(q_w, k_w, v_w, out_w);
    }
    // 3. Q GEMM (2-pass) + K/V GEMMs (1-pass)
    cudaFuncSetAttribute(q_mma_kernel,  cudaFuncAttributeMaxDynamicSharedMemorySize, SM_TOTAL_2P);
    cudaFuncSetAttribute(kv_mma_kernel, cudaFuncAttributeMaxDynamicSharedMemorySize, SM_TOTAL_1P);
    q_mma_kernel<<<dim3(EMBED / 128, MTILES, 1), 256, SM_TOTAL_2P>>>(q_b);
    kv_mma_kernel<<<dim3(EMBED / 128, MTILES, 2), 256, SM_TOTAL_1P>>>(v_b);

    // 4. RoPE (fp32 -> fp16 q hi/lo scaled, k)
    int nrope = T_TOTAL * NHEADS * 32;
    rope_kernel<<<(nrope + 255) / 256, 256>>>(cosp, sinp);

    // 5. Flash attention (fp16 MMA, writes g_chi/g_clo)
    cudaFuncSetAttribute(flash_kernel, cudaFuncAttributeMaxDynamicSharedMemorySize, FSM_TOTAL);
    flash_kernel<<<dim3(153, NHEADS), 128, FSM_TOTAL>>>();

    // 6. Output GEMM (2-pass)
    cudaFuncSetAttribute(out_mma_kernel, cudaFuncAttributeMaxDynamicSharedMemorySize, SM_TOTAL_2P);
    out_mma_kernel<<<dim3(EMBED / 128, MTILES, 1), 256, SM_TOTAL_2P>>>(out_b, out);
}

// round 10
// speedup vs baseline: 5.3632x; 1.0345x over previous
#include <cuda_runtime.h>
#include <cuda_fp16.h>
#include <cstdint>

#define T_TOTAL 9792
#define EMBED   1024
#define NHEADS  16
#define HDIM    64
#define MTILES  77          // ceil(9792/128)

// ------------------------- scratch (static device) -------------------------
__device__ float g_q[(size_t)T_TOTAL * EMBED];   // fp32 q before rope
__device__ float g_k[(size_t)T_TOTAL * EMBED];   // fp32 k before rope

__device__ __half g_ahi[(size_t)T_TOTAL * EMBED];
__device__ __half g_alo[(size_t)T_TOTAL * EMBED];
__device__ __half g_chi[(size_t)T_TOTAL * EMBED];
__device__ __half g_clo[(size_t)T_TOTAL * EMBED];
__device__ __half g_whi[4][(size_t)EMBED * EMBED];

__device__ __half g_qhi[(size_t)T_TOTAL * EMBED];  // rope'd q * 0.125, hi
__device__ __half g_qlo[(size_t)T_TOTAL * EMBED];  // rope'd q * 0.125, lo
__device__ __half g_kh [(size_t)T_TOTAL * EMBED];  // rope'd k, fp16
__device__ __half g_vh [(size_t)T_TOTAL * EMBED];  // v, fp16 (GEMM epilogue)

__constant__ int c_cu[12] = {0, 1024, 1792, 2688, 3200, 4224, 4864, 5888, 6656, 7168, 8064, 9088};
__constant__ int c_nt[12] = {16, 12, 14, 8, 16, 10, 16, 12, 8, 14, 16, 11};

// ------------------------- PTX helpers (baseline ISA only) ------------------
__device__ __forceinline__ uint32_t smem_u32(const void* p) {
    uint32_t a;
    asm("{ .reg .u64 t; cvta.to.shared.u64 t, %1; cvt.u32.u64 %0, t; }" : "=r"(a) : "l"(p));
    return a;
}

#define LDSM_X4(R, addr)                                                      \
    asm volatile("ldmatrix.sync.aligned.m8n8.x4.shared.b16 {%0,%1,%2,%3}, [%4];" \
        : "=r"((R)[0]), "=r"((R)[1]), "=r"((R)[2]), "=r"((R)[3]) : "r"(addr))

#define LDSM_X4_T(R, addr)                                                    \
    asm volatile("ldmatrix.sync.aligned.m8n8.x4.trans.shared.b16 {%0,%1,%2,%3}, [%4];" \
        : "=r"((R)[0]), "=r"((R)[1]), "=r"((R)[2]), "=r"((R)[3]) : "r"(addr))

#define MMA_F16(C, A, B0, B1)                                                 \
    asm volatile("mma.sync.aligned.m16n8k16.row.col.f32.f16.f16.f32 "         \
        "{%0,%1,%2,%3}, {%4,%5,%6,%7}, {%8,%9}, {%0,%1,%2,%3};"               \
        : "+f"((C)[0]), "+f"((C)[1]), "+f"((C)[2]), "+f"((C)[3])              \
        : "r"((A)[0]), "r"((A)[1]), "r"((A)[2]), "r"((A)[3]), "r"(B0), "r"(B1))

__device__ __forceinline__ void cp16(uint32_t dst, const void* src, int srcbytes) {
    asm volatile("cp.async.cg.shared.global [%0], [%1], 16, %2;"
                 :: "r"(dst), "l"(src), "r"(srcbytes) : "memory");
}
#define CP_COMMIT() asm volatile("cp.async.commit_group;" ::: "memory")
#define CP_WAIT(N)  asm volatile("cp.async.wait_group %0;" :: "n"(N) : "memory")

__device__ __forceinline__ uint32_t pack_h2(__half a, __half b) {
    __half2 t = __halves2half2(a, b);
    return *(uint32_t*)&t;
}

// ------------------------- fp32 -> fp16 hi/lo split -------------------------
__global__ void split_kernel(const float* __restrict__ src, __half* __restrict__ hi,
                             __half* __restrict__ lo, int n4) {
    int i = blockIdx.x * blockDim.x + threadIdx.x;
    if (i >= n4) return;
    float4 v = ((const float4*)src)[i];
    union { __half b[4]; uint2 u; } H, L;
    float x[4] = {v.x, v.y, v.z, v.w};
#pragma unroll
    for (int j = 0; j < 4; j++) {
        __half h = __float2half(x[j]);
        H.b[j] = h;
        L.b[j] = __float2half(x[j] - __half2float(h));
    }
    ((uint2*)hi)[i] = H.u;
    ((uint2*)lo)[i] = L.u;
}

__global__ void split_w_kernel(const float* __restrict__ w0, const float* __restrict__ w1,
                               const float* __restrict__ w2, const float* __restrict__ w3) {
    int z = blockIdx.z;
    const float* src = (z == 0) ? w0 : (z == 1) ? w1 : (z == 2) ? w2 : w3;
    int i = blockIdx.x * blockDim.x + threadIdx.x;
    int n4 = EMBED * EMBED / 4;
    if (i >= n4) return;
    float4 v = ((const float4*)src)[i];
    union { __half b[4]; uint2 u; } H;
    H.b[0] = __float2half(v.x);
    H.b[1] = __float2half(v.y);
    H.b[2] = __float2half(v.z);
    H.b[3] = __float2half(v.w);
    ((uint2*)g_whi[z])[i] = H.u;
}

// ------------------------- warp-MMA GEMM: C[M,1024] = A @ W^T (+bias) -------
// 3-stage cp.async pipeline, ONE __syncthreads per k-tile.
// TP: D = Ahi*Bhi + Alo*Bhi (A split). !TP: D = Ahi*Bhi.
#define SM_TOTAL_2P 147456   // 3 stages x (Ahi 16K + Alo 16K + Bhi 16K)
#define SM_TOTAL_1P 98304    // 3 stages x (Ahi 16K + Bhi 16K)

__device__ __forceinline__ uint32_t sw_off(int r, int chunk) {
    uint32_t off = (uint32_t)(r * 128 + chunk * 16);
    return off ^ ((off >> 3) & 0x70);
}

template<bool TP>
__device__ __forceinline__ void mma_gemm_body(
    const __half* __restrict__ Ahi, const __half* __restrict__ Alo,
    const __half* __restrict__ Bhi,
    const float* __restrict__ bias, float* __restrict__ C,
    __half* __restrict__ Ch, int M)
{
    constexpr uint32_t OFF_ALO  = 16384;
    constexpr uint32_t OFF_BHI  = TP ? 32768 : 16384;
    constexpr uint32_t SM_STAGE = TP ? 49152 : 32768;

    extern __shared__ char smem[];
    const uint32_t sb = smem_u32(smem);
    const int tid = threadIdx.x;
    const int wid = tid >> 5, lane = tid & 31;
    const int row0 = blockIdx.y * 128;
    const int col0 = blockIdx.x * 128;
    const int wm = (wid & 1) * 64;
    const int wn = (wid >> 1) * 32;

    float acc[4][4][4];
#pragma unroll
    for (int a = 0; a < 4; a++)
#pragma unroll
        for (int b = 0; b < 4; b++)
#pragma unroll
            for (int c = 0; c < 4; c++) acc[a][b][c] = 0.0f;

    const int l_r[4] = { (tid + 0) >> 3, (tid + 256) >> 3, (tid + 512) >> 3, (tid + 768) >> 3 };
    const int l_c = tid & 7;

    const int a_r = lane & 15;
    const int a_c = lane >> 4;
    const int b_r = ((lane >> 4) << 3) + (lane & 7);
    const int b_c = (lane >> 3) & 1;

    auto load_tile = [&](int kt, int stage) {
        const int k0 = kt * 64;
        const uint32_t stb = sb + stage * SM_STAGE;
#pragma unroll
        for (int j = 0; j < 4; j++) {
            int r = l_r[j];
            uint32_t sw = sw_off(r, l_c);
            int apred = (row0 + r < M) ? 16 : 0;
            size_t aoff = (size_t)(row0 + r) * EMBED + k0 + l_c * 8;
            size_t boff = (size_t)(col0 + r) * EMBED + k0 + l_c * 8;
            cp16(stb + sw, Ahi + aoff, apred);
            if (TP) cp16(stb + OFF_ALO + sw, Alo + aoff, apred);
            cp16(stb + OFF_BHI + sw, Bhi + boff, 16);
        }
        CP_COMMIT();
    };

    load_tile(0, 0);
    load_tile(1, 1);

    for (int kt = 0; kt < 16; kt++) {
        CP_WAIT(1);             // tile kt complete (2 newest groups may be pending)
        __syncthreads();        // visibility + all warps done with tile kt-1's slot
        if (kt + 2 < 16) load_tile(kt + 2, (kt + 2) % 3);
        else CP_COMMIT();       // dummy group keeps wait-count invariant

        const uint32_t stb = sb + (kt % 3) * SM_STAGE;
#pragma unroll
        for (int ks = 0; ks < 4; ks++) {
            uint32_t ahi[4][4], alo[4][4];
#pragma unroll
            for (int mt = 0; mt < 4; mt++) {
                uint32_t sw = sw_off(wm + mt * 16 + a_r, ks * 2 + a_c);
                LDSM_X4(ahi[mt], stb + sw);
                if (TP) LDSM_X4(alo[mt], stb + OFF_ALO + sw);
            }
            uint32_t bhi[2][4];
#pragma unroll
            for (int np = 0; np < 2; np++) {
                uint32_t sw = sw_off(wn + np * 16 + b_r, ks * 2 + b_c);
                LDSM_X4(bhi[np], stb + OFF_BHI + sw);
            }
#pragma unroll
            for (int mt = 0; mt < 4; mt++) {
#pragma unroll
                for (int nt = 0; nt < 4; nt++) {
                    uint32_t bh0 = bhi[nt >> 1][(nt & 1) * 2];
                    uint32_t bh1 = bhi[nt >> 1][(nt & 1) * 2 + 1];
                    MMA_F16(acc[mt][nt], ahi[mt], bh0, bh1);
                    if (TP) MMA_F16(acc[mt][nt], alo[mt], bh0, bh1);
                }
            }
        }
    }

    // Epilogue
    const int erow = lane >> 2;
    const int ecol = (lane & 3) * 2;
#pragma unroll
    for (int mt = 0; mt < 4; mt++) {
        int r0g = row0 + wm + mt * 16 + erow;
#pragma unroll
        for (int nt = 0; nt < 4; nt++) {
            int colg = col0 + wn + nt * 8 + ecol;
            float b0 = bias ? bias[colg] : 0.f;
            float b1 = bias ? bias[colg + 1] : 0.f;
            if (Ch) {
                if (r0g < M) {
                    __half2 v = __floats2half2_rn(acc[mt][nt][0] + b0, acc[mt][nt][1] + b1);
                    *(__half2*)&Ch[(size_t)r0g * EMBED + colg] = v;
                }
                if (r0g + 8 < M) {
                    __half2 v = __floats2half2_rn(acc[mt][nt][2] + b0, acc[mt][nt][3] + b1);
                    *(__half2*)&Ch[(size_t)(r0g + 8) * EMBED + colg] = v;
                }
            } else {
                if (r0g < M) {
                    float2 v = make_float2(acc[mt][nt][0] + b0, acc[mt][nt][1] + b1);
                    *(float2*)&C[(size_t)r0g * EMBED + colg] = v;
                }
                if (r0g + 8 < M) {
                    float2 v = make_float2(acc[mt][nt][2] + b0, acc[mt][nt][3] + b1);
                    *(float2*)&C[(size_t)(r0g + 8) * EMBED + colg] = v;
                }
            }
        }
    }
}

// Q projection: 2-pass (feeds exact hi/lo split into attention)
__global__ __launch_bounds__(256) void q_mma_kernel(const float* __restrict__ qb) {
    mma_gemm_body<true>(g_ahi, g_alo, g_whi[0], qb, g_q, nullptr, T_TOTAL);
}

// K,V projections: single-pass; cap regs at 128 for 2 CTAs/SM
__global__ __launch_bounds__(256, 2) void kv_mma_kernel(const float* __restrict__ vb) {
    int z = blockIdx.z;     // 0 -> k, 1 -> v
    if (z == 0)
        mma_gemm_body<false>(g_ahi, nullptr, g_whi[1], nullptr, g_k, nullptr, T_TOTAL);
    else
        mma_gemm_body<false>(g_ahi, nullptr, g_whi[2], vb, nullptr, g_vh, T_TOTAL);
}

// Output projection: 2-pass (directly gates final rel_err)
__global__ __launch_bounds__(256) void out_mma_kernel(const float* __restrict__ ob,
                                                      float* __restrict__ out) {
    mma_gemm_body<true>(g_chi, g_clo, g_whi[3], ob, out, nullptr, T_TOTAL);
}

// ------------------------- RoPE: fp32 in -> fp16 out (q scaled+split, k) ----
__global__ void rope_kernel(const float* __restrict__ cosp, const float* __restrict__ sinp) {
    int idx = blockIdx.x * blockDim.x + threadIdx.x;
    if (idx >= T_TOTAL * NHEADS * 32) return;
    int d = idx & 31;
    int h = (idx >> 5) & (NHEADS - 1);
    int t = idx >> 9;
    float c = cosp[t * HDIM + d];
    float s = sinp[t * HDIM + d];
    size_t base = (size_t)t * EMBED + h * HDIM + d;

    float q1 = g_q[base], q2 = g_q[base + 32];
    float q1r = (q1 * c - q2 * s) * 0.125f;
    float q2r = (q2 * c + q1 * s) * 0.125f;
    __half h1 = __float2half(q1r);
    __half h2 = __float2half(q2r);
    g_qhi[base]      = h1;
    g_qhi[base + 32] = h2;
    g_qlo[base]      = __float2half(q1r - __half2float(h1));
    g_qlo[base + 32] = __float2half(q2r - __half2float(h2));

    float k1 = g_k[base], k2 = g_k[base + 32];
    g_kh[base]      = __float2half(k1 * c - k2 * s);
    g_kh[base + 32] = __float2half(k2 * c + k1 * s);
}

// ------------------------- flash attention (fp16 MMA, 3-stage KV) -----------
// smem: Qhi 8K | Qlo 8K | 3 KV stages x 16K = 64KB total
#define FSM_QHI 0
#define FSM_QLO 8192
#define FSM_KV  16384
#define FSM_TOTAL 65536

__global__ __launch_bounds__(128) void flash_kernel() {
    extern __shared__ char smem[];
    const uint32_t sb = smem_u32(smem);
    const int tid = threadIdx.x;
    const int wid = tid >> 5, lane = tid & 31;
    const int h = blockIdx.y;

    int rem = blockIdx.x, b = 0;
    while (rem >= c_nt[b]) { rem -= c_nt[b]; ++b; }
    const int qt = rem;
    const int tok0 = c_cu[b];
    const int tokq = tok0 + qt * 64;

    auto kvload = [&](int kt, int slot) {
        const int tokk = tok0 + kt * 64;
        const uint32_t kb = sb + FSM_KV + slot * 16384;
#pragma unroll
        for (int j = 0; j < 4; j++) {
            int idx = tid + j * 128;
            int r = idx >> 3;
            int c = idx & 7;
            uint32_t sw = sw_off(r, c);
            size_t go = (size_t)(tokk + r) * EMBED + h * HDIM + c * 8;
            cp16(kb + sw, g_kh + go, 16);
            cp16(kb + 8192 + sw, g_vh + go, 16);
        }
    };

    // prologue: group0 = Q + kv0, group1 = kv1 (or dummy)
#pragma unroll
    for (int j = 0; j < 4; j++) {
        int idx = tid + j * 128;
        int r = idx >> 3;
        int c = idx & 7;
        uint32_t sw = sw_off(r, c);
        size_t go = (size_t)(tokq + r) * EMBED + h * HDIM + c * 8;
        cp16(sb + FSM_QHI + sw, g_qhi + go, 16);
        cp16(sb + FSM_QLO + sw, g_qlo + go, 16);
    }
    kvload(0, 0);
    CP_COMMIT();
    if (qt >= 1) kvload(1, 1);
    CP_COMMIT();

    CP_WAIT(1);          // group0 (Q + kv0) complete
    __syncthreads();

    uint32_t qhi[4][4], qlo[4][4];
    {
        const int a_row = wid * 16 + (lane & 15);
        const int a_c = lane >> 4;
#pragma unroll
        for (int ks = 0; ks < 4; ks++) {
            uint32_t sw = sw_off(a_row, ks * 2 + a_c);
            LDSM_X4(qhi[ks], sb + FSM_QHI + sw);
            LDSM_X4(qlo[ks], sb + FSM_QLO + sw);
        }
    }

    float oacc[8][4];
#pragma unroll
    for (int n = 0; n < 8; n++)
#pragma unroll
        for (int c = 0; c < 4; c++) oacc[n][c] = 0.0f;
    float m0 = -1e30f, m1 = -1e30f, l0 = 0.0f, l1 = 0.0f;

    const int b_r = ((lane >> 4) << 3) + (lane & 7);
    const int b_c = (lane >> 3) & 1;
    const int v_row = ((lane >> 3) & 1) * 8 + (lane & 7);
    const int v_ch  = lane >> 4;

    for (int kt = 0; kt <= qt; kt++) {
        CP_WAIT(1);           // kv(kt) complete
        __syncthreads();      // visibility + done consuming slot being refilled
        if (kt + 2 <= qt) kvload(kt + 2, (kt + 2) % 3);
        CP_COMMIT();

        const uint32_t kbase = sb + FSM_KV + (kt % 3) * 16384;
        const uint32_t vbase = kbase + 8192;

        float sacc[8][4];
#pragma unroll
        for (int n = 0; n < 8; n++)
#pragma unroll
            for (int c = 0; c < 4; c++) sacc[n][c] = 0.0f;

#pragma unroll
        for (int ks = 0; ks < 4; ks++) {
            uint32_t kf[4][4];
#pragma unroll
            for (int np = 0; np < 4; np++) {
                uint32_t sw = sw_off(np * 16 + b_r, ks * 2 + b_c);
                LDSM_X4(kf[np], kbase + sw);
            }
#pragma unroll
            for (int nt = 0; nt < 8; nt++) {
                uint32_t b0 = kf[nt >> 1][(nt & 1) * 2];
                uint32_t b1 = kf[nt >> 1][(nt & 1) * 2 + 1];
                MMA_F16(sacc[nt], qhi[ks], b0, b1);
                MMA_F16(sacc[nt], qlo[ks], b0, b1);
            }
        }

        if (kt == qt) {
            const int r0 = wid * 16 + (lane >> 2);
#pragma unroll
            for (int nt = 0; nt < 8; nt++) {
                int c0 = nt * 8 + (lane & 3) * 2;
                if (c0 > r0) sacc[nt][0] = -1e30f;
                if (c0 + 1 > r0) sacc[nt][1] = -1e30f;
                if (c0 > r0 + 8) sacc[nt][2] = -1e30f;
                if (c0 + 1 > r0 + 8) sacc[nt][3] = -1e30f;
            }
        }

        {
            float tm0 = -1e30f, tm1 = -1e30f;
#pragma unroll
            for (int nt = 0; nt < 8; nt++) {
                tm0 = fmaxf(tm0, fmaxf(sacc[nt][0], sacc[nt][1]));
                tm1 = fmaxf(tm1, fmaxf(sacc[nt][2], sacc[nt][3]));
            }
            tm0 = fmaxf(tm0, __shfl_xor_sync(0xffffffffu, tm0, 1, 32));
            tm0 = fmaxf(tm0, __shfl_xor_sync(0xffffffffu, tm0, 2, 32));
            tm1 = fmaxf(tm1, __shfl_xor_sync(0xffffffffu, tm1, 1, 32));
            tm1 = fmaxf(tm1, __shfl_xor_sync(0xffffffffu, tm1, 2, 32));
            float mn0 = fmaxf(m0, tm0), mn1 = fmaxf(m1, tm1);
            float al0 = __expf(m0 - mn0), al1 = __expf(m1 - mn1);
            float rs0 = 0.0f, rs1 = 0.0f;
#pragma unroll
            for (int nt = 0; nt < 8; nt++) {
                sacc[nt][0] = __expf(sacc[nt][0] - mn0); rs0 += sacc[nt][0];
                sacc[nt][1] = __expf(sacc[nt][1] - mn0); rs0 += sacc[nt][1];
                sacc[nt][2] = __expf(sacc[nt][2] - mn1); rs1 += sacc[nt][2];
                sacc[nt][3] = __expf(sacc[nt][3] - mn1); rs1 += sacc[nt][3];
            }
            rs0 += __shfl_xor_sync(0xffffffffu, rs0, 1, 32);
            rs0 += __shfl_xor_sync(0xffffffffu, rs0, 2, 32);
            rs1 += __shfl_xor_sync(0xffffffffu, rs1, 1, 32);
            rs1 += __shfl_xor_sync(0xffffffffu, rs1, 2, 32);
            l0 = l0 * al0 + rs0; m0 = mn0;
            l1 = l1 * al1 + rs1; m1 = mn1;
#pragma unroll
            for (int n = 0; n < 8; n++) {
                oacc[n][0] *= al0; oacc[n][1] *= al0;
                oacc[n][2] *= al1; oacc[n][3] *= al1;
            }
        }

#pragma unroll
        for (int ks = 0; ks < 4; ks++) {
            uint32_t ph[4], pl[4];
            {
                float* s0 = sacc[2 * ks];
                float* s1 = sacc[2 * ks + 1];
                __half h00 = __float2half(s0[0]), h01 = __float2half(s0[1]);
                __half h02 = __float2half(s0[2]), h03 = __float2half(s0[3]);
                __half h10 = __float2half(s1[0]), h11 = __float2half(s1[1]);
                __half h12 = __float2half(s1[2]), h13 = __float2half(s1[3]);
                ph[0] = pack_h2(h00, h01);
                ph[1] = pack_h2(h02, h03);
                ph[2] = pack_h2(h10, h11);
                ph[3] = pack_h2(h12, h13);
                pl[0] = pack_h2(__float2half(s0[0] - __half2float(h00)),
                                __float2half(s0[1] - __half2float(h01)));
                pl[1] = pack_h2(__float2half(s0[2] - __half2float(h02)),
                                __float2half(s0[3] - __half2float(h03)));
                pl[2] = pack_h2(__float2half(s1[0] - __half2float(h10)),
                                __float2half(s1[1] - __half2float(h11)));
                pl[3] = pack_h2(__float2half(s1[2] - __half2float(h12)),
                                __float2half(s1[3] - __half2float(h13)));
            }
#pragma unroll
            for (int nd2 = 0; nd2 < 4; nd2++) {
                uint32_t vf[4];
                uint32_t sw = sw_off(ks * 16 + v_row, nd2 * 2 + v_ch);
                LDSM_X4_T(vf, vbase + sw);
                MMA_F16(oacc[nd2 * 2],     ph, vf[0], vf[1]);
                MMA_F16(oacc[nd2 * 2],     pl, vf[0], vf[1]);
                MMA_F16(oacc[nd2 * 2 + 1], ph, vf[2], vf[3]);
                MMA_F16(oacc[nd2 * 2 + 1], pl, vf[2], vf[3]);
            }
        }
    }

    {
        float inv0 = 1.0f / l0;
        float inv1 = 1.0f / l1;
        int gr0 = tokq + wid * 16 + (lane >> 2);
        int gr1 = gr0 + 8;
#pragma unroll
        for (int nt = 0; nt < 8; nt++) {
            int col = h * HDIM + nt * 8 + (lane & 3) * 2;
            {
                float v0 = oacc[nt][0] * inv0, v1 = oacc[nt][1] * inv0;
                __half h0 = __float2half(v0), h1 = __float2half(v1);
                *(__half2*)&g_chi[(size_t)gr0 * EMBED + col] = __halves2half2(h0, h1);
                *(__half2*)&g_clo[(size_t)gr0 * EMBED + col] =
                    __halves2half2(__float2half(v0 - __half2float(h0)),
                                   __float2half(v1 - __half2float(h1)));
            }
            {
                float v0 = oacc[nt][2] * inv1, v1 = oacc[nt][3] * inv1;
                __half h0 = __float2half(v0), h1 = __float2half(v1);
                *(__half2*)&g_chi[(size_t)gr1 * EMBED + col] = __halves2half2(h0, h1);
                *(__half2*)&g_clo[(size_t)gr1 * EMBED + col] =
                    __halves2half2(__float2half(v0 - __half2float(h0)),
                                   __float2half(v1 - __half2float(h1)));
            }
        }
    }
}

// ---------------------------------------------------------------------------
extern "C" void kernel_launch(void* const* d_in, const int* in_sizes, int n_in,
                              void* d_out, int out_size)
{
    const float* hidden = (const float*)d_in[0];
    const float* cosp   = (const float*)d_in[1];
    const float* sinp   = (const float*)d_in[2];
    const float* q_w    = (const float*)d_in[3];
    const float* q_b    = (const float*)d_in[4];
    const float* k_w    = (const float*)d_in[5];
    const float* v_w    = (const float*)d_in[6];
    const float* v_b    = (const float*)d_in[7];
    const float* out_w  = (const float*)d_in[8];
    const float* out_b  = (const float*)d_in[9];
    float* out = (float*)d_out;

    __half *pahi, *palo;
    cudaGetSymbolAddress((void**)&pahi, g_ahi);
    cudaGetSymbolAddress((void**)&palo, g_alo);

    // 1. Split hidden -> fp16 hi/lo
    {
        int n4 = T_TOTAL * EMBED / 4;
        split_kernel<<<(n4 + 255) / 256, 256>>>(hidden, pahi, palo, n4);
    }
    // 2. Convert weights -> fp16 (z = q,k,v,out)
    {
        int n4 = EMBED * EMBED / 4;
        dim3 g((n4 + 255) / 256, 1, 4);
        split_w_kernel<<<g, 256>>>(q_w, k_w, v_w, out_w);
    }
    // 3. Q GEMM (2-pass) + K/V GEMMs (1-pass, 2 CTAs/SM)
    cudaFuncSetAttribute(q_mma_kernel,  cudaFuncAttributeMaxDynamicSharedMemorySize, SM_TOTAL_2P);
    cudaFuncSetAttribute(kv_mma_kernel, cudaFuncAttributeMaxDynamicSharedMemorySize, SM_TOTAL_1P);
    q_mma_kernel<<<dim3(EMBED / 128, MTILES, 1), 256, SM_TOTAL_2P>>>(q_b);
    kv_mma_kernel<<<dim3(EMBED / 128, MTILES, 2), 256, SM_TOTAL_1P>>>(v_b);

    // 4. RoPE (fp32 -> fp16 q hi/lo scaled, k)
    int nrope = T_TOTAL * NHEADS * 32;
    rope_kernel<<<(nrope + 255) / 256, 256>>>(cosp, sinp);

    // 5. Flash attention (fp16 MMA, writes g_chi/g_clo)
    cudaFuncSetAttribute(flash_kernel, cudaFuncAttributeMaxDynamicSharedMemorySize, FSM_TOTAL);
    flash_kernel<<<dim3(153, NHEADS), 128, FSM_TOTAL>>>();

    // 6. Output GEMM (2-pass)
    cudaFuncSetAttribute(out_mma_kernel, cudaFuncAttributeMaxDynamicSharedMemorySize, SM_TOTAL_2P);
    out_mma_kernel<<<dim3(EMBED / 128, MTILES, 1), 256, SM_TOTAL_2P>>>(out_b, out);
}

// round 11
// speedup vs baseline: 6.0205x; 1.1226x over previous
#include <cuda_runtime.h>
#include <cuda_fp16.h>
#include <cstdint>

#define T_TOTAL 9792
#define EMBED   1024
#define NHEADS  16
#define HDIM    64
#define MTILES  77          // ceil(9792/128)

// ------------------------- scratch (static device) -------------------------
__device__ __half g_ahi[(size_t)T_TOTAL * EMBED];
__device__ __half g_alo[(size_t)T_TOTAL * EMBED];
__device__ __half g_chi[(size_t)T_TOTAL * EMBED];
__device__ __half g_clo[(size_t)T_TOTAL * EMBED];
__device__ __half g_whi[4][(size_t)EMBED * EMBED];

__device__ __half g_qhi[(size_t)T_TOTAL * EMBED];  // rope'd q * 0.125, hi
__device__ __half g_qlo[(size_t)T_TOTAL * EMBED];  // rope'd q * 0.125, lo
__device__ __half g_kh [(size_t)T_TOTAL * EMBED];  // rope'd k, fp16
__device__ __half g_vh [(size_t)T_TOTAL * EMBED];  // v, fp16

__constant__ int c_cu[12] = {0, 1024, 1792, 2688, 3200, 4224, 4864, 5888, 6656, 7168, 8064, 9088};
__constant__ int c_nt[12] = {16, 12, 14, 8, 16, 10, 16, 12, 8, 14, 16, 11};

// ------------------------- PTX helpers (baseline ISA only) ------------------
__device__ __forceinline__ uint32_t smem_u32(const void* p) {
    uint32_t a;
    asm("{ .reg .u64 t; cvta.to.shared.u64 t, %1; cvt.u32.u64 %0, t; }" : "=r"(a) : "l"(p));
    return a;
}

#define LDSM_X4(R, addr)                                                      \
    asm volatile("ldmatrix.sync.aligned.m8n8.x4.shared.b16 {%0,%1,%2,%3}, [%4];" \
        : "=r"((R)[0]), "=r"((R)[1]), "=r"((R)[2]), "=r"((R)[3]) : "r"(addr))

#define LDSM_X4_T(R, addr)                                                    \
    asm volatile("ldmatrix.sync.aligned.m8n8.x4.trans.shared.b16 {%0,%1,%2,%3}, [%4];" \
        : "=r"((R)[0]), "=r"((R)[1]), "=r"((R)[2]), "=r"((R)[3]) : "r"(addr))

#define MMA_F16(C, A, B0, B1)                                                 \
    asm volatile("mma.sync.aligned.m16n8k16.row.col.f32.f16.f16.f32 "         \
        "{%0,%1,%2,%3}, {%4,%5,%6,%7}, {%8,%9}, {%0,%1,%2,%3};"               \
        : "+f"((C)[0]), "+f"((C)[1]), "+f"((C)[2]), "+f"((C)[3])              \
        : "r"((A)[0]), "r"((A)[1]), "r"((A)[2]), "r"((A)[3]), "r"(B0), "r"(B1))

__device__ __forceinline__ void cp16(uint32_t dst, const void* src, int srcbytes) {
    asm volatile("cp.async.cg.shared.global [%0], [%1], 16, %2;"
                 :: "r"(dst), "l"(src), "r"(srcbytes) : "memory");
}
#define CP_COMMIT() asm volatile("cp.async.commit_group;" ::: "memory")
#define CP_WAIT(N)  asm volatile("cp.async.wait_group %0;" :: "n"(N) : "memory")

__device__ __forceinline__ uint32_t pack_h2(__half a, __half b) {
    __half2 t = __halves2half2(a, b);
    return *(uint32_t*)&t;
}

// ------------------------- prep: splits + weight converts -------------------
__global__ void prep_kernel(const float* __restrict__ hidden,
                            const float* __restrict__ w0, const float* __restrict__ w1,
                            const float* __restrict__ w2, const float* __restrict__ w3) {
    int z = blockIdx.z;
    int i = blockIdx.x * blockDim.x + threadIdx.x;
    if (z == 0) {
        int n4 = T_TOTAL * EMBED / 4;
        if (i >= n4) return;
        float4 v = ((const float4*)hidden)[i];
        union { __half b[4]; uint2 u; } H, L;
        float x[4] = {v.x, v.y, v.z, v.w};
#pragma unroll
        for (int j = 0; j < 4; j++) {
            __half h = __float2half(x[j]);
            H.b[j] = h;
            L.b[j] = __float2half(x[j] - __half2float(h));
        }
        ((uint2*)g_ahi)[i] = H.u;
        ((uint2*)g_alo)[i] = L.u;
    } else {
        int n4 = EMBED * EMBED / 4;
        if (i >= n4) return;
        const float* src = (z == 1) ? w0 : (z == 2) ? w1 : (z == 3) ? w2 : w3;
        float4 v = ((const float4*)src)[i];
        union { __half b[4]; uint2 u; } H;
        H.b[0] = __float2half(v.x);
        H.b[1] = __float2half(v.y);
        H.b[2] = __float2half(v.z);
        H.b[3] = __float2half(v.w);
        ((uint2*)g_whi[z - 1])[i] = H.u;
    }
}

// ------------------------- GEMM mainloop (templated) ------------------------
#define SM_GEMM_TOTAL 98304   // 1-pass: 3 x 32K stages; 2-pass: 2 x 48K stages

__device__ __forceinline__ uint32_t sw_off(int r, int chunk) {
    uint32_t off = (uint32_t)(r * 128 + chunk * 16);
    return off ^ ((off >> 3) & 0x70);
}

template<bool TP, int NS>
__device__ __forceinline__ void gemm_mainloop(
    const __half* __restrict__ Ahi, const __half* __restrict__ Alo,
    const __half* __restrict__ Bhi, int M, float (&acc)[4][4][4], char* smem)
{
    constexpr uint32_t OFF_ALO  = 16384;
    constexpr uint32_t OFF_BHI  = TP ? 32768 : 16384;
    constexpr uint32_t SM_STAGE = TP ? 49152 : 32768;

    const uint32_t sb = smem_u32(smem);
    const int tid = threadIdx.x;
    const int wid = tid >> 5, lane = tid & 31;
    const int row0 = blockIdx.y * 128;
    const int col0 = blockIdx.x * 128;
    const int wm = (wid & 1) * 64;
    const int wn = (wid >> 1) * 32;

#pragma unroll
    for (int a = 0; a < 4; a++)
#pragma unroll
        for (int b = 0; b < 4; b++)
#pragma unroll
            for (int c = 0; c < 4; c++) acc[a][b][c] = 0.0f;

    const int l_r[4] = { (tid + 0) >> 3, (tid + 256) >> 3, (tid + 512) >> 3, (tid + 768) >> 3 };
    const int l_c = tid & 7;

    const int a_r = lane & 15;
    const int a_c = lane >> 4;
    const int b_r = ((lane >> 4) << 3) + (lane & 7);
    const int b_c = (lane >> 3) & 1;

    auto load_tile = [&](int kt, int stage) {
        const int k0 = kt * 64;
        const uint32_t stb = sb + stage * SM_STAGE;
#pragma unroll
        for (int j = 0; j < 4; j++) {
            int r = l_r[j];
            uint32_t sw = sw_off(r, l_c);
            int apred = (row0 + r < M) ? 16 : 0;
            size_t aoff = (size_t)(row0 + r) * EMBED + k0 + l_c * 8;
            size_t boff = (size_t)(col0 + r) * EMBED + k0 + l_c * 8;
            cp16(stb + sw, Ahi + aoff, apred);
            if (TP) cp16(stb + OFF_ALO + sw, Alo + aoff, apred);
            cp16(stb + OFF_BHI + sw, Bhi + boff, 16);
        }
        CP_COMMIT();
    };

#pragma unroll
    for (int s = 0; s < NS - 1; s++) load_tile(s, s);

    for (int kt = 0; kt < 16; kt++) {
        CP_WAIT(NS - 2);        // tile kt complete
        __syncthreads();        // visibility + all warps done with recycled slot
        if (kt + NS - 1 < 16) load_tile(kt + NS - 1, (kt + NS - 1) % NS);
        else CP_COMMIT();       // keep wait-count invariant

        const uint32_t stb = sb + (kt % NS) * SM_STAGE;
#pragma unroll
        for (int ks = 0; ks < 4; ks++) {
            uint32_t ahi[4][4], alo[4][4];
#pragma unroll
            for (int mt = 0; mt < 4; mt++) {
                uint32_t sw = sw_off(wm + mt * 16 + a_r, ks * 2 + a_c);
                LDSM_X4(ahi[mt], stb + sw);
                if (TP) LDSM_X4(alo[mt], stb + OFF_ALO + sw);
            }
            uint32_t bhi[2][4];
#pragma unroll
            for (int np = 0; np < 2; np++) {
                uint32_t sw = sw_off(wn + np * 16 + b_r, ks * 2 + b_c);
                LDSM_X4(bhi[np], stb + OFF_BHI + sw);
            }
#pragma unroll
            for (int mt = 0; mt < 4; mt++) {
#pragma unroll
                for (int nt = 0; nt < 4; nt++) {
                    uint32_t bh0 = bhi[nt >> 1][(nt & 1) * 2];
                    uint32_t bh1 = bhi[nt >> 1][(nt & 1) * 2 + 1];
                    MMA_F16(acc[mt][nt], ahi[mt], bh0, bh1);
                    if (TP) MMA_F16(acc[mt][nt], alo[mt], bh0, bh1);
                }
            }
        }
    }
}

// ------------------------- QKV GEMM (1-pass) + fused rope epilogue ----------
// z=0: q -> rope -> *0.125 -> hi/lo split -> g_qhi/g_qlo
// z=1: k -> rope -> fp16 -> g_kh
// z=2: v -> +bias -> fp16 -> g_vh (direct store, no staging)
__global__ __launch_bounds__(256, 2) void qkv_mma_kernel(
    const float* __restrict__ qb, const float* __restrict__ vb,
    const float* __restrict__ cosp, const float* __restrict__ sinp)
{
    extern __shared__ char smem[];
    const int z = blockIdx.z;
    float acc[4][4][4];
    gemm_mainloop<false, 3>(g_ahi, nullptr, g_whi[z], T_TOTAL, acc, smem);

    const int tid = threadIdx.x;
    const int wid = tid >> 5, lane = tid & 31;
    const int row0 = blockIdx.y * 128;
    const int col0 = blockIdx.x * 128;
    const int wm = (wid & 1) * 64;
    const int wn = (wid >> 1) * 32;
    const int erow = lane >> 2;
    const int ecol = (lane & 3) * 2;

    if (z == 2) {
        // direct v epilogue
#pragma unroll
        for (int mt = 0; mt < 4; mt++) {
            int r0g = row0 + wm + mt * 16 + erow;
#pragma unroll
            for (int nt = 0; nt < 4; nt++) {
                int colg = col0 + wn + nt * 8 + ecol;
                float b0 = vb[colg], b1 = vb[colg + 1];
                if (r0g < T_TOTAL) {
                    __half2 v = __floats2half2_rn(acc[mt][nt][0] + b0, acc[mt][nt][1] + b1);
                    *(__half2*)&g_vh[(size_t)r0g * EMBED + colg] = v;
                }
                if (r0g + 8 < T_TOTAL) {
                    __half2 v = __floats2half2_rn(acc[mt][nt][2] + b0, acc[mt][nt][3] + b1);
                    *(__half2*)&g_vh[(size_t)(r0g + 8) * EMBED + colg] = v;
                }
            }
        }
        return;
    }

    // q/k: stage fp32 tile in smem, then rope across the (d, d+32) pairs
    __syncthreads();                       // mainloop smem reads finished
    float* st = (float*)smem;              // [128][130]
#pragma unroll
    for (int mt = 0; mt < 4; mt++) {
        int r0 = wm + mt * 16 + erow;
#pragma unroll
        for (int nt = 0; nt < 4; nt++) {
            int c = wn + nt * 8 + ecol;
            float b0 = (z == 0) ? qb[col0 + c] : 0.0f;
            float b1 = (z == 0) ? qb[col0 + c + 1] : 0.0f;
            st[r0 * 130 + c]           = acc[mt][nt][0] + b0;
            st[r0 * 130 + c + 1]       = acc[mt][nt][1] + b1;
            st[(r0 + 8) * 130 + c]     = acc[mt][nt][2] + b0;
            st[(r0 + 8) * 130 + c + 1] = acc[mt][nt][3] + b1;
        }
    }
    __syncthreads();

    for (int i = tid; i < 128 * 64; i += 256) {
        int r = i >> 6;
        int p = i & 63;
        int t = row0 + r;
        if (t >= T_TOTAL) continue;
        int hh = p >> 5, d = p & 31;
        int c1 = hh * 64 + d, c2 = c1 + 32;
        float x1 = st[r * 130 + c1], x2 = st[r * 130 + c2];
        float cc = cosp[t * HDIM + d], ss = sinp[t * HDIM + d];
        float y1 = x1 * cc - x2 * ss;
        float y2 = x2 * cc + x1 * ss;
        size_t o1 = (size_t)t * EMBED + col0 + c1;
        size_t o2 = o1 + 32;
        if (z == 0) {
            y1 *= 0.125f; y2 *= 0.125f;
            __half h1 = __float2half(y1), h2 = __float2half(y2);
            g_qhi[o1] = h1;
            g_qhi[o2] = h2;
            g_qlo[o1] = __float2half(y1 - __half2float(h1));
            g_qlo[o2] = __float2half(y2 - __half2float(h2));
        } else {
            g_kh[o1] = __float2half(y1);
            g_kh[o2] = __float2half(y2);
        }
    }
}

// ------------------------- output projection (2-pass, 2-stage) --------------
__global__ __launch_bounds__(256, 2) void out_mma_kernel(const float* __restrict__ ob,
                                                         float* __restrict__ out)
{
    extern __shared__ char smem[];
    float acc[4][4][4];
    gemm_mainloop<true, 2>(g_chi, g_clo, g_whi[3], T_TOTAL, acc, smem);

    const int tid = threadIdx.x;
    const int wid = tid >> 5, lane = tid & 31;
    const int row0 = blockIdx.y * 128;
    const int col0 = blockIdx.x * 128;
    const int wm = (wid & 1) * 64;
    const int wn = (wid >> 1) * 32;
    const int erow = lane >> 2;
    const int ecol = (lane & 3) * 2;
#pragma unroll
    for (int mt = 0; mt < 4; mt++) {
        int r0g = row0 + wm + mt * 16 + erow;
#pragma unroll
        for (int nt = 0; nt < 4; nt++) {
            int colg = col0 + wn + nt * 8 + ecol;
            float b0 = ob[colg], b1 = ob[colg + 1];
            if (r0g < T_TOTAL) {
                float2 v = make_float2(acc[mt][nt][0] + b0, acc[mt][nt][1] + b1);
                *(float2*)&out[(size_t)r0g * EMBED + colg] = v;
            }
            if (r0g + 8 < T_TOTAL) {
                float2 v = make_float2(acc[mt][nt][2] + b0, acc[mt][nt][3] + b1);
                *(float2*)&out[(size_t)(r0g + 8) * EMBED + colg] = v;
            }
        }
    }
}

// ------------------------- flash attention (fp16 MMA, 3-stage KV) -----------
#define FSM_QHI 0
#define FSM_QLO 8192
#define FSM_KV  16384
#define FSM_TOTAL 65536

__global__ __launch_bounds__(128) void flash_kernel() {
    extern __shared__ char smem[];
    const uint32_t sb = smem_u32(smem);
    const int tid = threadIdx.x;
    const int wid = tid >> 5, lane = tid & 31;
    const int h = blockIdx.y;

    int rem = blockIdx.x, b = 0;
    while (rem >= c_nt[b]) { rem -= c_nt[b]; ++b; }
    const int qt = rem;
    const int tok0 = c_cu[b];
    const int tokq = tok0 + qt * 64;

    auto kvload = [&](int kt, int slot) {
        const int tokk = tok0 + kt * 64;
        const uint32_t kb = sb + FSM_KV + slot * 16384;
#pragma unroll
        for (int j = 0; j < 4; j++) {
            int idx = tid + j * 128;
            int r = idx >> 3;
            int c = idx & 7;
            uint32_t sw = sw_off(r, c);
            size_t go = (size_t)(tokk + r) * EMBED + h * HDIM + c * 8;
            cp16(kb + sw, g_kh + go, 16);
            cp16(kb + 8192 + sw, g_vh + go, 16);
        }
    };

#pragma unroll
    for (int j = 0; j < 4; j++) {
        int idx = tid + j * 128;
        int r = idx >> 3;
        int c = idx & 7;
        uint32_t sw = sw_off(r, c);
        size_t go = (size_t)(tokq + r) * EMBED + h * HDIM + c * 8;
        cp16(sb + FSM_QHI + sw, g_qhi + go, 16);
        cp16(sb + FSM_QLO + sw, g_qlo + go, 16);
    }
    kvload(0, 0);
    CP_COMMIT();
    if (qt >= 1) kvload(1, 1);
    CP_COMMIT();

    CP_WAIT(1);
    __syncthreads();

    uint32_t qhi[4][4], qlo[4][4];
    {
        const int a_row = wid * 16 + (lane & 15);
        const int a_c = lane >> 4;
#pragma unroll
        for (int ks = 0; ks < 4; ks++) {
            uint32_t sw = sw_off(a_row, ks * 2 + a_c);
            LDSM_X4(qhi[ks], sb + FSM_QHI + sw);
            LDSM_X4(qlo[ks], sb + FSM_QLO + sw);
        }
    }

    float oacc[8][4];
#pragma unroll
    for (int n = 0; n < 8; n++)
#pragma unroll
        for (int c = 0; c < 4; c++) oacc[n][c] = 0.0f;
    float m0 = -1e30f, m1 = -1e30f, l0 = 0.0f, l1 = 0.0f;

    const int b_r = ((lane >> 4) << 3) + (lane & 7);
    const int b_c = (lane >> 3) & 1;
    const int v_row = ((lane >> 3) & 1) * 8 + (lane & 7);
    const int v_ch  = lane >> 4;

    for (int kt = 0; kt <= qt; kt++) {
        CP_WAIT(1);
        __syncthreads();
        if (kt + 2 <= qt) kvload(kt + 2, (kt + 2) % 3);
        CP_COMMIT();

        const uint32_t kbase = sb + FSM_KV + (kt % 3) * 16384;
        const uint32_t vbase = kbase + 8192;

        float sacc[8][4];
#pragma unroll
        for (int n = 0; n < 8; n++)
#pragma unroll
            for (int c = 0; c < 4; c++) sacc[n][c] = 0.0f;

#pragma unroll
        for (int ks = 0; ks < 4; ks++) {
            uint32_t kf[4][4];
#pragma unroll
            for (int np = 0; np < 4; np++) {
                uint32_t sw = sw_off(np * 16 + b_r, ks * 2 + b_c);
                LDSM_X4(kf[np], kbase + sw);
            }
#pragma unroll
            for (int nt = 0; nt < 8; nt++) {
                uint32_t b0 = kf[nt >> 1][(nt & 1) * 2];
                uint32_t b1 = kf[nt >> 1][(nt & 1) * 2 + 1];
                MMA_F16(sacc[nt], qhi[ks], b0, b1);
                MMA_F16(sacc[nt], qlo[ks], b0, b1);
            }
        }

        if (kt == qt) {
            const int r0 = wid * 16 + (lane >> 2);
#pragma unroll
            for (int nt = 0; nt < 8; nt++) {
                int c0 = nt * 8 + (lane & 3) * 2;
                if (c0 > r0) sacc[nt][0] = -1e30f;
                if (c0 + 1 > r0) sacc[nt][1] = -1e30f;
                if (c0 > r0 + 8) sacc[nt][2] = -1e30f;
                if (c0 + 1 > r0 + 8) sacc[nt][3] = -1e30f;
            }
        }

        {
            float tm0 = -1e30f, tm1 = -1e30f;
#pragma unroll
            for (int nt = 0; nt < 8; nt++) {
                tm0 = fmaxf(tm0, fmaxf(sacc[nt][0], sacc[nt][1]));
                tm1 = fmaxf(tm1, fmaxf(sacc[nt][2], sacc[nt][3]));
            }
            tm0 = fmaxf(tm0, __shfl_xor_sync(0xffffffffu, tm0, 1, 32));
            tm0 = fmaxf(tm0, __shfl_xor_sync(0xffffffffu, tm0, 2, 32));
            tm1 = fmaxf(tm1, __shfl_xor_sync(0xffffffffu, tm1, 1, 32));
            tm1 = fmaxf(tm1, __shfl_xor_sync(0xffffffffu, tm1, 2, 32));
            float mn0 = fmaxf(m0, tm0), mn1 = fmaxf(m1, tm1);
            float al0 = __expf(m0 - mn0), al1 = __expf(m1 - mn1);
            float rs0 = 0.0f, rs1 = 0.0f;
#pragma unroll
            for (int nt = 0; nt < 8; nt++) {
                sacc[nt][0] = __expf(sacc[nt][0] - mn0); rs0 += sacc[nt][0];
                sacc[nt][1] = __expf(sacc[nt][1] - mn0); rs0 += sacc[nt][1];
                sacc[nt][2] = __expf(sacc[nt][2] - mn1); rs1 += sacc[nt][2];
                sacc[nt][3] = __expf(sacc[nt][3] - mn1); rs1 += sacc[nt][3];
            }
            rs0 += __shfl_xor_sync(0xffffffffu, rs0, 1, 32);
            rs0 += __shfl_xor_sync(0xffffffffu, rs0, 2, 32);
            rs1 += __shfl_xor_sync(0xffffffffu, rs1, 1, 32);
            rs1 += __shfl_xor_sync(0xffffffffu, rs1, 2, 32);
            l0 = l0 * al0 + rs0; m0 = mn0;
            l1 = l1 * al1 + rs1; m1 = mn1;
#pragma unroll
            for (int n = 0; n < 8; n++) {
                oacc[n][0] *= al0; oacc[n][1] *= al0;
                oacc[n][2] *= al1; oacc[n][3] *= al1;
            }
        }

#pragma unroll
        for (int ks = 0; ks < 4; ks++) {
            uint32_t ph[4], pl[4];
            {
                float* s0 = sacc[2 * ks];
                float* s1 = sacc[2 * ks + 1];
                __half h00 = __float2half(s0[0]), h01 = __float2half(s0[1]);
                __half h02 = __float2half(s0[2]), h03 = __float2half(s0[3]);
                __half h10 = __float2half(s1[0]), h11 = __float2half(s1[1]);
                __half h12 = __float2half(s1[2]), h13 = __float2half(s1[3]);
                ph[0] = pack_h2(h00, h01);
                ph[1] = pack_h2(h02, h03);
                ph[2] = pack_h2(h10, h11);
                ph[3] = pack_h2(h12, h13);
                pl[0] = pack_h2(__float2half(s0[0] - __half2float(h00)),
                                __float2half(s0[1] - __half2float(h01)));
                pl[1] = pack_h2(__float2half(s0[2] - __half2float(h02)),
                                __float2half(s0[3] - __half2float(h03)));
                pl[2] = pack_h2(__float2half(s1[0] - __half2float(h10)),
                                __float2half(s1[1] - __half2float(h11)));
                pl[3] = pack_h2(__float2half(s1[2] - __half2float(h12)),
                                __float2half(s1[3] - __half2float(h13)));
            }
#pragma unroll
            for (int nd2 = 0; nd2 < 4; nd2++) {
                uint32_t vf[4];
                uint32_t sw = sw_off(ks * 16 + v_row, nd2 * 2 + v_ch);
                LDSM_X4_T(vf, vbase + sw);
                MMA_F16(oacc[nd2 * 2],     ph, vf[0], vf[1]);
                MMA_F16(oacc[nd2 * 2],     pl, vf[0], vf[1]);
                MMA_F16(oacc[nd2 * 2 + 1], ph, vf[2], vf[3]);
                MMA_F16(oacc[nd2 * 2 + 1], pl, vf[2], vf[3]);
            }
        }
    }

    {
        float inv0 = 1.0f / l0;
        float inv1 = 1.0f / l1;
        int gr0 = tokq + wid * 16 + (lane >> 2);
        int gr1 = gr0 + 8;
#pragma unroll
        for (int nt = 0; nt < 8; nt++) {
            int col = h * HDIM + nt * 8 + (lane & 3) * 2;
            {
                float v0 = oacc[nt][0] * inv0, v1 = oacc[nt][1] * inv0;
                __half h0 = __float2half(v0), h1 = __float2half(v1);
                *(__half2*)&g_chi[(size_t)gr0 * EMBED + col] = __halves2half2(h0, h1);
                *(__half2*)&g_clo[(size_t)gr0 * EMBED + col] =
                    __halves2half2(__float2half(v0 - __half2float(h0)),
                                   __float2half(v1 - __half2float(h1)));
            }
            {
                float v0 = oacc[nt][2] * inv1, v1 = oacc[nt][3] * inv1;
                __half h0 = __float2half(v0), h1 = __float2half(v1);
                *(__half2*)&g_chi[(size_t)gr1 * EMBED + col] = __halves2half2(h0, h1);
                *(__half2*)&g_clo[(size_t)gr1 * EMBED + col] =
                    __halves2half2(__float2half(v0 - __half2float(h0)),
                                   __float2half(v1 - __half2float(h1)));
            }
        }
    }
}

// ---------------------------------------------------------------------------
extern "C" void kernel_launch(void* const* d_in, const int* in_sizes, int n_in,
                              void* d_out, int out_size)
{
    const float* hidden = (const float*)d_in[0];
    const float* cosp   = (const float*)d_in[1];
    const float* sinp   = (const float*)d_in[2];
    const float* q_w    = (const float*)d_in[3];
    const float* q_b    = (const float*)d_in[4];
    const float* k_w    = (const float*)d_in[5];
    const float* v_w    = (const float*)d_in[6];
    const float* v_b    = (const float*)d_in[7];
    const float* out_w  = (const float*)d_in[8];
    const float* out_b  = (const float*)d_in[9];
    float* out = (float*)d_out;

    // 1. Prep: hidden hi/lo split + weight fp16 converts (one launch)
    {
        int nblk = (T_TOTAL * EMBED / 4 + 255) / 256;   // covers the largest z
        prep_kernel<<<dim3(nblk, 1, 5), 256>>>(hidden, q_w, k_w, v_w, out_w);
    }
    // 2. QKV GEMMs (1-pass, fused rope/split epilogues)
    cudaFuncSetAttribute(qkv_mma_kernel, cudaFuncAttributeMaxDynamicSharedMemorySize, SM_GEMM_TOTAL);
    qkv_mma_kernel<<<dim3(EMBED / 128, MTILES, 3), 256, SM_GEMM_TOTAL>>>(q_b, v_b, cosp, sinp);

    // 3. Flash attention (fp16 MMA, writes g_chi/g_clo)
    cudaFuncSetAttribute(flash_kernel, cudaFuncAttributeMaxDynamicSharedMemorySize, FSM_TOTAL);
    flash_kernel<<<dim3(153, NHEADS), 128, FSM_TOTAL>>>();

    // 4. Output GEMM (2-pass, 2-stage, 2 CTAs/SM)
    cudaFuncSetAttribute(out_mma_kernel, cudaFuncAttributeMaxDynamicSharedMemorySize, SM_GEMM_TOTAL);
    out_mma_kernel<<<dim3(EMBED / 128, MTILES, 1), 256, SM_GEMM_TOTAL>>>(out_b, out);
}

// round 12
// speedup vs baseline: 7.2525x; 1.2046x over previous
#include <cuda_runtime.h>
#include <cuda_fp16.h>
#include <cstdint>

#define T_TOTAL 9792
#define EMBED   1024
#define NHEADS  16
#define HDIM    64
#define MTILES  77          // ceil(9792/128)

// ------------------------- scratch (static device) -------------------------
__device__ __half g_ahi[(size_t)T_TOTAL * EMBED];
__device__ __half g_alo[(size_t)T_TOTAL * EMBED];
__device__ __half g_chi[(size_t)T_TOTAL * EMBED];
__device__ __half g_whi[4][(size_t)EMBED * EMBED];

__device__ __half g_qhi[(size_t)T_TOTAL * EMBED];  // rope'd q * 0.125, hi
__device__ __half g_qlo[(size_t)T_TOTAL * EMBED];  // rope'd q * 0.125, lo
__device__ __half g_kh [(size_t)T_TOTAL * EMBED];  // rope'd k, fp16
__device__ __half g_vh [(size_t)T_TOTAL * EMBED];  // v, fp16

__constant__ int c_cu[12] = {0, 1024, 1792, 2688, 3200, 4224, 4864, 5888, 6656, 7168, 8064, 9088};
__constant__ int c_nt[12] = {16, 12, 14, 8, 16, 10, 16, 12, 8, 14, 16, 11};

// ------------------------- PTX helpers (baseline ISA only) ------------------
__device__ __forceinline__ uint32_t smem_u32(const void* p) {
    uint32_t a;
    asm("{ .reg .u64 t; cvta.to.shared.u64 t, %1; cvt.u32.u64 %0, t; }" : "=r"(a) : "l"(p));
    return a;
}

#define LDSM_X4(R, addr)                                                      \
    asm volatile("ldmatrix.sync.aligned.m8n8.x4.shared.b16 {%0,%1,%2,%3}, [%4];" \
        : "=r"((R)[0]), "=r"((R)[1]), "=r"((R)[2]), "=r"((R)[3]) : "r"(addr))

#define LDSM_X4_T(R, addr)                                                    \
    asm volatile("ldmatrix.sync.aligned.m8n8.x4.trans.shared.b16 {%0,%1,%2,%3}, [%4];" \
        : "=r"((R)[0]), "=r"((R)[1]), "=r"((R)[2]), "=r"((R)[3]) : "r"(addr))

#define MMA_F16(C, A, B0, B1)                                                 \
    asm volatile("mma.sync.aligned.m16n8k16.row.col.f32.f16.f16.f32 "         \
        "{%0,%1,%2,%3}, {%4,%5,%6,%7}, {%8,%9}, {%0,%1,%2,%3};"               \
        : "+f"((C)[0]), "+f"((C)[1]), "+f"((C)[2]), "+f"((C)[3])              \
        : "r"((A)[0]), "r"((A)[1]), "r"((A)[2]), "r"((A)[3]), "r"(B0), "r"(B1))

__device__ __forceinline__ void cp16(uint32_t dst, const void* src, int srcbytes) {
    asm volatile("cp.async.cg.shared.global [%0], [%1], 16, %2;"
                 :: "r"(dst), "l"(src), "r"(srcbytes) : "memory");
}
#define CP_COMMIT() asm volatile("cp.async.commit_group;" ::: "memory")
#define CP_WAIT(N)  asm volatile("cp.async.wait_group %0;" :: "n"(N) : "memory")

__device__ __forceinline__ uint32_t pack_h2(__half a, __half b) {
    __half2 t = __halves2half2(a, b);
    return *(uint32_t*)&t;
}

// ------------------------- prep: splits + weight converts -------------------
__global__ void prep_kernel(const float* __restrict__ hidden,
                            const float* __restrict__ w0, const float* __restrict__ w1,
                            const float* __restrict__ w2, const float* __restrict__ w3) {
    int z = blockIdx.z;
    int i = blockIdx.x * blockDim.x + threadIdx.x;
    if (z == 0) {
        int n4 = T_TOTAL * EMBED / 4;
        if (i >= n4) return;
        float4 v = ((const float4*)hidden)[i];
        union { __half b[4]; uint2 u; } H, L;
        float x[4] = {v.x, v.y, v.z, v.w};
#pragma unroll
        for (int j = 0; j < 4; j++) {
            __half h = __float2half(x[j]);
            H.b[j] = h;
            L.b[j] = __float2half(x[j] - __half2float(h));
        }
        ((uint2*)g_ahi)[i] = H.u;
        ((uint2*)g_alo)[i] = L.u;
    } else {
        int n4 = EMBED * EMBED / 4;
        if (i >= n4) return;
        const float* src = (z == 1) ? w0 : (z == 2) ? w1 : (z == 3) ? w2 : w3;
        float4 v = ((const float4*)src)[i];
        union { __half b[4]; uint2 u; } H;
        H.b[0] = __float2half(v.x);
        H.b[1] = __float2half(v.y);
        H.b[2] = __float2half(v.z);
        H.b[3] = __float2half(v.w);
        ((uint2*)g_whi[z - 1])[i] = H.u;
    }
}

// ------------------------- GEMM mainloop (1-pass, 3-stage) ------------------
#define SM_GEMM_TOTAL 98304   // 3 x 32K stages

__device__ __forceinline__ uint32_t sw_off(int r, int chunk) {
    uint32_t off = (uint32_t)(r * 128 + chunk * 16);
    return off ^ ((off >> 3) & 0x70);
}

__device__ __forceinline__ void gemm_mainloop(
    const __half* __restrict__ Ahi, const __half* __restrict__ Bhi,
    int M, float (&acc)[4][4][4], char* smem)
{
    constexpr uint32_t OFF_BHI  = 16384;
    constexpr uint32_t SM_STAGE = 32768;
    constexpr int NS = 3;

    const uint32_t sb = smem_u32(smem);
    const int tid = threadIdx.x;
    const int wid = tid >> 5, lane = tid & 31;
    const int row0 = blockIdx.y * 128;
    const int col0 = blockIdx.x * 128;
    const int wm = (wid & 1) * 64;
    const int wn = (wid >> 1) * 32;

#pragma unroll
    for (int a = 0; a < 4; a++)
#pragma unroll
        for (int b = 0; b < 4; b++)
#pragma unroll
            for (int c = 0; c < 4; c++) acc[a][b][c] = 0.0f;

    const int l_r[4] = { (tid + 0) >> 3, (tid + 256) >> 3, (tid + 512) >> 3, (tid + 768) >> 3 };
    const int l_c = tid & 7;

    const int a_r = lane & 15;
    const int a_c = lane >> 4;
    const int b_r = ((lane >> 4) << 3) + (lane & 7);
    const int b_c = (lane >> 3) & 1;

    auto load_tile = [&](int kt, int stage) {
        const int k0 = kt * 64;
        const uint32_t stb = sb + stage * SM_STAGE;
#pragma unroll
        for (int j = 0; j < 4; j++) {
            int r = l_r[j];
            uint32_t sw = sw_off(r, l_c);
            int apred = (row0 + r < M) ? 16 : 0;
            size_t aoff = (size_t)(row0 + r) * EMBED + k0 + l_c * 8;
            size_t boff = (size_t)(col0 + r) * EMBED + k0 + l_c * 8;
            cp16(stb + sw, Ahi + aoff, apred);
            cp16(stb + OFF_BHI + sw, Bhi + boff, 16);
        }
        CP_COMMIT();
    };

#pragma unroll
    for (int s = 0; s < NS - 1; s++) load_tile(s, s);

    for (int kt = 0; kt < 16; kt++) {
        CP_WAIT(NS - 2);        // tile kt complete
        __syncthreads();        // visibility + all warps done with recycled slot
        if (kt + NS - 1 < 16) load_tile(kt + NS - 1, (kt + NS - 1) % NS);
        else CP_COMMIT();       // keep wait-count invariant

        const uint32_t stb = sb + (kt % NS) * SM_STAGE;
#pragma unroll
        for (int ks = 0; ks < 4; ks++) {
            uint32_t ahi[4][4];
#pragma unroll
            for (int mt = 0; mt < 4; mt++) {
                uint32_t sw = sw_off(wm + mt * 16 + a_r, ks * 2 + a_c);
                LDSM_X4(ahi[mt], stb + sw);
            }
            uint32_t bhi[2][4];
#pragma unroll
            for (int np = 0; np < 2; np++) {
                uint32_t sw = sw_off(wn + np * 16 + b_r, ks * 2 + b_c);
                LDSM_X4(bhi[np], stb + OFF_BHI + sw);
            }
#pragma unroll
            for (int mt = 0; mt < 4; mt++) {
#pragma unroll
                for (int nt = 0; nt < 4; nt++) {
                    uint32_t bh0 = bhi[nt >> 1][(nt & 1) * 2];
                    uint32_t bh1 = bhi[nt >> 1][(nt & 1) * 2 + 1];
                    MMA_F16(acc[mt][nt], ahi[mt], bh0, bh1);
                }
            }
        }
    }
}

// ------------------------- QKV GEMM (1-pass) + fused rope epilogue ----------
__global__ __launch_bounds__(256, 2) void qkv_mma_kernel(
    const float* __restrict__ qb, const float* __restrict__ vb,
    const float* __restrict__ cosp, const float* __restrict__ sinp)
{
    extern __shared__ char smem[];
    const int z = blockIdx.z;
    float acc[4][4][4];
    gemm_mainloop(g_ahi, g_whi[z], T_TOTAL, acc, smem);

    const int tid = threadIdx.x;
    const int wid = tid >> 5, lane = tid & 31;
    const int row0 = blockIdx.y * 128;
    const int col0 = blockIdx.x * 128;
    const int wm = (wid & 1) * 64;
    const int wn = (wid >> 1) * 32;
    const int erow = lane >> 2;
    const int ecol = (lane & 3) * 2;

    if (z == 2) {
#pragma unroll
        for (int mt = 0; mt < 4; mt++) {
            int r0g = row0 + wm + mt * 16 + erow;
#pragma unroll
            for (int nt = 0; nt < 4; nt++) {
                int colg = col0 + wn + nt * 8 + ecol;
                float b0 = vb[colg], b1 = vb[colg + 1];
                if (r0g < T_TOTAL) {
                    __half2 v = __floats2half2_rn(acc[mt][nt][0] + b0, acc[mt][nt][1] + b1);
                    *(__half2*)&g_vh[(size_t)r0g * EMBED + colg] = v;
                }
                if (r0g + 8 < T_TOTAL) {
                    __half2 v = __floats2half2_rn(acc[mt][nt][2] + b0, acc[mt][nt][3] + b1);
                    *(__half2*)&g_vh[(size_t)(r0g + 8) * EMBED + colg] = v;
                }
            }
        }
        return;
    }

    // q/k: stage fp32 tile in smem, then rope across the (d, d+32) pairs
    __syncthreads();
    float* st = (float*)smem;              // [128][130]
#pragma unroll
    for (int mt = 0; mt < 4; mt++) {
        int r0 = wm + mt * 16 + erow;
#pragma unroll
        for (int nt = 0; nt < 4; nt++) {
            int c = wn + nt * 8 + ecol;
            float b0 = (z == 0) ? qb[col0 + c] : 0.0f;
            float b1 = (z == 0) ? qb[col0 + c + 1] : 0.0f;
            st[r0 * 130 + c]           = acc[mt][nt][0] + b0;
            st[r0 * 130 + c + 1]       = acc[mt][nt][1] + b1;
            st[(r0 + 8) * 130 + c]     = acc[mt][nt][2] + b0;
            st[(r0 + 8) * 130 + c + 1] = acc[mt][nt][3] + b1;
        }
    }
    __syncthreads();

    for (int i = tid; i < 128 * 64; i += 256) {
        int r = i >> 6;
        int p = i & 63;
        int t = row0 + r;
        if (t >= T_TOTAL) continue;
        int hh = p >> 5, d = p & 31;
        int c1 = hh * 64 + d, c2 = c1 + 32;
        float x1 = st[r * 130 + c1], x2 = st[r * 130 + c2];
        float cc = cosp[t * HDIM + d], ss = sinp[t * HDIM + d];
        float y1 = x1 * cc - x2 * ss;
        float y2 = x2 * cc + x1 * ss;
        size_t o1 = (size_t)t * EMBED + col0 + c1;
        size_t o2 = o1 + 32;
        if (z == 0) {
            y1 *= 0.125f; y2 *= 0.125f;
            __half h1 = __float2half(y1), h2 = __float2half(y2);
            g_qhi[o1] = h1;
            g_qhi[o2] = h2;
            g_qlo[o1] = __float2half(y1 - __half2float(h1));
            g_qlo[o2] = __float2half(y2 - __half2float(h2));
        } else {
            g_kh[o1] = __float2half(y1);
            g_kh[o2] = __float2half(y2);
        }
    }
}

// ------------------------- output projection (1-pass, 3-stage) --------------
__global__ __launch_bounds__(256, 2) void out_mma_kernel(const float* __restrict__ ob,
                                                         float* __restrict__ out)
{
    extern __shared__ char smem[];
    float acc[4][4][4];
    gemm_mainloop(g_chi, g_whi[3], T_TOTAL, acc, smem);

    const int tid = threadIdx.x;
    const int wid = tid >> 5, lane = tid & 31;
    const int row0 = blockIdx.y * 128;
    const int col0 = blockIdx.x * 128;
    const int wm = (wid & 1) * 64;
    const int wn = (wid >> 1) * 32;
    const int erow = lane >> 2;
    const int ecol = (lane & 3) * 2;
#pragma unroll
    for (int mt = 0; mt < 4; mt++) {
        int r0g = row0 + wm + mt * 16 + erow;
#pragma unroll
        for (int nt = 0; nt < 4; nt++) {
            int colg = col0 + wn + nt * 8 + ecol;
            float b0 = ob[colg], b1 = ob[colg + 1];
            if (r0g < T_TOTAL) {
                float2 v = make_float2(acc[mt][nt][0] + b0, acc[mt][nt][1] + b1);
                *(float2*)&out[(size_t)r0g * EMBED + colg] = v;
            }
            if (r0g + 8 < T_TOTAL) {
                float2 v = make_float2(acc[mt][nt][2] + b0, acc[mt][nt][3] + b1);
                *(float2*)&out[(size_t)(r0g + 8) * EMBED + colg] = v;
            }
        }
    }
}

// ------------------------- flash attention (fp16 MMA) ----------------------
// S = (Qhi+Qlo)·K (2-pass), O = P·V (1-pass). 3-stage KV pipeline.
#define FSM_QHI 0
#define FSM_QLO 8192
#define FSM_KV  16384
#define FSM_TOTAL 65536

__global__ __launch_bounds__(128) void flash_kernel() {
    extern __shared__ char smem[];
    const uint32_t sb = smem_u32(smem);
    const int tid = threadIdx.x;
    const int wid = tid >> 5, lane = tid & 31;
    const int h = blockIdx.y;

    int rem = blockIdx.x, b = 0;
    while (rem >= c_nt[b]) { rem -= c_nt[b]; ++b; }
    const int qt = rem;
    const int tok0 = c_cu[b];
    const int tokq = tok0 + qt * 64;

    auto kvload = [&](int kt, int slot) {
        const int tokk = tok0 + kt * 64;
        const uint32_t kb = sb + FSM_KV + slot * 16384;
#pragma unroll
        for (int j = 0; j < 4; j++) {
            int idx = tid + j * 128;
            int r = idx >> 3;
            int c = idx & 7;
            uint32_t sw = sw_off(r, c);
            size_t go = (size_t)(tokk + r) * EMBED + h * HDIM + c * 8;
            cp16(kb + sw, g_kh + go, 16);
            cp16(kb + 8192 + sw, g_vh + go, 16);
        }
    };

#pragma unroll
    for (int j = 0; j < 4; j++) {
        int idx = tid + j * 128;
        int r = idx >> 3;
        int c = idx & 7;
        uint32_t sw = sw_off(r, c);
        size_t go = (size_t)(tokq + r) * EMBED + h * HDIM + c * 8;
        cp16(sb + FSM_QHI + sw, g_qhi + go, 16);
        cp16(sb + FSM_QLO + sw, g_qlo + go, 16);
    }
    kvload(0, 0);
    CP_COMMIT();
    if (qt >= 1) kvload(1, 1);
    CP_COMMIT();

    CP_WAIT(1);
    __syncthreads();

    uint32_t qhi[4][4], qlo[4][4];
    {
        const int a_row = wid * 16 + (lane & 15);
        const int a_c = lane >> 4;
#pragma unroll
        for (int ks = 0; ks < 4; ks++) {
            uint32_t sw = sw_off(a_row, ks * 2 + a_c);
            LDSM_X4(qhi[ks], sb + FSM_QHI + sw);
            LDSM_X4(qlo[ks], sb + FSM_QLO + sw);
        }
    }

    float oacc[8][4];
#pragma unroll
    for (int n = 0; n < 8; n++)
#pragma unroll
        for (int c = 0; c < 4; c++) oacc[n][c] = 0.0f;
    float m0 = -1e30f, m1 = -1e30f, l0 = 0.0f, l1 = 0.0f;

    const int b_r = ((lane >> 4) << 3) + (lane & 7);
    const int b_c = (lane >> 3) & 1;
    const int v_row = ((lane >> 3) & 1) * 8 + (lane & 7);
    const int v_ch  = lane >> 4;

    for (int kt = 0; kt <= qt; kt++) {
        CP_WAIT(1);
        __syncthreads();
        if (kt + 2 <= qt) kvload(kt + 2, (kt + 2) % 3);
        CP_COMMIT();

        const uint32_t kbase = sb + FSM_KV + (kt % 3) * 16384;
        const uint32_t vbase = kbase + 8192;

        float sacc[8][4];
#pragma unroll
        for (int n = 0; n < 8; n++)
#pragma unroll
            for (int c = 0; c < 4; c++) sacc[n][c] = 0.0f;

#pragma unroll
        for (int ks = 0; ks < 4; ks++) {
            uint32_t kf[4][4];
#pragma unroll
            for (int np = 0; np < 4; np++) {
                uint32_t sw = sw_off(np * 16 + b_r, ks * 2 + b_c);
                LDSM_X4(kf[np], kbase + sw);
            }
#pragma unroll
            for (int nt = 0; nt < 8; nt++) {
                uint32_t b0 = kf[nt >> 1][(nt & 1) * 2];
                uint32_t b1 = kf[nt >> 1][(nt & 1) * 2 + 1];
                MMA_F16(sacc[nt], qhi[ks], b0, b1);
                MMA_F16(sacc[nt], qlo[ks], b0, b1);
            }
        }

        if (kt == qt) {
            const int r0 = wid * 16 + (lane >> 2);
#pragma unroll
            for (int nt = 0; nt < 8; nt++) {
                int c0 = nt * 8 + (lane & 3) * 2;
                if (c0 > r0) sacc[nt][0] = -1e30f;
                if (c0 + 1 > r0) sacc[nt][1] = -1e30f;
                if (c0 > r0 + 8) sacc[nt][2] = -1e30f;
                if (c0 + 1 > r0 + 8) sacc[nt][3] = -1e30f;
            }
        }

        {
            float tm0 = -1e30f, tm1 = -1e30f;
#pragma unroll
            for (int nt = 0; nt < 8; nt++) {
                tm0 = fmaxf(tm0, fmaxf(sacc[nt][0], sacc[nt][1]));
                tm1 = fmaxf(tm1, fmaxf(sacc[nt][2], sacc[nt][3]));
            }
            tm0 = fmaxf(tm0, __shfl_xor_sync(0xffffffffu, tm0, 1, 32));
            tm0 = fmaxf(tm0, __shfl_xor_sync(0xffffffffu, tm0, 2, 32));
            tm1 = fmaxf(tm1, __shfl_xor_sync(0xffffffffu, tm1, 1, 32));
            tm1 = fmaxf(tm1, __shfl_xor_sync(0xffffffffu, tm1, 2, 32));
            float mn0 = fmaxf(m0, tm0), mn1 = fmaxf(m1, tm1);
            float al0 = __expf(m0 - mn0), al1 = __expf(m1 - mn1);
            float rs0 = 0.0f, rs1 = 0.0f;
#pragma unroll
            for (int nt = 0; nt < 8; nt++) {
                sacc[nt][0] = __expf(sacc[nt][0] - mn0); rs0 += sacc[nt][0];
                sacc[nt][1] = __expf(sacc[nt][1] - mn0); rs0 += sacc[nt][1];
                sacc[nt][2] = __expf(sacc[nt][2] - mn1); rs1 += sacc[nt][2];
                sacc[nt][3] = __expf(sacc[nt][3] - mn1); rs1 += sacc[nt][3];
            }
            rs0 += __shfl_xor_sync(0xffffffffu, rs0, 1, 32);
            rs0 += __shfl_xor_sync(0xffffffffu, rs0, 2, 32);
            rs1 += __shfl_xor_sync(0xffffffffu, rs1, 1, 32);
            rs1 += __shfl_xor_sync(0xffffffffu, rs1, 2, 32);
            l0 = l0 * al0 + rs0; m0 = mn0;
            l1 = l1 * al1 + rs1; m1 = mn1;
#pragma unroll
            for (int n = 0; n < 8; n++) {
                oacc[n][0] *= al0; oacc[n][1] *= al0;
                oacc[n][2] *= al1; oacc[n][3] *= al1;
            }
        }

        // O += P @ V (1-pass fp16 P)
#pragma unroll
        for (int ks = 0; ks < 4; ks++) {
            uint32_t ph[4];
            {
                float* s0 = sacc[2 * ks];
                float* s1 = sacc[2 * ks + 1];
                ph[0] = pack_h2(__float2half(s0[0]), __float2half(s0[1]));
                ph[1] = pack_h2(__float2half(s0[2]), __float2half(s0[3]));
                ph[2] = pack_h2(__float2half(s1[0]), __float2half(s1[1]));
                ph[3] = pack_h2(__float2half(s1[2]), __float2half(s1[3]));
            }
#pragma unroll
            for (int nd2 = 0; nd2 < 4; nd2++) {
                uint32_t vf[4];
                uint32_t sw = sw_off(ks * 16 + v_row, nd2 * 2 + v_ch);
                LDSM_X4_T(vf, vbase + sw);
                MMA_F16(oacc[nd2 * 2],     ph, vf[0], vf[1]);
                MMA_F16(oacc[nd2 * 2 + 1], ph, vf[2], vf[3]);
            }
        }
    }

    // Epilogue: normalize + write fp16 (out GEMM is 1-pass now)
    {
        float inv0 = 1.0f / l0;
        float inv1 = 1.0f / l1;
        int gr0 = tokq + wid * 16 + (lane >> 2);
        int gr1 = gr0 + 8;
#pragma unroll
        for (int nt = 0; nt < 8; nt++) {
            int col = h * HDIM + nt * 8 + (lane & 3) * 2;
            *(__half2*)&g_chi[(size_t)gr0 * EMBED + col] =
                __floats2half2_rn(oacc[nt][0] * inv0, oacc[nt][1] * inv0);
            *(__half2*)&g_chi[(size_t)gr1 * EMBED + col] =
                __floats2half2_rn(oacc[nt][2] * inv1, oacc[nt][3] * inv1);
        }
    }
}

// ---------------------------------------------------------------------------
extern "C" void kernel_launch(void* const* d_in, const int* in_sizes, int n_in,
                              void* d_out, int out_size)
{
    const float* hidden = (const float*)d_in[0];
    const float* cosp   = (const float*)d_in[1];
    const float* sinp   = (const float*)d_in[2];
    const float* q_w    = (const float*)d_in[3];
    const float* q_b    = (const float*)d_in[4];
    const float* k_w    = (const float*)d_in[5];
    const float* v_w    = (const float*)d_in[6];
    const float* v_b    = (const float*)d_in[7];
    const float* out_w  = (const float*)d_in[8];
    const float* out_b  = (const float*)d_in[9];
    float* out = (float*)d_out;

    // 1. Prep: hidden hi/lo split + weight fp16 converts (one launch)
    {
        int nblk = (T_TOTAL * EMBED / 4 + 255) / 256;
        prep_kernel<<<dim3(nblk, 1, 5), 256>>>(hidden, q_w, k_w, v_w, out_w);
    }
    // 2. QKV GEMMs (1-pass, fused rope/split epilogues)
    cudaFuncSetAttribute(qkv_mma_kernel, cudaFuncAttributeMaxDynamicSharedMemorySize, SM_GEMM_TOTAL);
    qkv_mma_kernel<<<dim3(EMBED / 128, MTILES, 3), 256, SM_GEMM_TOTAL>>>(q_b, v_b, cosp, sinp);

    // 3. Flash attention (fp16 MMA, writes g_chi)
    cudaFuncSetAttribute(flash_kernel, cudaFuncAttributeMaxDynamicSharedMemorySize, FSM_TOTAL);
    flash_kernel<<<dim3(153, NHEADS), 128, FSM_TOTAL>>>();

    // 4. Output GEMM (1-pass, 3-stage, 2 CTAs/SM)
    cudaFuncSetAttribute(out_mma_kernel, cudaFuncAttributeMaxDynamicSharedMemorySize, SM_GEMM_TOTAL);
    out_mma_kernel<<<dim3(EMBED / 128, MTILES, 1), 256, SM_GEMM_TOTAL>>>(out_b, out);
}